// round 10
// baseline (speedup 1.0000x reference)
#include <cuda_runtime.h>
#include <math.h>
#include <stdint.h>

// Problem constants
#define B 512
#define N 100
#define D 128
#define H 8
#define DK 16
#define FF 512
#define TD 384          // 3*D
#define M_ROWS (B*N)    // 51200
#define NEGV -1e9f
#define CLIPV 10.0

static __device__ float g_h [ (size_t)M_ROWS * D ];     // hidden state
static __device__ float g_3d[ (size_t)M_ROWS * TD ];    // qkv / hp scratch
static __device__ float g_ff[ (size_t)M_ROWS * FF ];    // ff1 output
static __device__ float g_o [ (size_t)M_ROWS * D ];     // attention output
static __device__ float g_s [ (size_t)M_ROWS * D ];     // pre-BN (residual sum)
static __device__ float g_ef[ (size_t)M_ROWS * D ];     // h @ Wstep[0:128]
static __device__ float g_ed[ (size_t)M_ROWS * D ];     // h @ Wstep[128:256]
static __device__ float g_part32[2][400][128];          // per-block BN partials
static __device__ double g_mean[D], g_rstd[D];
static __device__ double g_wphw[D];                     // Wph @ Wstep
static __device__ float g_fc[B*D], g_q0[B*D];           // fixed_ctx, step-0 query

// ---------------------------------------------------------------------------
// h = x @ init_W + init_b  (float4 over D)
// ---------------------------------------------------------------------------
__global__ void init_embed_kernel(const float* __restrict__ x,
                                  const float* __restrict__ W,
                                  const float* __restrict__ bias) {
    int idx = blockIdx.x * blockDim.x + threadIdx.x;   // over M_ROWS*32
    if (idx >= M_ROWS * 32) return;
    int i = idx >> 5, d0 = (idx & 31) * 4;
    double x0 = (double)x[i*2], x1 = (double)x[i*2+1];
    float4 o;
    o.x = (float)(x0 * (double)W[d0+0] + x1 * (double)W[D+d0+0] + (double)bias[d0+0]);
    o.y = (float)(x0 * (double)W[d0+1] + x1 * (double)W[D+d0+1] + (double)bias[d0+1]);
    o.z = (float)(x0 * (double)W[d0+2] + x1 * (double)W[D+d0+2] + (double)bias[d0+2]);
    o.w = (float)(x0 * (double)W[d0+3] + x1 * (double)W[D+d0+3] + (double)bias[d0+3]);
    *reinterpret_cast<float4*>(&g_h[(size_t)idx*4]) = o;
}

// ---------------------------------------------------------------------------
// 3xTF32 tensor-core GEMM. BM=BN=128, BK=16, 256 threads = 8 warps (2m x 4n).
// A = Ah+Al, W = Bh+Bl (tf32 splits in smem); C += AhBh + AhBl + AlBh.
// Epilogue: (+bias)(+res)(relu).
// ---------------------------------------------------------------------------
#define TSTR 136   // smem row stride (words): banks (8*k + m) %32 conflict-free

__device__ __forceinline__ void tf32_split(float v, float& hi, float& lo) {
    unsigned h, l;
    asm("cvt.rna.tf32.f32 %0, %1;" : "=r"(h) : "f"(v));
    float hf = __uint_as_float(h);
    asm("cvt.rna.tf32.f32 %0, %1;" : "=r"(l) : "f"(v - hf));
    hi = hf; lo = __uint_as_float(l);
}

#define MMA_TF32(c, a0, a1, a2, a3, b0, b1)                                 \
    asm("mma.sync.aligned.m16n8k8.row.col.f32.tf32.tf32.f32 "               \
        "{%0,%1,%2,%3}, {%4,%5,%6,%7}, {%8,%9}, {%0,%1,%2,%3};"             \
        : "+f"((c)[0]), "+f"((c)[1]), "+f"((c)[2]), "+f"((c)[3])            \
        : "r"(a0), "r"(a1), "r"(a2), "r"(a3), "r"(b0), "r"(b1))

__global__ __launch_bounds__(256)
void tc_gemm_kernel(const float* __restrict__ A, const float* __restrict__ W,
                    const float* __restrict__ bias, const float* __restrict__ res,
                    float* __restrict__ C, int M, int K, int Nc, int relu) {
    __shared__ float Ah[16*TSTR], Al[16*TSTR], Bh[16*TSTR], Bl[16*TSTR];  // 34.8 KB
    const int tid = threadIdx.x;
    const int lane = tid & 31, wid = tid >> 5;
    const int g = lane >> 2, tig = lane & 3;
    const int wm = (wid & 1) * 64, wn = (wid >> 1) * 32;
    const int row0 = blockIdx.y * 128, col0 = blockIdx.x * 128;
    // loader indices
    const int ar = tid >> 1, akc = (tid & 1) * 8;   // A: 128 rows x 16 k
    const int bkr = tid >> 4, bcc = (tid & 15) * 8; // B: 16 k x 128 cols

    float acc[4][4][4];
#pragma unroll
    for (int mf = 0; mf < 4; mf++)
#pragma unroll
        for (int nf = 0; nf < 4; nf++)
#pragma unroll
            for (int e = 0; e < 4; e++) acc[mf][nf][e] = 0.f;

    for (int kt = 0; kt < K; kt += 16) {
        // --- load + split A tile ---
        float4 av0 = *reinterpret_cast<const float4*>(&A[(size_t)(row0+ar)*K + kt + akc]);
        float4 av1 = *reinterpret_cast<const float4*>(&A[(size_t)(row0+ar)*K + kt + akc + 4]);
        {
            float hi, lo;
            tf32_split(av0.x, hi, lo); Ah[(akc+0)*TSTR + ar] = hi; Al[(akc+0)*TSTR + ar] = lo;
            tf32_split(av0.y, hi, lo); Ah[(akc+1)*TSTR + ar] = hi; Al[(akc+1)*TSTR + ar] = lo;
            tf32_split(av0.z, hi, lo); Ah[(akc+2)*TSTR + ar] = hi; Al[(akc+2)*TSTR + ar] = lo;
            tf32_split(av0.w, hi, lo); Ah[(akc+3)*TSTR + ar] = hi; Al[(akc+3)*TSTR + ar] = lo;
            tf32_split(av1.x, hi, lo); Ah[(akc+4)*TSTR + ar] = hi; Al[(akc+4)*TSTR + ar] = lo;
            tf32_split(av1.y, hi, lo); Ah[(akc+5)*TSTR + ar] = hi; Al[(akc+5)*TSTR + ar] = lo;
            tf32_split(av1.z, hi, lo); Ah[(akc+6)*TSTR + ar] = hi; Al[(akc+6)*TSTR + ar] = lo;
            tf32_split(av1.w, hi, lo); Ah[(akc+7)*TSTR + ar] = hi; Al[(akc+7)*TSTR + ar] = lo;
        }
        // --- load + split B tile ---
        float4 bv0 = *reinterpret_cast<const float4*>(&W[(size_t)(kt+bkr)*Nc + col0 + bcc]);
        float4 bv1 = *reinterpret_cast<const float4*>(&W[(size_t)(kt+bkr)*Nc + col0 + bcc + 4]);
        {
            float hi, lo;
            tf32_split(bv0.x, hi, lo); Bh[bkr*TSTR + bcc+0] = hi; Bl[bkr*TSTR + bcc+0] = lo;
            tf32_split(bv0.y, hi, lo); Bh[bkr*TSTR + bcc+1] = hi; Bl[bkr*TSTR + bcc+1] = lo;
            tf32_split(bv0.z, hi, lo); Bh[bkr*TSTR + bcc+2] = hi; Bl[bkr*TSTR + bcc+2] = lo;
            tf32_split(bv0.w, hi, lo); Bh[bkr*TSTR + bcc+3] = hi; Bl[bkr*TSTR + bcc+3] = lo;
            tf32_split(bv1.x, hi, lo); Bh[bkr*TSTR + bcc+4] = hi; Bl[bkr*TSTR + bcc+4] = lo;
            tf32_split(bv1.y, hi, lo); Bh[bkr*TSTR + bcc+5] = hi; Bl[bkr*TSTR + bcc+5] = lo;
            tf32_split(bv1.z, hi, lo); Bh[bkr*TSTR + bcc+6] = hi; Bl[bkr*TSTR + bcc+6] = lo;
            tf32_split(bv1.w, hi, lo); Bh[bkr*TSTR + bcc+7] = hi; Bl[bkr*TSTR + bcc+7] = lo;
        }
        __syncthreads();
#pragma unroll
        for (int ks = 0; ks < 16; ks += 8) {
            // B fragments (k rows ks+tig, ks+tig+4; n col wn+nf*8+g)
            unsigned bhf[4][2], blf[4][2];
#pragma unroll
            for (int nf = 0; nf < 4; nf++) {
                int n0 = wn + nf*8 + g;
                bhf[nf][0] = __float_as_uint(Bh[(ks+tig)*TSTR + n0]);
                bhf[nf][1] = __float_as_uint(Bh[(ks+tig+4)*TSTR + n0]);
                blf[nf][0] = __float_as_uint(Bl[(ks+tig)*TSTR + n0]);
                blf[nf][1] = __float_as_uint(Bl[(ks+tig+4)*TSTR + n0]);
            }
#pragma unroll
            for (int mf = 0; mf < 4; mf++) {
                int m0 = wm + mf*16;
                unsigned ahf[4], alf[4];
                ahf[0] = __float_as_uint(Ah[(ks+tig)*TSTR + m0+g]);
                ahf[1] = __float_as_uint(Ah[(ks+tig)*TSTR + m0+g+8]);
                ahf[2] = __float_as_uint(Ah[(ks+tig+4)*TSTR + m0+g]);
                ahf[3] = __float_as_uint(Ah[(ks+tig+4)*TSTR + m0+g+8]);
                alf[0] = __float_as_uint(Al[(ks+tig)*TSTR + m0+g]);
                alf[1] = __float_as_uint(Al[(ks+tig)*TSTR + m0+g+8]);
                alf[2] = __float_as_uint(Al[(ks+tig+4)*TSTR + m0+g]);
                alf[3] = __float_as_uint(Al[(ks+tig+4)*TSTR + m0+g+8]);
#pragma unroll
                for (int nf = 0; nf < 4; nf++) {
                    MMA_TF32(acc[mf][nf], alf[0], alf[1], alf[2], alf[3], bhf[nf][0], bhf[nf][1]);
                    MMA_TF32(acc[mf][nf], ahf[0], ahf[1], ahf[2], ahf[3], blf[nf][0], blf[nf][1]);
                    MMA_TF32(acc[mf][nf], ahf[0], ahf[1], ahf[2], ahf[3], bhf[nf][0], bhf[nf][1]);
                }
            }
        }
        __syncthreads();
    }
    // epilogue
#pragma unroll
    for (int mf = 0; mf < 4; mf++) {
        int r0 = row0 + wm + mf*16 + g;
        int r1 = r0 + 8;
#pragma unroll
        for (int nf = 0; nf < 4; nf++) {
            int c0 = col0 + wn + nf*8 + tig*2;
            float v0 = acc[mf][nf][0], v1 = acc[mf][nf][1];
            float v2 = acc[mf][nf][2], v3 = acc[mf][nf][3];
            if (bias) { v0 += bias[c0]; v1 += bias[c0+1]; v2 += bias[c0]; v3 += bias[c0+1]; }
            if (res) {
                v0 += res[(size_t)r0*Nc + c0]; v1 += res[(size_t)r0*Nc + c0+1];
                v2 += res[(size_t)r1*Nc + c0]; v3 += res[(size_t)r1*Nc + c0+1];
            }
            if (relu) {
                v0 = fmaxf(v0, 0.f); v1 = fmaxf(v1, 0.f);
                v2 = fmaxf(v2, 0.f); v3 = fmaxf(v3, 0.f);
            }
            C[(size_t)r0*Nc + c0]   = v0;
            C[(size_t)r0*Nc + c0+1] = v1;
            C[(size_t)r1*Nc + c0]   = v2;
            C[(size_t)r1*Nc + c0+1] = v3;
        }
    }
}

// ---------------------------------------------------------------------------
// Fused MHA (R7 proven version): one block per (b,h), 256 threads.
// ---------------------------------------------------------------------------
#define ATTN_SMEM_BYTES ((3*1700 + 10000) * 4)
__global__ __launch_bounds__(256)
void attn_kernel(const float* __restrict__ qkv, float* __restrict__ o) {
    extern __shared__ float asm_[];
    float* qsh = asm_;            // 100*17
    float* ksh = qsh + 1700;      // 100*17
    float* vsh = ksh + 1700;      // 100*17
    float* psh = vsh + 1700;      // 100*100
    int bh = blockIdx.x;
    int b = bh >> 3, hh = bh & 7;
    int tid = threadIdx.x;
    for (int i = tid; i < 1600; i += 256) {
        int m = i >> 4, d = i & 15;
        const float* base = qkv + (size_t)(b*N + m) * TD + hh*16 + d;
        qsh[m*17 + d] = base[0];
        ksh[m*17 + d] = base[D];
        vsh[m*17 + d] = base[2*D];
    }
    __syncthreads();
    int w = tid >> 5, lane = tid & 31;
    for (int n = w; n < 100; n += 8) {
        float qreg[16];
        const float* qp = qsh + n*17;
#pragma unroll
        for (int d = 0; d < 16; d++) qreg[d] = qp[d];
        float sc[4];
        float mx = -1e30f;
#pragma unroll
        for (int j = 0; j < 4; j++) {
            int m = lane + 32*j;
            if (m < 100) {
                const float* kp = ksh + m*17;
                float a0 = 0.f, a1 = 0.f;
#pragma unroll
                for (int d = 0; d < 16; d += 2) {
                    a0 = fmaf(qreg[d],   kp[d],   a0);
                    a1 = fmaf(qreg[d+1], kp[d+1], a1);
                }
                sc[j] = (a0 + a1) * 0.25f;
                mx = fmaxf(mx, sc[j]);
            } else sc[j] = -1e30f;
        }
#pragma unroll
        for (int off = 16; off; off >>= 1) mx = fmaxf(mx, __shfl_xor_sync(0xffffffffu, mx, off));
        double sum = 0.0, ev[4];
#pragma unroll
        for (int j = 0; j < 4; j++) {
            int m = lane + 32*j;
            if (m < 100) { ev[j] = exp((double)(sc[j] - mx)); sum += ev[j]; }
            else ev[j] = 0.0;
        }
#pragma unroll
        for (int off = 16; off; off >>= 1) sum += __shfl_xor_sync(0xffffffffu, sum, off);
        double inv = 1.0 / sum;
#pragma unroll
        for (int j = 0; j < 4; j++) {
            int m = lane + 32*j;
            if (m < 100) psh[n*100 + m] = (float)(ev[j] * inv);
        }
    }
    __syncthreads();
    for (int idx = tid; idx < 1600; idx += 256) {
        int n = idx >> 4, dk = idx & 15;
        const float* pp = psh + n*100;
        const float* vp = vsh + dk;
        float a0 = 0.f, a1 = 0.f;
#pragma unroll 4
        for (int m = 0; m < 100; m += 2) {
            a0 = fmaf(pp[m],   vp[(m)*17],   a0);
            a1 = fmaf(pp[m+1], vp[(m+1)*17], a1);
        }
        o[(size_t)(b*N + n) * D + hh*16 + dk] = a0 + a1;
    }
}

// ---------------------------------------------------------------------------
// BN stats stage 1: 400 blocks x 256 thr, float4. Deterministic.
// ---------------------------------------------------------------------------
__global__ __launch_bounds__(256)
void bn_stats1_kernel(const float* __restrict__ s) {
    __shared__ float red[2][8][128];
    int p = blockIdx.x, t = threadIdx.x;
    int rg = t >> 5, cw = t & 31;
    float sm[4] = {0,0,0,0}, sq[4] = {0,0,0,0};
    size_t base = (size_t)p * 128 * 128;
    for (int r = rg*16; r < rg*16 + 16; r++) {
        float4 v = *reinterpret_cast<const float4*>(&s[base + (size_t)r*128 + cw*4]);
        sm[0] += v.x; sq[0] = fmaf(v.x, v.x, sq[0]);
        sm[1] += v.y; sq[1] = fmaf(v.y, v.y, sq[1]);
        sm[2] += v.z; sq[2] = fmaf(v.z, v.z, sq[2]);
        sm[3] += v.w; sq[3] = fmaf(v.w, v.w, sq[3]);
    }
#pragma unroll
    for (int c = 0; c < 4; c++) { red[0][rg][cw*4+c] = sm[c]; red[1][rg][cw*4+c] = sq[c]; }
    __syncthreads();
    if (t < 128) {
        float a = 0.f, q = 0.f;
#pragma unroll
        for (int r2 = 0; r2 < 8; r2++) { a += red[0][r2][t]; q += red[1][r2][t]; }
        g_part32[0][p][t] = a;
        g_part32[1][p][t] = q;
    }
}
__global__ void bn_stats2_kernel() {
    int c = threadIdx.x;
    double a = 0.0, q = 0.0;
    for (int p = 0; p < 400; p++) { a += (double)g_part32[0][p][c]; q += (double)g_part32[1][p][c]; }
    double mean = a * (1.0 / (double)M_ROWS);
    double var  = q * (1.0 / (double)M_ROWS) - mean*mean;
    g_mean[c] = mean;
    g_rstd[c] = 1.0 / sqrt(var + 1e-5);
}
__global__ void bn_apply_kernel(const float* __restrict__ s, const float* __restrict__ gb,
                                float* __restrict__ h) {
    int idx = blockIdx.x * blockDim.x + threadIdx.x;   // over M_ROWS*32
    if (idx >= M_ROWS * 32) return;
    float4 v = *reinterpret_cast<const float4*>(&s[(size_t)idx*4]);
    int d0 = (idx * 4) & 127;
    float4 o;
    o.x = (float)((double)gb[d0+0] * ((double)v.x - g_mean[d0+0]) * g_rstd[d0+0] + (double)gb[D+d0+0]);
    o.y = (float)((double)gb[d0+1] * ((double)v.y - g_mean[d0+1]) * g_rstd[d0+1] + (double)gb[D+d0+1]);
    o.z = (float)((double)gb[d0+2] * ((double)v.z - g_mean[d0+2]) * g_rstd[d0+2] + (double)gb[D+d0+2]);
    o.w = (float)((double)gb[d0+3] * ((double)v.w - g_mean[d0+3]) * g_rstd[d0+3] + (double)gb[D+d0+3]);
    *reinterpret_cast<float4*>(&h[(size_t)idx*4]) = o;
}

// ---------------------------------------------------------------------------
// wphw[d] = Wph @ Wstep (column d)
// ---------------------------------------------------------------------------
__global__ void wphw_kernel(const float* __restrict__ Wph, const float* __restrict__ Wstep) {
    int d = threadIdx.x;
    double a0 = 0.0, a1 = 0.0;
    for (int k = 0; k < 2*D; k += 2) {
        a0 = fma((double)Wph[k],   (double)Wstep[(k)*D + d],   a0);
        a1 = fma((double)Wph[k+1], (double)Wstep[(k+1)*D + d], a1);
    }
    g_wphw[d] = a0 + a1;
}

// ---------------------------------------------------------------------------
// Per-batch: hm = mean_n(h); fc = hm @ Wf; q0 = fc + wphw
// ---------------------------------------------------------------------------
__global__ void meanfix_kernel(const float* __restrict__ Wf) {
    __shared__ float sh[D];
    int b = blockIdx.x, d = threadIdx.x;
    double a = 0.0;
    for (int n = 0; n < N; n++) a += (double)g_h[(size_t)(b*N + n) * D + d];
    sh[d] = (float)(a * (1.0 / (double)N));
    __syncthreads();
    double fc = 0.0;
    for (int k = 0; k < D; k++) fc = fma((double)sh[k], (double)Wf[k*D + d], fc);
    g_fc[b*D + d] = (float)fc;
    g_q0[b*D + d] = (float)(fc + g_wphw[d]);
}

// ---------------------------------------------------------------------------
// Persistent greedy decode (unchanged). 512 threads, 2 blocks/SM.
// ---------------------------------------------------------------------------
#define HPS2 257
#define DEC_SMEM_BYTES (16 + (N*HPS2 + 128 + 128 + 800 + 128 + 128 + 512 + 100)*4 + 202*4)

__global__ __launch_bounds__(512, 2)
void decode_kernel(const float* __restrict__ x,
                   const float* __restrict__ Wout,
                   float* __restrict__ out) {
    extern __shared__ double dsm[];
    double* sh_ll  = dsm;
    float* sh_hp   = (float*)(dsm + 2);     // 100*257 (gK | gV)
    float* sh_q    = sh_hp + N*HPS2;
    float* sh_qb   = sh_q + D;
    float* sh_c    = sh_qb + D;
    float* sh_g    = sh_c + 800;
    float* sh_g2   = sh_g + D;
    float* sh_part = sh_g2 + D;
    float* sh_lg   = sh_part + 512;
    int*   sh_mask = (int*)(sh_lg + 100);
    int*   sh_pi   = sh_mask + 100;
    int*   sh_ctrl = sh_pi + 100;

    const float NF = 0.08838834764831843f;
    int b = blockIdx.x, tid = threadIdx.x;
    int w = tid >> 5, lane = tid & 31;
    int dd = tid & 127, part = tid >> 7;
    const float* lKg = g_3d + (size_t)b * (N*TD) + 2*D;

    for (int i = tid; i < N*256; i += 512) {
        int n = i >> 8, j = i & 255;
        sh_hp[n*HPS2 + j] = g_3d[(size_t)b * (N*TD) + n*TD + j];
    }
    if (tid < N) sh_mask[tid] = 0;
    if (tid == 0) { sh_ll[0] = 0.0; sh_ctrl[0] = 0; sh_ctrl[1] = 0; }
    __syncthreads();

    for (int s = 0; s < N; s++) {
        if (tid < 128) {
            if (s == 0) {
                sh_q[tid] = g_q0[b*D + tid];
            } else {
                float qb;
                if (s == 1) {
                    qb = g_fc[b*D + tid] + g_ef[(size_t)(b*N + sh_ctrl[0]) * D + tid];
                    sh_qb[tid] = qb;
                } else qb = sh_qb[tid];
                sh_q[tid] = qb + g_ed[(size_t)(b*N + sh_ctrl[1]) * D + tid];
            }
        }
        __syncthreads();
        for (int idx = tid; idx < 800; idx += 512) {
            int hh = idx / 100, n = idx - hh*100;
            const float* kp = sh_hp + n*HPS2 + hh*16;
            const float* qp = sh_q + hh*16;
            float a0 = 0.f, a1 = 0.f;
#pragma unroll
            for (int d2 = 0; d2 < 16; d2 += 2) {
                a0 = fmaf(qp[d2],   kp[d2],   a0);
                a1 = fmaf(qp[d2+1], kp[d2+1], a1);
            }
            sh_c[idx] = sh_mask[n] ? NEGV : (a0 + a1) * NF;
        }
        __syncthreads();
        if (w < 8) {
            int head = w;
            float mx = -1e30f;
            for (int n = lane; n < 100; n += 32) mx = fmaxf(mx, sh_c[head*100 + n]);
#pragma unroll
            for (int off = 16; off; off >>= 1) mx = fmaxf(mx, __shfl_xor_sync(0xffffffffu, mx, off));
            double sum = 0.0, ev[4];
#pragma unroll
            for (int j = 0; j < 4; j++) {
                int n = lane + 32*j;
                if (n < 100) { ev[j] = exp((double)(sh_c[head*100 + n] - mx)); sum += ev[j]; }
                else ev[j] = 0.0;
            }
#pragma unroll
            for (int off = 16; off; off >>= 1) sum += __shfl_xor_sync(0xffffffffu, sum, off);
            double inv = 1.0 / sum;
#pragma unroll
            for (int j = 0; j < 4; j++) {
                int n = lane + 32*j;
                if (n < 100) sh_c[head*100 + n] = (float)(ev[j] * inv);
            }
        }
        __syncthreads();
        {
            int hh = dd >> 4;
            const float* pp = sh_c + hh*100 + part*25;
            const float* vp = sh_hp + (size_t)(part*25) * HPS2 + D + dd;
            float a0 = 0.f, a1 = 0.f;
#pragma unroll 4
            for (int n = 0; n < 24; n += 2) {
                a0 = fmaf(pp[n],   vp[(n)*HPS2],   a0);
                a1 = fmaf(pp[n+1], vp[(n+1)*HPS2], a1);
            }
            a0 = fmaf(pp[24], vp[24*HPS2], a0);
            sh_part[tid] = a0 + a1;
        }
        __syncthreads();
        if (tid < 128) sh_g[tid] = sh_part[tid] + sh_part[tid+128] + sh_part[tid+256] + sh_part[tid+384];
        __syncthreads();
        {
            int k0 = part * 32;
            float a0 = 0.f, a1 = 0.f;
#pragma unroll 4
            for (int k = 0; k < 32; k += 2) {
                a0 = fmaf(sh_g[k0+k],   __ldg(&Wout[(k0+k)*D + dd]),   a0);
                a1 = fmaf(sh_g[k0+k+1], __ldg(&Wout[(k0+k+1)*D + dd]), a1);
            }
            sh_part[tid] = a0 + a1;
        }
        __syncthreads();
        if (tid < 128) sh_g2[tid] = sh_part[tid] + sh_part[tid+128] + sh_part[tid+256] + sh_part[tid+384];
        __syncthreads();
        if (dd < 100) {
            int k0 = part * 32;
            const float* lp = lKg + (size_t)dd * TD + k0;
            float a0 = 0.f, a1 = 0.f;
#pragma unroll
            for (int q4 = 0; q4 < 8; q4++) {
                float4 v = __ldg(reinterpret_cast<const float4*>(lp + q4*4));
                float4 g = *reinterpret_cast<const float4*>(&sh_g2[k0 + q4*4]);
                a0 = fmaf(g.x, v.x, a0); a1 = fmaf(g.y, v.y, a1);
                a0 = fmaf(g.z, v.z, a0); a1 = fmaf(g.w, v.w, a1);
            }
            sh_part[tid] = a0 + a1;
        }
        __syncthreads();
        if (tid < 100) {
            double a = (double)(sh_part[tid] + sh_part[tid+128] + sh_part[tid+256] + sh_part[tid+384]);
            sh_lg[tid] = sh_mask[tid] ? NEGV : (float)(tanh(a * (double)NF) * CLIPV);
        }
        __syncthreads();
        if (w == 0) {
            float mx = -1e30f; int mi = N + 1;
            for (int n = lane; n < N; n += 32) {
                float v = sh_lg[n];
                if (v > mx) { mx = v; mi = n; }
            }
#pragma unroll
            for (int off = 16; off; off >>= 1) {
                float om = __shfl_xor_sync(0xffffffffu, mx, off);
                int   oi = __shfl_xor_sync(0xffffffffu, mi, off);
                if (om > mx || (om == mx && oi < mi)) { mx = om; mi = oi; }
            }
            double sum = 0.0;
            for (int n = lane; n < N; n += 32) sum += exp((double)sh_lg[n] - (double)mx);
#pragma unroll
            for (int off = 16; off; off >>= 1) sum += __shfl_xor_sync(0xffffffffu, sum, off);
            if (lane == 0) {
                double lse = (double)mx + log(sum);
                sh_ll[0] += (double)sh_lg[mi] - lse;
                sh_mask[mi] = 1;
                sh_ctrl[1] = mi;
                if (s == 0) sh_ctrl[0] = mi;
                sh_pi[s] = mi;
                out[2*B + b*N + s] = (float)mi;
            }
        }
        __syncthreads();
    }
    if (tid < N) {
        int a = sh_pi[tid], c = sh_pi[(tid + 1) % N];
        double dx = (double)x[(b*N + a)*2]     - (double)x[(b*N + c)*2];
        double dy = (double)x[(b*N + a)*2 + 1] - (double)x[(b*N + c)*2 + 1];
        sh_lg[tid] = (float)sqrt(dx*dx + dy*dy);
    }
    __syncthreads();
    if (tid == 0) {
        double cst = 0.0;
        for (int t = 0; t < N; t++) cst += (double)sh_lg[t];
        out[b] = (float)cst;
        out[B + b] = (float)sh_ll[0];
    }
}

// ---------------------------------------------------------------------------
extern "C" void kernel_launch(void* const* d_in, const int* in_sizes, int n_in,
                              void* d_out, int out_size) {
    const float* x        = (const float*)d_in[0];
    const float* init_W   = (const float*)d_in[1];
    const float* init_b   = (const float*)d_in[2];
    const float* qkv_W    = (const float*)d_in[3];
    const float* out_W    = (const float*)d_in[4];
    const float* bn1      = (const float*)d_in[5];
    const float* bn2      = (const float*)d_in[6];
    const float* ff1_W    = (const float*)d_in[7];
    const float* ff1_b    = (const float*)d_in[8];
    const float* ff2_W    = (const float*)d_in[9];
    const float* ff2_b    = (const float*)d_in[10];
    const float* Wph      = (const float*)d_in[11];
    const float* nodes_W  = (const float*)d_in[12];
    const float* fixed_W  = (const float*)d_in[13];
    const float* step_W   = (const float*)d_in[14];
    const float* pout_W   = (const float*)d_in[15];
    float* out = (float*)d_out;

    cudaFuncSetAttribute(decode_kernel, cudaFuncAttributeMaxDynamicSharedMemorySize,
                         DEC_SMEM_BYTES + 128);
    cudaFuncSetAttribute(attn_kernel, cudaFuncAttributeMaxDynamicSharedMemorySize,
                         ATTN_SMEM_BYTES + 128);

    float *p_h, *p_3d, *p_ff, *p_o, *p_s, *p_ef, *p_ed;
    cudaGetSymbolAddress((void**)&p_h,  g_h);
    cudaGetSymbolAddress((void**)&p_3d, g_3d);
    cudaGetSymbolAddress((void**)&p_ff, g_ff);
    cudaGetSymbolAddress((void**)&p_o,  g_o);
    cudaGetSymbolAddress((void**)&p_s,  g_s);
    cudaGetSymbolAddress((void**)&p_ef, g_ef);
    cudaGetSymbolAddress((void**)&p_ed, g_ed);

    int vgrid = (M_ROWS * 32 + 255) / 256;   // float4 elementwise grids

    init_embed_kernel<<<vgrid, 256>>>(x, init_W, init_b);
    wphw_kernel<<<1, 128>>>(Wph, step_W);

    for (int l = 0; l < 2; l++) {
        tc_gemm_kernel<<<dim3(TD/128, M_ROWS/128), 256>>>(
            p_h, qkv_W + (size_t)l*D*TD, nullptr, nullptr, p_3d, M_ROWS, D, TD, 0);
        attn_kernel<<<B*H, 256, ATTN_SMEM_BYTES + 128>>>(p_3d, p_o);
        tc_gemm_kernel<<<dim3(D/128, M_ROWS/128), 256>>>(
            p_o, out_W + (size_t)l*D*D, nullptr, p_h, p_s, M_ROWS, D, D, 0);
        bn_stats1_kernel<<<400, 256>>>(p_s);
        bn_stats2_kernel<<<1, 128>>>();
        bn_apply_kernel<<<vgrid, 256>>>(p_s, bn1 + (size_t)l*2*D, p_h);
        tc_gemm_kernel<<<dim3(FF/128, M_ROWS/128), 256>>>(
            p_h, ff1_W + (size_t)l*D*FF, ff1_b + (size_t)l*FF, nullptr, p_ff, M_ROWS, D, FF, 1);
        tc_gemm_kernel<<<dim3(D/128, M_ROWS/128), 256>>>(
            p_ff, ff2_W + (size_t)l*FF*D, ff2_b + (size_t)l*D, p_h, p_s, M_ROWS, FF, D, 0);
        bn_stats1_kernel<<<400, 256>>>(p_s);
        bn_stats2_kernel<<<1, 128>>>();
        bn_apply_kernel<<<vgrid, 256>>>(p_s, bn2 + (size_t)l*2*D, p_h);
    }

    // decoder precompute
    tc_gemm_kernel<<<dim3(TD/128, M_ROWS/128), 256>>>(
        p_h, nodes_W, nullptr, nullptr, p_3d, M_ROWS, D, TD, 0);
    tc_gemm_kernel<<<dim3(D/128, M_ROWS/128), 256>>>(
        p_h, step_W, nullptr, nullptr, p_ef, M_ROWS, D, D, 0);
    tc_gemm_kernel<<<dim3(D/128, M_ROWS/128), 256>>>(
        p_h, step_W + (size_t)D*D, nullptr, nullptr, p_ed, M_ROWS, D, D, 0);
    meanfix_kernel<<<B, D>>>(fixed_W);

    decode_kernel<<<B, 512, DEC_SMEM_BYTES + 128>>>(x, pout_W, out);
}

// round 11
// speedup vs baseline: 1.0910x; 1.0910x over previous
#include <cuda_runtime.h>
#include <math.h>
#include <stdint.h>

// Problem constants
#define B 512
#define N 100
#define D 128
#define H 8
#define DK 16
#define FF 512
#define TD 384          // 3*D
#define M_ROWS (B*N)    // 51200
#define NEGV -1e9f
#define CLIPV 10.0

static __device__ float g_h [ (size_t)M_ROWS * D ];     // hidden state
static __device__ float g_3d[ (size_t)M_ROWS * TD ];    // qkv / hp scratch
static __device__ float g_ff[ (size_t)M_ROWS * FF ];    // ff1 output
static __device__ float g_o [ (size_t)M_ROWS * D ];     // attention output
static __device__ float g_s [ (size_t)M_ROWS * D ];     // pre-BN (residual sum)
static __device__ float g_ef[ (size_t)M_ROWS * D ];     // h @ Wstep[0:128]
static __device__ float g_ed[ (size_t)M_ROWS * D ];     // h @ Wstep[128:256]
static __device__ float g_part32[2][400][128];          // per-block BN partials
static __device__ double g_mean[D], g_rstd[D];
static __device__ double g_wphw[D];                     // Wph @ Wstep
static __device__ float g_fc[B*D], g_q0[B*D];           // fixed_ctx, step-0 query

// ---------------------------------------------------------------------------
// h = x @ init_W + init_b  (float4 over D)
// ---------------------------------------------------------------------------
__global__ void init_embed_kernel(const float* __restrict__ x,
                                  const float* __restrict__ W,
                                  const float* __restrict__ bias) {
    int idx = blockIdx.x * blockDim.x + threadIdx.x;   // over M_ROWS*32
    if (idx >= M_ROWS * 32) return;
    int i = idx >> 5, d0 = (idx & 31) * 4;
    double x0 = (double)x[i*2], x1 = (double)x[i*2+1];
    float4 o;
    o.x = (float)(x0 * (double)W[d0+0] + x1 * (double)W[D+d0+0] + (double)bias[d0+0]);
    o.y = (float)(x0 * (double)W[d0+1] + x1 * (double)W[D+d0+1] + (double)bias[d0+1]);
    o.z = (float)(x0 * (double)W[d0+2] + x1 * (double)W[D+d0+2] + (double)bias[d0+2]);
    o.w = (float)(x0 * (double)W[d0+3] + x1 * (double)W[D+d0+3] + (double)bias[d0+3]);
    *reinterpret_cast<float4*>(&g_h[(size_t)idx*4]) = o;
}

// ---------------------------------------------------------------------------
// fp32 tiled GEMM, cp.async double-buffered (R9 proven version).
// BM=BN=128, BK=16, 256 threads, 8x8 per thread.
// bnstats!=0: per-column (sum,sumsq) partials -> g_part32[*][blockIdx.y][*]
// (requires gridDim.x==1, Nc==128).
// ---------------------------------------------------------------------------
#define ARS 20
__global__ __launch_bounds__(256, 2)
void gemm32_kernel(const float* __restrict__ A, const float* __restrict__ W,
                   const float* __restrict__ bias, const float* __restrict__ res,
                   float* __restrict__ C, int M, int K, int Nc, int relu, int bnstats) {
    __shared__ float As[2][128][ARS];    // 20.5 KB
    __shared__ float Bs[2][16][132];     // 16.9 KB
    const int tid = threadIdx.x;
    const int tx = tid & 15, ty = tid >> 4;
    const int row0 = blockIdx.y * 128, col0 = blockIdx.x * 128;
    float acc[8][8];
#pragma unroll
    for (int i = 0; i < 8; i++)
#pragma unroll
        for (int j = 0; j < 8; j++) acc[i][j] = 0.f;

    auto loadtile = [&](int kt, int buf) {
#pragma unroll
        for (int p = 0; p < 2; p++) {
            int c = tid + p*256;
            int ar = c >> 2, asub = (c & 3) * 4;
            unsigned da = (unsigned)__cvta_generic_to_shared(&As[buf][ar][asub]);
            const float* sa = &A[(size_t)(row0+ar)*K + kt + asub];
            asm volatile("cp.async.cg.shared.global [%0], [%1], 16;" :: "r"(da), "l"(sa));
            int br = c >> 5, bsub = (c & 31) * 4;
            unsigned db = (unsigned)__cvta_generic_to_shared(&Bs[buf][br][bsub]);
            const float* sb = &W[(size_t)(kt+br)*Nc + col0 + bsub];
            asm volatile("cp.async.cg.shared.global [%0], [%1], 16;" :: "r"(db), "l"(sb));
        }
        asm volatile("cp.async.commit_group;");
    };

    const int T = K >> 4;
    loadtile(0, 0);
    if (T > 1) loadtile(16, 1);

    for (int t = 0; t < T; t++) {
        if (t + 1 < T) asm volatile("cp.async.wait_group 1;");
        else           asm volatile("cp.async.wait_group 0;");
        __syncthreads();
        const int buf = t & 1;
#pragma unroll
        for (int k = 0; k < 16; k++) {
            float a[8], bb[8];
#pragma unroll
            for (int i = 0; i < 4; i++) {
                a[i]   = As[buf][ty*4 + i][k];
                a[i+4] = As[buf][64 + ty*4 + i][k];
            }
            float4 b0 = *reinterpret_cast<const float4*>(&Bs[buf][k][tx*4]);
            float4 b1 = *reinterpret_cast<const float4*>(&Bs[buf][k][64 + tx*4]);
            bb[0]=b0.x;bb[1]=b0.y;bb[2]=b0.z;bb[3]=b0.w;bb[4]=b1.x;bb[5]=b1.y;bb[6]=b1.z;bb[7]=b1.w;
#pragma unroll
            for (int i = 0; i < 8; i++)
#pragma unroll
                for (int j = 0; j < 8; j++) acc[i][j] = fmaf(a[i], bb[j], acc[i][j]);
        }
        __syncthreads();
        if (t + 2 < T) loadtile((t+2)*16, buf);
    }

    float cs[8], cq[8];
#pragma unroll
    for (int j = 0; j < 8; j++) { cs[j] = 0.f; cq[j] = 0.f; }
#pragma unroll
    for (int i = 0; i < 8; i++) {
        int r = row0 + ty*4 + (i < 4 ? i : 60 + i);
#pragma unroll
        for (int j = 0; j < 8; j++) {
            int c = col0 + tx*4 + (j < 4 ? j : 60 + j);
            float v = acc[i][j];
            if (bias) v += bias[c];
            if (res)  v += res[(size_t)r*Nc + c];
            if (relu) v = fmaxf(v, 0.f);
            C[(size_t)r*Nc + c] = v;
            cs[j] += v;
            cq[j] = fmaf(v, v, cq[j]);
        }
    }
    if (bnstats) {
        float* red1 = &As[0][0][0];      // reuse smem: 16x128
        float* red2 = &Bs[0][0][0];
        __syncthreads();
#pragma unroll
        for (int j = 0; j < 8; j++) {
            int c = tx*4 + (j < 4 ? j : 60 + j);
            red1[ty*128 + c] = cs[j];
            red2[ty*128 + c] = cq[j];
        }
        __syncthreads();
        if (tid < 128) {
            float ssum = 0.f, ssq = 0.f;
#pragma unroll
            for (int t = 0; t < 16; t++) { ssum += red1[t*128 + tid]; ssq += red2[t*128 + tid]; }
            g_part32[0][blockIdx.y][tid] = ssum;
            g_part32[1][blockIdx.y][tid] = ssq;
        }
    }
}

// ---------------------------------------------------------------------------
// Fused MHA v5: one block per (b,h), 256 threads.
// Per-warp row buffer (no 40KB psh): smem 23.5 KB -> higher occupancy.
// Per row (one warp): scores -> softmax (double exp) -> P@V fused.
// ---------------------------------------------------------------------------
#define ATTN_SMEM_BYTES ((3*1700 + 8*104) * 4)
__global__ __launch_bounds__(256)
void attn_kernel(const float* __restrict__ qkv, float* __restrict__ o) {
    extern __shared__ float asm_[];
    float* qsh  = asm_;            // 100*17
    float* ksh  = qsh + 1700;      // 100*17
    float* vsh  = ksh + 1700;      // 100*17
    float* prow = vsh + 1700;      // 8 warps x 104
    int bh = blockIdx.x;
    int b = bh >> 3, hh = bh & 7;
    int tid = threadIdx.x;
    for (int i = tid; i < 1600; i += 256) {
        int m = i >> 4, d = i & 15;
        const float* base = qkv + (size_t)(b*N + m) * TD + hh*16 + d;
        qsh[m*17 + d] = base[0];
        ksh[m*17 + d] = base[D];
        vsh[m*17 + d] = base[2*D];
    }
    __syncthreads();
    int w = tid >> 5, lane = tid & 31;
    float* myrow = prow + w*104;
    const int dk = lane & 15, half = lane >> 4;
    for (int n = w; n < 100; n += 8) {
        float qreg[16];
        const float* qp = qsh + n*17;
#pragma unroll
        for (int d = 0; d < 16; d++) qreg[d] = qp[d];
        float sc[4];
        float mx = -1e30f;
#pragma unroll
        for (int j = 0; j < 4; j++) {
            int m = lane + 32*j;
            if (m < 100) {
                const float* kp = ksh + m*17;
                float a0 = 0.f, a1 = 0.f;
#pragma unroll
                for (int d = 0; d < 16; d += 2) {
                    a0 = fmaf(qreg[d],   kp[d],   a0);
                    a1 = fmaf(qreg[d+1], kp[d+1], a1);
                }
                sc[j] = (a0 + a1) * 0.25f;
                mx = fmaxf(mx, sc[j]);
            } else sc[j] = -1e30f;
        }
#pragma unroll
        for (int off = 16; off; off >>= 1) mx = fmaxf(mx, __shfl_xor_sync(0xffffffffu, mx, off));
        double sum = 0.0, ev[4];
#pragma unroll
        for (int j = 0; j < 4; j++) {
            int m = lane + 32*j;
            if (m < 100) { ev[j] = exp((double)(sc[j] - mx)); sum += ev[j]; }
            else ev[j] = 0.0;
        }
#pragma unroll
        for (int off = 16; off; off >>= 1) sum += __shfl_xor_sync(0xffffffffu, sum, off);
        double inv = 1.0 / sum;
#pragma unroll
        for (int j = 0; j < 4; j++) {
            int m = lane + 32*j;
            if (m < 100) myrow[m] = (float)(ev[j] * inv);
        }
        __syncwarp();
        // fused P@V: 2 lanes per dk, 50 m's each
        {
            const float* pp = myrow + half*50;
            const float* vp = vsh + (half*50)*17 + dk;
            float a0 = 0.f, a1 = 0.f;
#pragma unroll 4
            for (int m = 0; m < 50; m += 2) {
                a0 = fmaf(pp[m],   vp[(m)*17],   a0);
                a1 = fmaf(pp[m+1], vp[(m+1)*17], a1);
            }
            float r = a0 + a1;
            r += __shfl_xor_sync(0xffffffffu, r, 16);
            if (lane < 16) o[(size_t)(b*N + n) * D + hh*16 + dk] = r;
        }
        __syncwarp();
    }
}

// ---------------------------------------------------------------------------
// BN finalize: reduce 400 per-block partials (double), store mean/rstd.
// ---------------------------------------------------------------------------
__global__ void bn_stats2_kernel() {
    int c = threadIdx.x;
    double a = 0.0, q = 0.0;
    for (int p = 0; p < 400; p++) { a += (double)g_part32[0][p][c]; q += (double)g_part32[1][p][c]; }
    double mean = a * (1.0 / (double)M_ROWS);
    double var  = q * (1.0 / (double)M_ROWS) - mean*mean;
    g_mean[c] = mean;
    g_rstd[c] = 1.0 / sqrt(var + 1e-5);
}
__global__ void bn_apply_kernel(const float* __restrict__ s, const float* __restrict__ gb,
                                float* __restrict__ h) {
    int idx = blockIdx.x * blockDim.x + threadIdx.x;   // over M_ROWS*32
    if (idx >= M_ROWS * 32) return;
    float4 v = *reinterpret_cast<const float4*>(&s[(size_t)idx*4]);
    int d0 = (idx * 4) & 127;
    float4 o;
    o.x = (float)((double)gb[d0+0] * ((double)v.x - g_mean[d0+0]) * g_rstd[d0+0] + (double)gb[D+d0+0]);
    o.y = (float)((double)gb[d0+1] * ((double)v.y - g_mean[d0+1]) * g_rstd[d0+1] + (double)gb[D+d0+1]);
    o.z = (float)((double)gb[d0+2] * ((double)v.z - g_mean[d0+2]) * g_rstd[d0+2] + (double)gb[D+d0+2]);
    o.w = (float)((double)gb[d0+3] * ((double)v.w - g_mean[d0+3]) * g_rstd[d0+3] + (double)gb[D+d0+3]);
    *reinterpret_cast<float4*>(&h[(size_t)idx*4]) = o;
}

// ---------------------------------------------------------------------------
// wphw[d] = Wph @ Wstep (column d)
// ---------------------------------------------------------------------------
__global__ void wphw_kernel(const float* __restrict__ Wph, const float* __restrict__ Wstep) {
    int d = threadIdx.x;
    double a0 = 0.0, a1 = 0.0;
    for (int k = 0; k < 2*D; k += 2) {
        a0 = fma((double)Wph[k],   (double)Wstep[(k)*D + d],   a0);
        a1 = fma((double)Wph[k+1], (double)Wstep[(k+1)*D + d], a1);
    }
    g_wphw[d] = a0 + a1;
}

// ---------------------------------------------------------------------------
// Per-batch: hm = mean_n(h); fc = hm @ Wf; q0 = fc + wphw
// ---------------------------------------------------------------------------
__global__ void meanfix_kernel(const float* __restrict__ Wf) {
    __shared__ float sh[D];
    int b = blockIdx.x, d = threadIdx.x;
    double a = 0.0;
    for (int n = 0; n < N; n++) a += (double)g_h[(size_t)(b*N + n) * D + d];
    sh[d] = (float)(a * (1.0 / (double)N));
    __syncthreads();
    double fc = 0.0;
    for (int k = 0; k < D; k++) fc = fma((double)sh[k], (double)Wf[k*D + d], fc);
    g_fc[b*D + d] = (float)fc;
    g_q0[b*D + d] = (float)(fc + g_wphw[d]);
}

// ---------------------------------------------------------------------------
// Persistent greedy decode (unchanged). 512 threads, 2 blocks/SM.
// ---------------------------------------------------------------------------
#define HPS2 257
#define DEC_SMEM_BYTES (16 + (N*HPS2 + 128 + 128 + 800 + 128 + 128 + 512 + 100)*4 + 202*4)

__global__ __launch_bounds__(512, 2)
void decode_kernel(const float* __restrict__ x,
                   const float* __restrict__ Wout,
                   float* __restrict__ out) {
    extern __shared__ double dsm[];
    double* sh_ll  = dsm;
    float* sh_hp   = (float*)(dsm + 2);     // 100*257 (gK | gV)
    float* sh_q    = sh_hp + N*HPS2;
    float* sh_qb   = sh_q + D;
    float* sh_c    = sh_qb + D;
    float* sh_g    = sh_c + 800;
    float* sh_g2   = sh_g + D;
    float* sh_part = sh_g2 + D;
    float* sh_lg   = sh_part + 512;
    int*   sh_mask = (int*)(sh_lg + 100);
    int*   sh_pi   = sh_mask + 100;
    int*   sh_ctrl = sh_pi + 100;

    const float NF = 0.08838834764831843f;
    int b = blockIdx.x, tid = threadIdx.x;
    int w = tid >> 5, lane = tid & 31;
    int dd = tid & 127, part = tid >> 7;
    const float* lKg = g_3d + (size_t)b * (N*TD) + 2*D;

    for (int i = tid; i < N*256; i += 512) {
        int n = i >> 8, j = i & 255;
        sh_hp[n*HPS2 + j] = g_3d[(size_t)b * (N*TD) + n*TD + j];
    }
    if (tid < N) sh_mask[tid] = 0;
    if (tid == 0) { sh_ll[0] = 0.0; sh_ctrl[0] = 0; sh_ctrl[1] = 0; }
    __syncthreads();

    for (int s = 0; s < N; s++) {
        if (tid < 128) {
            if (s == 0) {
                sh_q[tid] = g_q0[b*D + tid];
            } else {
                float qb;
                if (s == 1) {
                    qb = g_fc[b*D + tid] + g_ef[(size_t)(b*N + sh_ctrl[0]) * D + tid];
                    sh_qb[tid] = qb;
                } else qb = sh_qb[tid];
                sh_q[tid] = qb + g_ed[(size_t)(b*N + sh_ctrl[1]) * D + tid];
            }
        }
        __syncthreads();
        for (int idx = tid; idx < 800; idx += 512) {
            int hh = idx / 100, n = idx - hh*100;
            const float* kp = sh_hp + n*HPS2 + hh*16;
            const float* qp = sh_q + hh*16;
            float a0 = 0.f, a1 = 0.f;
#pragma unroll
            for (int d2 = 0; d2 < 16; d2 += 2) {
                a0 = fmaf(qp[d2],   kp[d2],   a0);
                a1 = fmaf(qp[d2+1], kp[d2+1], a1);
            }
            sh_c[idx] = sh_mask[n] ? NEGV : (a0 + a1) * NF;
        }
        __syncthreads();
        if (w < 8) {
            int head = w;
            float mx = -1e30f;
            for (int n = lane; n < 100; n += 32) mx = fmaxf(mx, sh_c[head*100 + n]);
#pragma unroll
            for (int off = 16; off; off >>= 1) mx = fmaxf(mx, __shfl_xor_sync(0xffffffffu, mx, off));
            double sum = 0.0, ev[4];
#pragma unroll
            for (int j = 0; j < 4; j++) {
                int n = lane + 32*j;
                if (n < 100) { ev[j] = exp((double)(sh_c[head*100 + n] - mx)); sum += ev[j]; }
                else ev[j] = 0.0;
            }
#pragma unroll
            for (int off = 16; off; off >>= 1) sum += __shfl_xor_sync(0xffffffffu, sum, off);
            double inv = 1.0 / sum;
#pragma unroll
            for (int j = 0; j < 4; j++) {
                int n = lane + 32*j;
                if (n < 100) sh_c[head*100 + n] = (float)(ev[j] * inv);
            }
        }
        __syncthreads();
        {
            int hh = dd >> 4;
            const float* pp = sh_c + hh*100 + part*25;
            const float* vp = sh_hp + (size_t)(part*25) * HPS2 + D + dd;
            float a0 = 0.f, a1 = 0.f;
#pragma unroll 4
            for (int n = 0; n < 24; n += 2) {
                a0 = fmaf(pp[n],   vp[(n)*HPS2],   a0);
                a1 = fmaf(pp[n+1], vp[(n+1)*HPS2], a1);
            }
            a0 = fmaf(pp[24], vp[24*HPS2], a0);
            sh_part[tid] = a0 + a1;
        }
        __syncthreads();
        if (tid < 128) sh_g[tid] = sh_part[tid] + sh_part[tid+128] + sh_part[tid+256] + sh_part[tid+384];
        __syncthreads();
        {
            int k0 = part * 32;
            float a0 = 0.f, a1 = 0.f;
#pragma unroll 4
            for (int k = 0; k < 32; k += 2) {
                a0 = fmaf(sh_g[k0+k],   __ldg(&Wout[(k0+k)*D + dd]),   a0);
                a1 = fmaf(sh_g[k0+k+1], __ldg(&Wout[(k0+k+1)*D + dd]), a1);
            }
            sh_part[tid] = a0 + a1;
        }
        __syncthreads();
        if (tid < 128) sh_g2[tid] = sh_part[tid] + sh_part[tid+128] + sh_part[tid+256] + sh_part[tid+384];
        __syncthreads();
        if (dd < 100) {
            int k0 = part * 32;
            const float* lp = lKg + (size_t)dd * TD + k0;
            float a0 = 0.f, a1 = 0.f;
#pragma unroll
            for (int q4 = 0; q4 < 8; q4++) {
                float4 v = __ldg(reinterpret_cast<const float4*>(lp + q4*4));
                float4 g = *reinterpret_cast<const float4*>(&sh_g2[k0 + q4*4]);
                a0 = fmaf(g.x, v.x, a0); a1 = fmaf(g.y, v.y, a1);
                a0 = fmaf(g.z, v.z, a0); a1 = fmaf(g.w, v.w, a1);
            }
            sh_part[tid] = a0 + a1;
        }
        __syncthreads();
        if (tid < 100) {
            double a = (double)(sh_part[tid] + sh_part[tid+128] + sh_part[tid+256] + sh_part[tid+384]);
            sh_lg[tid] = sh_mask[tid] ? NEGV : (float)(tanh(a * (double)NF) * CLIPV);
        }
        __syncthreads();
        if (w == 0) {
            float mx = -1e30f; int mi = N + 1;
            for (int n = lane; n < N; n += 32) {
                float v = sh_lg[n];
                if (v > mx) { mx = v; mi = n; }
            }
#pragma unroll
            for (int off = 16; off; off >>= 1) {
                float om = __shfl_xor_sync(0xffffffffu, mx, off);
                int   oi = __shfl_xor_sync(0xffffffffu, mi, off);
                if (om > mx || (om == mx && oi < mi)) { mx = om; mi = oi; }
            }
            double sum = 0.0;
            for (int n = lane; n < N; n += 32) sum += exp((double)sh_lg[n] - (double)mx);
#pragma unroll
            for (int off = 16; off; off >>= 1) sum += __shfl_xor_sync(0xffffffffu, sum, off);
            if (lane == 0) {
                double lse = (double)mx + log(sum);
                sh_ll[0] += (double)sh_lg[mi] - lse;
                sh_mask[mi] = 1;
                sh_ctrl[1] = mi;
                if (s == 0) sh_ctrl[0] = mi;
                sh_pi[s] = mi;
                out[2*B + b*N + s] = (float)mi;
            }
        }
        __syncthreads();
    }
    if (tid < N) {
        int a = sh_pi[tid], c = sh_pi[(tid + 1) % N];
        double dx = (double)x[(b*N + a)*2]     - (double)x[(b*N + c)*2];
        double dy = (double)x[(b*N + a)*2 + 1] - (double)x[(b*N + c)*2 + 1];
        sh_lg[tid] = (float)sqrt(dx*dx + dy*dy);
    }
    __syncthreads();
    if (tid == 0) {
        double cst = 0.0;
        for (int t = 0; t < N; t++) cst += (double)sh_lg[t];
        out[b] = (float)cst;
        out[B + b] = (float)sh_ll[0];
    }
}

// ---------------------------------------------------------------------------
extern "C" void kernel_launch(void* const* d_in, const int* in_sizes, int n_in,
                              void* d_out, int out_size) {
    const float* x        = (const float*)d_in[0];
    const float* init_W   = (const float*)d_in[1];
    const float* init_b   = (const float*)d_in[2];
    const float* qkv_W    = (const float*)d_in[3];
    const float* out_W    = (const float*)d_in[4];
    const float* bn1      = (const float*)d_in[5];
    const float* bn2      = (const float*)d_in[6];
    const float* ff1_W    = (const float*)d_in[7];
    const float* ff1_b    = (const float*)d_in[8];
    const float* ff2_W    = (const float*)d_in[9];
    const float* ff2_b    = (const float*)d_in[10];
    const float* Wph      = (const float*)d_in[11];
    const float* nodes_W  = (const float*)d_in[12];
    const float* fixed_W  = (const float*)d_in[13];
    const float* step_W   = (const float*)d_in[14];
    const float* pout_W   = (const float*)d_in[15];
    float* out = (float*)d_out;

    cudaFuncSetAttribute(decode_kernel, cudaFuncAttributeMaxDynamicSharedMemorySize,
                         DEC_SMEM_BYTES + 128);
    cudaFuncSetAttribute(attn_kernel, cudaFuncAttributeMaxDynamicSharedMemorySize,
                         ATTN_SMEM_BYTES + 128);

    float *p_h, *p_3d, *p_ff, *p_o, *p_s, *p_ef, *p_ed;
    cudaGetSymbolAddress((void**)&p_h,  g_h);
    cudaGetSymbolAddress((void**)&p_3d, g_3d);
    cudaGetSymbolAddress((void**)&p_ff, g_ff);
    cudaGetSymbolAddress((void**)&p_o,  g_o);
    cudaGetSymbolAddress((void**)&p_s,  g_s);
    cudaGetSymbolAddress((void**)&p_ef, g_ef);
    cudaGetSymbolAddress((void**)&p_ed, g_ed);

    int vgrid = (M_ROWS * 32 + 255) / 256;   // float4 elementwise grids

    init_embed_kernel<<<vgrid, 256>>>(x, init_W, init_b);
    wphw_kernel<<<1, 128>>>(Wph, step_W);

    for (int l = 0; l < 2; l++) {
        gemm32_kernel<<<dim3(TD/128, M_ROWS/128), 256>>>(
            p_h, qkv_W + (size_t)l*D*TD, nullptr, nullptr, p_3d, M_ROWS, D, TD, 0, 0);
        attn_kernel<<<B*H, 256, ATTN_SMEM_BYTES + 128>>>(p_3d, p_o);
        // s = o @ Wout + h, with fused BN stats
        gemm32_kernel<<<dim3(D/128, M_ROWS/128), 256>>>(
            p_o, out_W + (size_t)l*D*D, nullptr, p_h, p_s, M_ROWS, D, D, 0, 1);
        bn_stats2_kernel<<<1, 128>>>();
        bn_apply_kernel<<<vgrid, 256>>>(p_s, bn1 + (size_t)l*2*D, p_h);
        gemm32_kernel<<<dim3(FF/128, M_ROWS/128), 256>>>(
            p_h, ff1_W + (size_t)l*D*FF, ff1_b + (size_t)l*FF, nullptr, p_ff, M_ROWS, D, FF, 1, 0);
        // s = ff1 @ W2 + b2 + h, with fused BN stats
        gemm32_kernel<<<dim3(D/128, M_ROWS/128), 256>>>(
            p_ff, ff2_W + (size_t)l*FF*D, ff2_b + (size_t)l*D, p_h, p_s, M_ROWS, FF, D, 0, 1);
        bn_stats2_kernel<<<1, 128>>>();
        bn_apply_kernel<<<vgrid, 256>>>(p_s, bn2 + (size_t)l*2*D, p_h);
    }

    // decoder precompute
    gemm32_kernel<<<dim3(TD/128, M_ROWS/128), 256>>>(
        p_h, nodes_W, nullptr, nullptr, p_3d, M_ROWS, D, TD, 0, 0);
    gemm32_kernel<<<dim3(D/128, M_ROWS/128), 256>>>(
        p_h, step_W, nullptr, nullptr, p_ef, M_ROWS, D, D, 0, 0);
    gemm32_kernel<<<dim3(D/128, M_ROWS/128), 256>>>(
        p_h, step_W + (size_t)D*D, nullptr, nullptr, p_ed, M_ROWS, D, D, 0, 0);
    meanfix_kernel<<<B, D>>>(fixed_W);

    decode_kernel<<<B, 512, DEC_SMEM_BYTES + 128>>>(x, pout_W, out);
}

// round 12
// speedup vs baseline: 1.2060x; 1.1055x over previous
#include <cuda_runtime.h>
#include <math.h>
#include <stdint.h>

// Problem constants
#define B 512
#define N 100
#define D 128
#define H 8
#define DK 16
#define FF 512
#define TD 384          // 3*D
#define M_ROWS (B*N)    // 51200
#define NEGV -1e9f
#define CLIPV 10.0

static __device__ float g_h [ (size_t)M_ROWS * D ];     // hidden state
static __device__ float g_3d[ (size_t)M_ROWS * TD ];    // qkv / hp scratch
static __device__ float g_ff[ (size_t)M_ROWS * FF ];    // ff1 output
static __device__ float g_o [ (size_t)M_ROWS * D ];     // attention output
static __device__ float g_s [ (size_t)M_ROWS * D ];     // pre-BN (residual sum)
static __device__ float g_ef[ (size_t)M_ROWS * D ];     // h @ Wstep[0:128]
static __device__ float g_ed[ (size_t)M_ROWS * D ];     // h @ Wstep[128:256]
static __device__ float g_lkw[ (size_t)M_ROWS * D ];    // lK @ Wout^T
static __device__ float g_wt[D*D];                      // Wout^T
static __device__ float g_part32[2][400][128];          // per-block BN partials
static __device__ double g_mean[D], g_rstd[D];
static __device__ double g_wphw[D];                     // Wph @ Wstep
static __device__ float g_fc[B*D], g_q0[B*D];           // fixed_ctx, step-0 query

// ---------------------------------------------------------------------------
// h = x @ init_W + init_b  (float4 over D)
// ---------------------------------------------------------------------------
__global__ void init_embed_kernel(const float* __restrict__ x,
                                  const float* __restrict__ W,
                                  const float* __restrict__ bias) {
    int idx = blockIdx.x * blockDim.x + threadIdx.x;   // over M_ROWS*32
    if (idx >= M_ROWS * 32) return;
    int i = idx >> 5, d0 = (idx & 31) * 4;
    double x0 = (double)x[i*2], x1 = (double)x[i*2+1];
    float4 o;
    o.x = (float)(x0 * (double)W[d0+0] + x1 * (double)W[D+d0+0] + (double)bias[d0+0]);
    o.y = (float)(x0 * (double)W[d0+1] + x1 * (double)W[D+d0+1] + (double)bias[d0+1]);
    o.z = (float)(x0 * (double)W[d0+2] + x1 * (double)W[D+d0+2] + (double)bias[d0+2]);
    o.w = (float)(x0 * (double)W[d0+3] + x1 * (double)W[D+d0+3] + (double)bias[d0+3]);
    *reinterpret_cast<float4*>(&g_h[(size_t)idx*4]) = o;
}

// ---------------------------------------------------------------------------
// Wout^T (128x128)
// ---------------------------------------------------------------------------
__global__ void transpose_kernel(const float* __restrict__ Wout) {
    int idx = blockIdx.x * blockDim.x + threadIdx.x;   // over D*D
    int d = idx >> 7, k = idx & 127;
    g_wt[d*D + k] = Wout[k*D + d];
}

// ---------------------------------------------------------------------------
// fp32 tiled GEMM, cp.async double-buffered (R9 proven version + lda).
// BM=BN=128, BK=16, 256 threads, 8x8 per thread. A row stride = lda.
// bnstats!=0: per-column (sum,sumsq) partials -> g_part32[*][blockIdx.y][*]
// (requires gridDim.x==1, Nc==128).
// ---------------------------------------------------------------------------
#define ARS 20
__global__ __launch_bounds__(256, 2)
void gemm32_kernel(const float* __restrict__ A, const float* __restrict__ W,
                   const float* __restrict__ bias, const float* __restrict__ res,
                   float* __restrict__ C, int M, int K, int Nc, int lda,
                   int relu, int bnstats) {
    __shared__ float As[2][128][ARS];    // 20.5 KB
    __shared__ float Bs[2][16][132];     // 16.9 KB
    const int tid = threadIdx.x;
    const int tx = tid & 15, ty = tid >> 4;
    const int row0 = blockIdx.y * 128, col0 = blockIdx.x * 128;
    float acc[8][8];
#pragma unroll
    for (int i = 0; i < 8; i++)
#pragma unroll
        for (int j = 0; j < 8; j++) acc[i][j] = 0.f;

    auto loadtile = [&](int kt, int buf) {
#pragma unroll
        for (int p = 0; p < 2; p++) {
            int c = tid + p*256;
            int ar = c >> 2, asub = (c & 3) * 4;
            unsigned da = (unsigned)__cvta_generic_to_shared(&As[buf][ar][asub]);
            const float* sa = &A[(size_t)(row0+ar)*lda + kt + asub];
            asm volatile("cp.async.cg.shared.global [%0], [%1], 16;" :: "r"(da), "l"(sa));
            int br = c >> 5, bsub = (c & 31) * 4;
            unsigned db = (unsigned)__cvta_generic_to_shared(&Bs[buf][br][bsub]);
            const float* sb = &W[(size_t)(kt+br)*Nc + col0 + bsub];
            asm volatile("cp.async.cg.shared.global [%0], [%1], 16;" :: "r"(db), "l"(sb));
        }
        asm volatile("cp.async.commit_group;");
    };

    const int T = K >> 4;
    loadtile(0, 0);
    if (T > 1) loadtile(16, 1);

    for (int t = 0; t < T; t++) {
        if (t + 1 < T) asm volatile("cp.async.wait_group 1;");
        else           asm volatile("cp.async.wait_group 0;");
        __syncthreads();
        const int buf = t & 1;
#pragma unroll
        for (int k = 0; k < 16; k++) {
            float a[8], bb[8];
#pragma unroll
            for (int i = 0; i < 4; i++) {
                a[i]   = As[buf][ty*4 + i][k];
                a[i+4] = As[buf][64 + ty*4 + i][k];
            }
            float4 b0 = *reinterpret_cast<const float4*>(&Bs[buf][k][tx*4]);
            float4 b1 = *reinterpret_cast<const float4*>(&Bs[buf][k][64 + tx*4]);
            bb[0]=b0.x;bb[1]=b0.y;bb[2]=b0.z;bb[3]=b0.w;bb[4]=b1.x;bb[5]=b1.y;bb[6]=b1.z;bb[7]=b1.w;
#pragma unroll
            for (int i = 0; i < 8; i++)
#pragma unroll
                for (int j = 0; j < 8; j++) acc[i][j] = fmaf(a[i], bb[j], acc[i][j]);
        }
        __syncthreads();
        if (t + 2 < T) loadtile((t+2)*16, buf);
    }

    float cs[8], cq[8];
#pragma unroll
    for (int j = 0; j < 8; j++) { cs[j] = 0.f; cq[j] = 0.f; }
#pragma unroll
    for (int i = 0; i < 8; i++) {
        int r = row0 + ty*4 + (i < 4 ? i : 60 + i);
#pragma unroll
        for (int j = 0; j < 8; j++) {
            int c = col0 + tx*4 + (j < 4 ? j : 60 + j);
            float v = acc[i][j];
            if (bias) v += bias[c];
            if (res)  v += res[(size_t)r*Nc + c];
            if (relu) v = fmaxf(v, 0.f);
            C[(size_t)r*Nc + c] = v;
            cs[j] += v;
            cq[j] = fmaf(v, v, cq[j]);
        }
    }
    if (bnstats) {
        float* red1 = &As[0][0][0];      // reuse smem: 16x128
        float* red2 = &Bs[0][0][0];
        __syncthreads();
#pragma unroll
        for (int j = 0; j < 8; j++) {
            int c = tx*4 + (j < 4 ? j : 60 + j);
            red1[ty*128 + c] = cs[j];
            red2[ty*128 + c] = cq[j];
        }
        __syncthreads();
        if (tid < 128) {
            float ssum = 0.f, ssq = 0.f;
#pragma unroll
            for (int t = 0; t < 16; t++) { ssum += red1[t*128 + tid]; ssq += red2[t*128 + tid]; }
            g_part32[0][blockIdx.y][tid] = ssum;
            g_part32[1][blockIdx.y][tid] = ssq;
        }
    }
}

// ---------------------------------------------------------------------------
// Fused MHA (R9 proven version): one block per (b,h), 256 threads.
// ---------------------------------------------------------------------------
#define ATTN_SMEM_BYTES ((3*1700 + 10000) * 4)
__global__ __launch_bounds__(256)
void attn_kernel(const float* __restrict__ qkv, float* __restrict__ o) {
    extern __shared__ float asm_[];
    float* qsh = asm_;            // 100*17
    float* ksh = qsh + 1700;      // 100*17
    float* vsh = ksh + 1700;      // 100*17
    float* psh = vsh + 1700;      // 100*100
    int bh = blockIdx.x;
    int b = bh >> 3, hh = bh & 7;
    int tid = threadIdx.x;
    for (int i = tid; i < 1600; i += 256) {
        int m = i >> 4, d = i & 15;
        const float* base = qkv + (size_t)(b*N + m) * TD + hh*16 + d;
        qsh[m*17 + d] = base[0];
        ksh[m*17 + d] = base[D];
        vsh[m*17 + d] = base[2*D];
    }
    __syncthreads();
    int w = tid >> 5, lane = tid & 31;
    for (int n = w; n < 100; n += 8) {
        float qreg[16];
        const float* qp = qsh + n*17;
#pragma unroll
        for (int d = 0; d < 16; d++) qreg[d] = qp[d];
        float sc[4];
        float mx = -1e30f;
#pragma unroll
        for (int j = 0; j < 4; j++) {
            int m = lane + 32*j;
            if (m < 100) {
                const float* kp = ksh + m*17;
                float a0 = 0.f, a1 = 0.f;
#pragma unroll
                for (int d = 0; d < 16; d += 2) {
                    a0 = fmaf(qreg[d],   kp[d],   a0);
                    a1 = fmaf(qreg[d+1], kp[d+1], a1);
                }
                sc[j] = (a0 + a1) * 0.25f;
                mx = fmaxf(mx, sc[j]);
            } else sc[j] = -1e30f;
        }
#pragma unroll
        for (int off = 16; off; off >>= 1) mx = fmaxf(mx, __shfl_xor_sync(0xffffffffu, mx, off));
        double sum = 0.0, ev[4];
#pragma unroll
        for (int j = 0; j < 4; j++) {
            int m = lane + 32*j;
            if (m < 100) { ev[j] = exp((double)(sc[j] - mx)); sum += ev[j]; }
            else ev[j] = 0.0;
        }
#pragma unroll
        for (int off = 16; off; off >>= 1) sum += __shfl_xor_sync(0xffffffffu, sum, off);
        double inv = 1.0 / sum;
#pragma unroll
        for (int j = 0; j < 4; j++) {
            int m = lane + 32*j;
            if (m < 100) psh[n*100 + m] = (float)(ev[j] * inv);
        }
    }
    __syncthreads();
    for (int idx = tid; idx < 1600; idx += 256) {
        int n = idx >> 4, dk = idx & 15;
        const float* pp = psh + n*100;
        const float* vp = vsh + dk;
        float a0 = 0.f, a1 = 0.f;
#pragma unroll 4
        for (int m = 0; m < 100; m += 2) {
            a0 = fmaf(pp[m],   vp[(m)*17],   a0);
            a1 = fmaf(pp[m+1], vp[(m+1)*17], a1);
        }
        o[(size_t)(b*N + n) * D + hh*16 + dk] = a0 + a1;
    }
}

// ---------------------------------------------------------------------------
// BN finalize: reduce 400 per-block partials (double), store mean/rstd.
// ---------------------------------------------------------------------------
__global__ void bn_stats2_kernel() {
    int c = threadIdx.x;
    double a = 0.0, q = 0.0;
    for (int p = 0; p < 400; p++) { a += (double)g_part32[0][p][c]; q += (double)g_part32[1][p][c]; }
    double mean = a * (1.0 / (double)M_ROWS);
    double var  = q * (1.0 / (double)M_ROWS) - mean*mean;
    g_mean[c] = mean;
    g_rstd[c] = 1.0 / sqrt(var + 1e-5);
}
__global__ void bn_apply_kernel(const float* __restrict__ s, const float* __restrict__ gb,
                                float* __restrict__ h) {
    int idx = blockIdx.x * blockDim.x + threadIdx.x;   // over M_ROWS*32
    if (idx >= M_ROWS * 32) return;
    float4 v = *reinterpret_cast<const float4*>(&s[(size_t)idx*4]);
    int d0 = (idx * 4) & 127;
    float4 o;
    o.x = (float)((double)gb[d0+0] * ((double)v.x - g_mean[d0+0]) * g_rstd[d0+0] + (double)gb[D+d0+0]);
    o.y = (float)((double)gb[d0+1] * ((double)v.y - g_mean[d0+1]) * g_rstd[d0+1] + (double)gb[D+d0+1]);
    o.z = (float)((double)gb[d0+2] * ((double)v.z - g_mean[d0+2]) * g_rstd[d0+2] + (double)gb[D+d0+2]);
    o.w = (float)((double)gb[d0+3] * ((double)v.w - g_mean[d0+3]) * g_rstd[d0+3] + (double)gb[D+d0+3]);
    *reinterpret_cast<float4*>(&h[(size_t)idx*4]) = o;
}

// ---------------------------------------------------------------------------
// wphw[d] = Wph @ Wstep (column d)
// ---------------------------------------------------------------------------
__global__ void wphw_kernel(const float* __restrict__ Wph, const float* __restrict__ Wstep) {
    int d = threadIdx.x;
    double a0 = 0.0, a1 = 0.0;
    for (int k = 0; k < 2*D; k += 2) {
        a0 = fma((double)Wph[k],   (double)Wstep[(k)*D + d],   a0);
        a1 = fma((double)Wph[k+1], (double)Wstep[(k+1)*D + d], a1);
    }
    g_wphw[d] = a0 + a1;
}

// ---------------------------------------------------------------------------
// Per-batch: hm = mean_n(h); fc = hm @ Wf; q0 = fc + wphw
// ---------------------------------------------------------------------------
__global__ void meanfix_kernel(const float* __restrict__ Wf) {
    __shared__ float sh[D];
    int b = blockIdx.x, d = threadIdx.x;
    double a = 0.0;
    for (int n = 0; n < N; n++) a += (double)g_h[(size_t)(b*N + n) * D + d];
    sh[d] = (float)(a * (1.0 / (double)N));
    __syncthreads();
    double fc = 0.0;
    for (int k = 0; k < D; k++) fc = fma((double)sh[k], (double)Wf[k*D + d], fc);
    g_fc[b*D + d] = (float)fc;
    g_q0[b*D + d] = (float)(fc + g_wphw[d]);
}

// ---------------------------------------------------------------------------
// Persistent greedy decode v4. 512 threads, 2 blocks/SM.
// g2 stage eliminated: logits_n = g . lKW[n] with lKW = lK @ Wout^T precomputed.
// ---------------------------------------------------------------------------
#define HPS2 257
#define DEC_SMEM_BYTES (16 + (N*HPS2 + 128 + 128 + 800 + 128 + 512 + 100)*4 + 202*4)

__global__ __launch_bounds__(512, 2)
void decode_kernel(const float* __restrict__ x,
                   float* __restrict__ out) {
    extern __shared__ double dsm[];
    double* sh_ll  = dsm;
    float* sh_hp   = (float*)(dsm + 2);     // 100*257 (gK | gV)
    float* sh_q    = sh_hp + N*HPS2;        // 128
    float* sh_qb   = sh_q + D;              // 128
    float* sh_c    = sh_qb + D;             // 800
    float* sh_g    = sh_c + 800;            // 128
    float* sh_part = sh_g + D;              // 512
    float* sh_lg   = sh_part + 512;         // 100
    int*   sh_mask = (int*)(sh_lg + 100);
    int*   sh_pi   = sh_mask + 100;
    int*   sh_ctrl = sh_pi + 100;

    const float NF = 0.08838834764831843f;
    int b = blockIdx.x, tid = threadIdx.x;
    int w = tid >> 5, lane = tid & 31;
    int dd = tid & 127, part = tid >> 7;
    const float* lkwB = g_lkw + (size_t)b * N * D;

    for (int i = tid; i < N*256; i += 512) {
        int n = i >> 8, j = i & 255;
        sh_hp[n*HPS2 + j] = g_3d[(size_t)b * (N*TD) + n*TD + j];
    }
    if (tid < N) sh_mask[tid] = 0;
    if (tid == 0) { sh_ll[0] = 0.0; sh_ctrl[0] = 0; sh_ctrl[1] = 0; }
    __syncthreads();

    for (int s = 0; s < N; s++) {
        // 1. q from precomputed tables
        if (tid < 128) {
            if (s == 0) {
                sh_q[tid] = g_q0[b*D + tid];
            } else {
                float qb;
                if (s == 1) {
                    qb = g_fc[b*D + tid] + g_ef[(size_t)(b*N + sh_ctrl[0]) * D + tid];
                    sh_qb[tid] = qb;
                } else qb = sh_qb[tid];
                sh_q[tid] = qb + g_ed[(size_t)(b*N + sh_ctrl[1]) * D + tid];
            }
        }
        __syncthreads();
        // 2. compat [H,N]
        for (int idx = tid; idx < 800; idx += 512) {
            int hh = idx / 100, n = idx - hh*100;
            const float* kp = sh_hp + n*HPS2 + hh*16;
            const float* qp = sh_q + hh*16;
            float a0 = 0.f, a1 = 0.f;
#pragma unroll
            for (int d2 = 0; d2 < 16; d2 += 2) {
                a0 = fmaf(qp[d2],   kp[d2],   a0);
                a1 = fmaf(qp[d2+1], kp[d2+1], a1);
            }
            sh_c[idx] = sh_mask[n] ? NEGV : (a0 + a1) * NF;
        }
        __syncthreads();
        // 3. softmax, warps 0-7 (double exp)
        if (w < 8) {
            int head = w;
            float mx = -1e30f;
            for (int n = lane; n < 100; n += 32) mx = fmaxf(mx, sh_c[head*100 + n]);
#pragma unroll
            for (int off = 16; off; off >>= 1) mx = fmaxf(mx, __shfl_xor_sync(0xffffffffu, mx, off));
            double sum = 0.0, ev[4];
#pragma unroll
            for (int j = 0; j < 4; j++) {
                int n = lane + 32*j;
                if (n < 100) { ev[j] = exp((double)(sh_c[head*100 + n] - mx)); sum += ev[j]; }
                else ev[j] = 0.0;
            }
#pragma unroll
            for (int off = 16; off; off >>= 1) sum += __shfl_xor_sync(0xffffffffu, sum, off);
            double inv = 1.0 / sum;
#pragma unroll
            for (int j = 0; j < 4; j++) {
                int n = lane + 32*j;
                if (n < 100) sh_c[head*100 + n] = (float)(ev[j] * inv);
            }
        }
        __syncthreads();
        // 4. glimpse partials
        {
            int hh = dd >> 4;
            const float* pp = sh_c + hh*100 + part*25;
            const float* vp = sh_hp + (size_t)(part*25) * HPS2 + D + dd;
            float a0 = 0.f, a1 = 0.f;
#pragma unroll 4
            for (int n = 0; n < 24; n += 2) {
                a0 = fmaf(pp[n],   vp[(n)*HPS2],   a0);
                a1 = fmaf(pp[n+1], vp[(n+1)*HPS2], a1);
            }
            a0 = fmaf(pp[24], vp[24*HPS2], a0);
            sh_part[tid] = a0 + a1;
        }
        __syncthreads();
        if (tid < 128) sh_g[tid] = sh_part[tid] + sh_part[tid+128] + sh_part[tid+256] + sh_part[tid+384];
        __syncthreads();
        // 5. logits partials: lKW from L2 (float4 per thread)
        if (dd < 100) {
            int k0 = part * 32;
            const float* lp = lkwB + (size_t)dd * D + k0;
            float a0 = 0.f, a1 = 0.f;
#pragma unroll
            for (int q4 = 0; q4 < 8; q4++) {
                float4 v = __ldg(reinterpret_cast<const float4*>(lp + q4*4));
                float4 g = *reinterpret_cast<const float4*>(&sh_g[k0 + q4*4]);
                a0 = fmaf(g.x, v.x, a0); a1 = fmaf(g.y, v.y, a1);
                a0 = fmaf(g.z, v.z, a0); a1 = fmaf(g.w, v.w, a1);
            }
            sh_part[tid] = a0 + a1;
        }
        __syncthreads();
        if (tid < 100) {
            double a = (double)(sh_part[tid] + sh_part[tid+128] + sh_part[tid+256] + sh_part[tid+384]);
            sh_lg[tid] = sh_mask[tid] ? NEGV : (float)(tanh(a * (double)NF) * CLIPV);
        }
        __syncthreads();
        // 6. argmax + logsumexp, warp 0
        if (w == 0) {
            float mx = -1e30f; int mi = N + 1;
            for (int n = lane; n < N; n += 32) {
                float v = sh_lg[n];
                if (v > mx) { mx = v; mi = n; }
            }
#pragma unroll
            for (int off = 16; off; off >>= 1) {
                float om = __shfl_xor_sync(0xffffffffu, mx, off);
                int   oi = __shfl_xor_sync(0xffffffffu, mi, off);
                if (om > mx || (om == mx && oi < mi)) { mx = om; mi = oi; }
            }
            double sum = 0.0;
            for (int n = lane; n < N; n += 32) sum += exp((double)sh_lg[n] - (double)mx);
#pragma unroll
            for (int off = 16; off; off >>= 1) sum += __shfl_xor_sync(0xffffffffu, sum, off);
            if (lane == 0) {
                double lse = (double)mx + log(sum);
                sh_ll[0] += (double)sh_lg[mi] - lse;
                sh_mask[mi] = 1;
                sh_ctrl[1] = mi;
                if (s == 0) sh_ctrl[0] = mi;
                sh_pi[s] = mi;
                out[2*B + b*N + s] = (float)mi;
            }
        }
        __syncthreads();
    }
    // tour cost (closed cycle)
    if (tid < N) {
        int a = sh_pi[tid], c = sh_pi[(tid + 1) % N];
        double dx = (double)x[(b*N + a)*2]     - (double)x[(b*N + c)*2];
        double dy = (double)x[(b*N + a)*2 + 1] - (double)x[(b*N + c)*2 + 1];
        sh_lg[tid] = (float)sqrt(dx*dx + dy*dy);
    }
    __syncthreads();
    if (tid == 0) {
        double cst = 0.0;
        for (int t = 0; t < N; t++) cst += (double)sh_lg[t];
        out[b] = (float)cst;
        out[B + b] = (float)sh_ll[0];
    }
}

// ---------------------------------------------------------------------------
extern "C" void kernel_launch(void* const* d_in, const int* in_sizes, int n_in,
                              void* d_out, int out_size) {
    const float* x        = (const float*)d_in[0];
    const float* init_W   = (const float*)d_in[1];
    const float* init_b   = (const float*)d_in[2];
    const float* qkv_W    = (const float*)d_in[3];
    const float* out_W    = (const float*)d_in[4];
    const float* bn1      = (const float*)d_in[5];
    const float* bn2      = (const float*)d_in[6];
    const float* ff1_W    = (const float*)d_in[7];
    const float* ff1_b    = (const float*)d_in[8];
    const float* ff2_W    = (const float*)d_in[9];
    const float* ff2_b    = (const float*)d_in[10];
    const float* Wph      = (const float*)d_in[11];
    const float* nodes_W  = (const float*)d_in[12];
    const float* fixed_W  = (const float*)d_in[13];
    const float* step_W   = (const float*)d_in[14];
    const float* pout_W   = (const float*)d_in[15];
    float* out = (float*)d_out;

    cudaFuncSetAttribute(decode_kernel, cudaFuncAttributeMaxDynamicSharedMemorySize,
                         DEC_SMEM_BYTES + 128);
    cudaFuncSetAttribute(attn_kernel, cudaFuncAttributeMaxDynamicSharedMemorySize,
                         ATTN_SMEM_BYTES + 128);

    float *p_h, *p_3d, *p_ff, *p_o, *p_s, *p_ef, *p_ed, *p_lkw, *p_wt;
    cudaGetSymbolAddress((void**)&p_h,   g_h);
    cudaGetSymbolAddress((void**)&p_3d,  g_3d);
    cudaGetSymbolAddress((void**)&p_ff,  g_ff);
    cudaGetSymbolAddress((void**)&p_o,   g_o);
    cudaGetSymbolAddress((void**)&p_s,   g_s);
    cudaGetSymbolAddress((void**)&p_ef,  g_ef);
    cudaGetSymbolAddress((void**)&p_ed,  g_ed);
    cudaGetSymbolAddress((void**)&p_lkw, g_lkw);
    cudaGetSymbolAddress((void**)&p_wt,  g_wt);

    int vgrid = (M_ROWS * 32 + 255) / 256;   // float4 elementwise grids

    init_embed_kernel<<<vgrid, 256>>>(x, init_W, init_b);
    wphw_kernel<<<1, 128>>>(Wph, step_W);
    transpose_kernel<<<64, 256>>>(pout_W);

    for (int l = 0; l < 2; l++) {
        gemm32_kernel<<<dim3(TD/128, M_ROWS/128), 256>>>(
            p_h, qkv_W + (size_t)l*D*TD, nullptr, nullptr, p_3d, M_ROWS, D, TD, D, 0, 0);
        attn_kernel<<<B*H, 256, ATTN_SMEM_BYTES + 128>>>(p_3d, p_o);
        // s = o @ Wout + h, with fused BN stats
        gemm32_kernel<<<dim3(D/128, M_ROWS/128), 256>>>(
            p_o, out_W + (size_t)l*D*D, nullptr, p_h, p_s, M_ROWS, D, D, D, 0, 1);
        bn_stats2_kernel<<<1, 128>>>();
        bn_apply_kernel<<<vgrid, 256>>>(p_s, bn1 + (size_t)l*2*D, p_h);
        gemm32_kernel<<<dim3(FF/128, M_ROWS/128), 256>>>(
            p_h, ff1_W + (size_t)l*D*FF, ff1_b + (size_t)l*FF, nullptr, p_ff, M_ROWS, D, FF, D, 1, 0);
        // s = ff1 @ W2 + b2 + h, with fused BN stats
        gemm32_kernel<<<dim3(D/128, M_ROWS/128), 256>>>(
            p_ff, ff2_W + (size_t)l*FF*D, ff2_b + (size_t)l*D, p_h, p_s, M_ROWS, FF, D, FF, 0, 1);
        bn_stats2_kernel<<<1, 128>>>();
        bn_apply_kernel<<<vgrid, 256>>>(p_s, bn2 + (size_t)l*2*D, p_h);
    }

    // decoder precompute
    gemm32_kernel<<<dim3(TD/128, M_ROWS/128), 256>>>(
        p_h, nodes_W, nullptr, nullptr, p_3d, M_ROWS, D, TD, D, 0, 0);
    gemm32_kernel<<<dim3(D/128, M_ROWS/128), 256>>>(
        p_h, step_W, nullptr, nullptr, p_ef, M_ROWS, D, D, D, 0, 0);
    gemm32_kernel<<<dim3(D/128, M_ROWS/128), 256>>>(
        p_h, step_W + (size_t)D*D, nullptr, nullptr, p_ed, M_ROWS, D, D, D, 0, 0);
    // lKW = lK @ Wout^T  (lK = strided rows inside g_3d)
    gemm32_kernel<<<dim3(D/128, M_ROWS/128), 256>>>(
        p_3d + 2*D, p_wt, nullptr, nullptr, p_lkw, M_ROWS, D, D, TD, 0, 0);
    meanfix_kernel<<<B, D>>>(fixed_W);

    decode_kernel<<<B, 512, DEC_SMEM_BYTES + 128>>>(x, out);
}

// round 14
// speedup vs baseline: 1.2196x; 1.0112x over previous
#include <cuda_runtime.h>
#include <math.h>
#include <stdint.h>

// Problem constants
#define B 512
#define N 100
#define D 128
#define H 8
#define DK 16
#define FF 512
#define TD 384          // 3*D
#define M_ROWS (B*N)    // 51200
#define NEGV -1e9f
#define CLIPV 10.0

static __device__ float g_h [ (size_t)M_ROWS * D ];     // hidden state
static __device__ float g_3d[ (size_t)M_ROWS * TD ];    // qkv / hp scratch
static __device__ float g_ff[ (size_t)M_ROWS * FF ];    // ff1 output
static __device__ float g_o [ (size_t)M_ROWS * D ];     // attention output
static __device__ float g_s [ (size_t)M_ROWS * D ];     // pre-BN (residual sum)
static __device__ float g_efed[ (size_t)M_ROWS * 256 ]; // h @ [Wstep1|Wstep2]
static __device__ float g_lkw[ (size_t)M_ROWS * D ];    // lK @ Wout^T
static __device__ float g_wt[D*D];                      // Wout^T
static __device__ float g_w2p[D*256];                   // packed [Wstep1|Wstep2]
static __device__ float g_part32[2][400][128];          // per-block BN partials
static __device__ double g_mean[D], g_rstd[D];
static __device__ double g_wphw[D];                     // Wph @ Wstep
static __device__ float g_fc[B*D], g_q0[B*D];           // fixed_ctx, step-0 query

// ---------------------------------------------------------------------------
// h = x @ init_W + init_b  (float4 over D)
// ---------------------------------------------------------------------------
__global__ void init_embed_kernel(const float* __restrict__ x,
                                  const float* __restrict__ W,
                                  const float* __restrict__ bias) {
    int idx = blockIdx.x * blockDim.x + threadIdx.x;   // over M_ROWS*32
    if (idx >= M_ROWS * 32) return;
    int i = idx >> 5, d0 = (idx & 31) * 4;
    double x0 = (double)x[i*2], x1 = (double)x[i*2+1];
    float4 o;
    o.x = (float)(x0 * (double)W[d0+0] + x1 * (double)W[D+d0+0] + (double)bias[d0+0]);
    o.y = (float)(x0 * (double)W[d0+1] + x1 * (double)W[D+d0+1] + (double)bias[d0+1]);
    o.z = (float)(x0 * (double)W[d0+2] + x1 * (double)W[D+d0+2] + (double)bias[d0+2]);
    o.w = (float)(x0 * (double)W[d0+3] + x1 * (double)W[D+d0+3] + (double)bias[d0+3]);
    *reinterpret_cast<float4*>(&g_h[(size_t)idx*4]) = o;
}

// ---------------------------------------------------------------------------
// Wout^T and packed step weights
// ---------------------------------------------------------------------------
__global__ void transpose_kernel(const float* __restrict__ Wout) {
    int idx = blockIdx.x * blockDim.x + threadIdx.x;   // over D*D
    int d = idx >> 7, k = idx & 127;
    g_wt[d*D + k] = Wout[k*D + d];
}
__global__ void pack_w2_kernel(const float* __restrict__ Wstep) {
    int idx = blockIdx.x * blockDim.x + threadIdx.x;   // over D*256
    int k = idx >> 8, j = idx & 255;
    g_w2p[k*256 + j] = (j < 128) ? Wstep[k*D + j] : Wstep[(128 + k)*D + (j - 128)];
}

// ---------------------------------------------------------------------------
// fp32 tiled GEMM v3: k-major A smem (LDG->STS transpose), cp.async B,
// double-buffered, RACE-FREE ordering (loads issued only after the
// post-compute barrier). BM=BN=128, BK=16, 256 threads, 8x8/thread.
// Inner loop: 4 x LDS.128 + 64 FFMA per k.
// bnstats!=0: per-column (sum,sumsq) partials -> g_part32[*][blockIdx.y][*]
// (requires gridDim.x==1, Nc==128).
// ---------------------------------------------------------------------------
__global__ __launch_bounds__(256, 2)
void gemm32_kernel(const float* __restrict__ A, const float* __restrict__ W,
                   const float* __restrict__ bias, const float* __restrict__ res,
                   float* __restrict__ C, int M, int K, int Nc, int lda,
                   int relu, int bnstats) {
    __shared__ float As[2][16][132];     // k-major, 16.9 KB
    __shared__ float Bs[2][16][132];     // k-major, 16.9 KB
    const int tid = threadIdx.x;
    const int tx = tid & 15, ty = tid >> 4;
    const int row0 = blockIdx.y * 128, col0 = blockIdx.x * 128;
    const int ar = tid >> 1, akc = (tid & 1) * 8;   // A: row ar, k cols akc..akc+7
    float acc[8][8];
#pragma unroll
    for (int i = 0; i < 8; i++)
#pragma unroll
        for (int j = 0; j < 8; j++) acc[i][j] = 0.f;

    float4 pa0, pa1;
    auto ldgA = [&](int kt) {
        const float* base = &A[(size_t)(row0 + ar) * lda + kt + akc];
        pa0 = *reinterpret_cast<const float4*>(base);
        pa1 = *reinterpret_cast<const float4*>(base + 4);
    };
    auto stsA = [&](int buf) {
        As[buf][akc+0][ar] = pa0.x; As[buf][akc+1][ar] = pa0.y;
        As[buf][akc+2][ar] = pa0.z; As[buf][akc+3][ar] = pa0.w;
        As[buf][akc+4][ar] = pa1.x; As[buf][akc+5][ar] = pa1.y;
        As[buf][akc+6][ar] = pa1.z; As[buf][akc+7][ar] = pa1.w;
    };
    auto loadB = [&](int kt, int buf) {
#pragma unroll
        for (int p = 0; p < 2; p++) {
            int c = tid + p*256;
            int br = c >> 5, bsub = (c & 31) * 4;
            unsigned db = (unsigned)__cvta_generic_to_shared(&Bs[buf][br][bsub]);
            const float* sb = &W[(size_t)(kt+br)*Nc + col0 + bsub];
            asm volatile("cp.async.cg.shared.global [%0], [%1], 16;" :: "r"(db), "l"(sb));
        }
        asm volatile("cp.async.commit_group;");
    };

    const int T = K >> 4;
    // prologue: A0 -> smem; B0, B1 async; A1 -> regs
    ldgA(0);
    loadB(0, 0);
    stsA(0);
    if (T > 1) { ldgA(16); loadB(16, 1); }
    if (T > 1) asm volatile("cp.async.wait_group 1;");
    else       asm volatile("cp.async.wait_group 0;");
    __syncthreads();

    for (int t = 0; t < T; t++) {
        const int buf = t & 1;
#pragma unroll
        for (int k = 0; k < 16; k++) {
            float a[8], bb[8];
            float4 a0 = *reinterpret_cast<const float4*>(&As[buf][k][ty*4]);
            float4 a1 = *reinterpret_cast<const float4*>(&As[buf][k][64 + ty*4]);
            float4 b0 = *reinterpret_cast<const float4*>(&Bs[buf][k][tx*4]);
            float4 b1 = *reinterpret_cast<const float4*>(&Bs[buf][k][64 + tx*4]);
            a[0]=a0.x;a[1]=a0.y;a[2]=a0.z;a[3]=a0.w;a[4]=a1.x;a[5]=a1.y;a[6]=a1.z;a[7]=a1.w;
            bb[0]=b0.x;bb[1]=b0.y;bb[2]=b0.z;bb[3]=b0.w;bb[4]=b1.x;bb[5]=b1.y;bb[6]=b1.z;bb[7]=b1.w;
#pragma unroll
            for (int i = 0; i < 8; i++)
#pragma unroll
                for (int j = 0; j < 8; j++) acc[i][j] = fmaf(a[i], bb[j], acc[i][j]);
        }
        __syncthreads();                 // all reads of buf done before reuse
        if (t + 1 < T) {
            stsA(1 - buf);               // commit A(t+1) (regs) into other buffer
            if (t + 2 < T) { ldgA((t+2)*16); loadB((t+2)*16, buf); }
            if (t + 2 < T) asm volatile("cp.async.wait_group 1;");
            else           asm volatile("cp.async.wait_group 0;");
            __syncthreads();             // A(t+1) visible, B(t+1) complete
        }
    }

    float cs[8], cq[8];
#pragma unroll
    for (int j = 0; j < 8; j++) { cs[j] = 0.f; cq[j] = 0.f; }
#pragma unroll
    for (int i = 0; i < 8; i++) {
        int r = row0 + ty*4 + (i < 4 ? i : 60 + i);
#pragma unroll
        for (int j = 0; j < 8; j++) {
            int c = col0 + tx*4 + (j < 4 ? j : 60 + j);
            float v = acc[i][j];
            if (bias) v += bias[c];
            if (res)  v += res[(size_t)r*Nc + c];
            if (relu) v = fmaxf(v, 0.f);
            C[(size_t)r*Nc + c] = v;
            cs[j] += v;
            cq[j] = fmaf(v, v, cq[j]);
        }
    }
    if (bnstats) {
        float* red1 = &As[0][0][0];      // reuse smem: 16x128
        float* red2 = &Bs[0][0][0];
        __syncthreads();
#pragma unroll
        for (int j = 0; j < 8; j++) {
            int c = tx*4 + (j < 4 ? j : 60 + j);
            red1[ty*128 + c] = cs[j];
            red2[ty*128 + c] = cq[j];
        }
        __syncthreads();
        if (tid < 128) {
            float ssum = 0.f, ssq = 0.f;
#pragma unroll
            for (int t = 0; t < 16; t++) { ssum += red1[t*128 + tid]; ssq += red2[t*128 + tid]; }
            g_part32[0][blockIdx.y][tid] = ssum;
            g_part32[1][blockIdx.y][tid] = ssq;
        }
    }
}

// ---------------------------------------------------------------------------
// Fused MHA (proven version): one block per (b,h), 256 threads.
// ---------------------------------------------------------------------------
#define ATTN_SMEM_BYTES ((3*1700 + 10000) * 4)
__global__ __launch_bounds__(256)
void attn_kernel(const float* __restrict__ qkv, float* __restrict__ o) {
    extern __shared__ float asm_[];
    float* qsh = asm_;            // 100*17
    float* ksh = qsh + 1700;      // 100*17
    float* vsh = ksh + 1700;      // 100*17
    float* psh = vsh + 1700;      // 100*100
    int bh = blockIdx.x;
    int b = bh >> 3, hh = bh & 7;
    int tid = threadIdx.x;
    for (int i = tid; i < 1600; i += 256) {
        int m = i >> 4, d = i & 15;
        const float* base = qkv + (size_t)(b*N + m) * TD + hh*16 + d;
        qsh[m*17 + d] = base[0];
        ksh[m*17 + d] = base[D];
        vsh[m*17 + d] = base[2*D];
    }
    __syncthreads();
    int w = tid >> 5, lane = tid & 31;
    for (int n = w; n < 100; n += 8) {
        float qreg[16];
        const float* qp = qsh + n*17;
#pragma unroll
        for (int d = 0; d < 16; d++) qreg[d] = qp[d];
        float sc[4];
        float mx = -1e30f;
#pragma unroll
        for (int j = 0; j < 4; j++) {
            int m = lane + 32*j;
            if (m < 100) {
                const float* kp = ksh + m*17;
                float a0 = 0.f, a1 = 0.f;
#pragma unroll
                for (int d = 0; d < 16; d += 2) {
                    a0 = fmaf(qreg[d],   kp[d],   a0);
                    a1 = fmaf(qreg[d+1], kp[d+1], a1);
                }
                sc[j] = (a0 + a1) * 0.25f;
                mx = fmaxf(mx, sc[j]);
            } else sc[j] = -1e30f;
        }
#pragma unroll
        for (int off = 16; off; off >>= 1) mx = fmaxf(mx, __shfl_xor_sync(0xffffffffu, mx, off));
        double sum = 0.0, ev[4];
#pragma unroll
        for (int j = 0; j < 4; j++) {
            int m = lane + 32*j;
            if (m < 100) { ev[j] = exp((double)(sc[j] - mx)); sum += ev[j]; }
            else ev[j] = 0.0;
        }
#pragma unroll
        for (int off = 16; off; off >>= 1) sum += __shfl_xor_sync(0xffffffffu, sum, off);
        double inv = 1.0 / sum;
#pragma unroll
        for (int j = 0; j < 4; j++) {
            int m = lane + 32*j;
            if (m < 100) psh[n*100 + m] = (float)(ev[j] * inv);
        }
    }
    __syncthreads();
    for (int idx = tid; idx < 1600; idx += 256) {
        int n = idx >> 4, dk = idx & 15;
        const float* pp = psh + n*100;
        const float* vp = vsh + dk;
        float a0 = 0.f, a1 = 0.f;
#pragma unroll 4
        for (int m = 0; m < 100; m += 2) {
            a0 = fmaf(pp[m],   vp[(m)*17],   a0);
            a1 = fmaf(pp[m+1], vp[(m+1)*17], a1);
        }
        o[(size_t)(b*N + n) * D + hh*16 + dk] = a0 + a1;
    }
}

// ---------------------------------------------------------------------------
// BN finalize + apply
// ---------------------------------------------------------------------------
__global__ void bn_stats2_kernel() {
    int c = threadIdx.x;
    double a = 0.0, q = 0.0;
    for (int p = 0; p < 400; p++) { a += (double)g_part32[0][p][c]; q += (double)g_part32[1][p][c]; }
    double mean = a * (1.0 / (double)M_ROWS);
    double var  = q * (1.0 / (double)M_ROWS) - mean*mean;
    g_mean[c] = mean;
    g_rstd[c] = 1.0 / sqrt(var + 1e-5);
}
__global__ void bn_apply_kernel(const float* __restrict__ s, const float* __restrict__ gb,
                                float* __restrict__ h) {
    int idx = blockIdx.x * blockDim.x + threadIdx.x;   // over M_ROWS*32
    if (idx >= M_ROWS * 32) return;
    float4 v = *reinterpret_cast<const float4*>(&s[(size_t)idx*4]);
    int d0 = (idx * 4) & 127;
    float4 o;
    o.x = (float)((double)gb[d0+0] * ((double)v.x - g_mean[d0+0]) * g_rstd[d0+0] + (double)gb[D+d0+0]);
    o.y = (float)((double)gb[d0+1] * ((double)v.y - g_mean[d0+1]) * g_rstd[d0+1] + (double)gb[D+d0+1]);
    o.z = (float)((double)gb[d0+2] * ((double)v.z - g_mean[d0+2]) * g_rstd[d0+2] + (double)gb[D+d0+2]);
    o.w = (float)((double)gb[d0+3] * ((double)v.w - g_mean[d0+3]) * g_rstd[d0+3] + (double)gb[D+d0+3]);
    *reinterpret_cast<float4*>(&h[(size_t)idx*4]) = o;
}

// ---------------------------------------------------------------------------
// wphw[d] = Wph @ Wstep (column d)
// ---------------------------------------------------------------------------
__global__ void wphw_kernel(const float* __restrict__ Wph, const float* __restrict__ Wstep) {
    int d = threadIdx.x;
    double a0 = 0.0, a1 = 0.0;
    for (int k = 0; k < 2*D; k += 2) {
        a0 = fma((double)Wph[k],   (double)Wstep[(k)*D + d],   a0);
        a1 = fma((double)Wph[k+1], (double)Wstep[(k+1)*D + d], a1);
    }
    g_wphw[d] = a0 + a1;
}

// ---------------------------------------------------------------------------
// Per-batch: hm = mean_n(h); fc = hm @ Wf; q0 = fc + wphw
// ---------------------------------------------------------------------------
__global__ void meanfix_kernel(const float* __restrict__ Wf) {
    __shared__ float sh[D];
    int b = blockIdx.x, d = threadIdx.x;
    double a = 0.0;
    for (int n = 0; n < N; n++) a += (double)g_h[(size_t)(b*N + n) * D + d];
    sh[d] = (float)(a * (1.0 / (double)N));
    __syncthreads();
    double fc = 0.0;
    for (int k = 0; k < D; k++) fc = fma((double)sh[k], (double)Wf[k*D + d], fc);
    g_fc[b*D + d] = (float)fc;
    g_q0[b*D + d] = (float)(fc + g_wphw[d]);
}

// ---------------------------------------------------------------------------
// Persistent greedy decode v4. 512 threads, 2 blocks/SM.
// q lookups from combined g_efed; logits via precomputed lKW.
// ---------------------------------------------------------------------------
#define HPS2 257
#define DEC_SMEM_BYTES (16 + (N*HPS2 + 128 + 128 + 800 + 128 + 512 + 100)*4 + 202*4)

__global__ __launch_bounds__(512, 2)
void decode_kernel(const float* __restrict__ x,
                   float* __restrict__ out) {
    extern __shared__ double dsm[];
    double* sh_ll  = dsm;
    float* sh_hp   = (float*)(dsm + 2);     // 100*257 (gK | gV)
    float* sh_q    = sh_hp + N*HPS2;        // 128
    float* sh_qb   = sh_q + D;              // 128
    float* sh_c    = sh_qb + D;             // 800
    float* sh_g    = sh_c + 800;            // 128
    float* sh_part = sh_g + D;              // 512
    float* sh_lg   = sh_part + 512;         // 100
    int*   sh_mask = (int*)(sh_lg + 100);
    int*   sh_pi   = sh_mask + 100;
    int*   sh_ctrl = sh_pi + 100;

    const float NF = 0.08838834764831843f;
    int b = blockIdx.x, tid = threadIdx.x;
    int w = tid >> 5, lane = tid & 31;
    int dd = tid & 127, part = tid >> 7;
    const float* lkwB = g_lkw + (size_t)b * N * D;

    for (int i = tid; i < N*256; i += 512) {
        int n = i >> 8, j = i & 255;
        sh_hp[n*HPS2 + j] = g_3d[(size_t)b * (N*TD) + n*TD + j];
    }
    if (tid < N) sh_mask[tid] = 0;
    if (tid == 0) { sh_ll[0] = 0.0; sh_ctrl[0] = 0; sh_ctrl[1] = 0; }
    __syncthreads();

    for (int s = 0; s < N; s++) {
        // 1. q from precomputed tables
        if (tid < 128) {
            if (s == 0) {
                sh_q[tid] = g_q0[b*D + tid];
            } else {
                float qb;
                if (s == 1) {
                    qb = g_fc[b*D + tid] + g_efed[(size_t)(b*N + sh_ctrl[0]) * 256 + tid];
                    sh_qb[tid] = qb;
                } else qb = sh_qb[tid];
                sh_q[tid] = qb + g_efed[(size_t)(b*N + sh_ctrl[1]) * 256 + 128 + tid];
            }
        }
        __syncthreads();
        // 2. compat [H,N]
        for (int idx = tid; idx < 800; idx += 512) {
            int hh = idx / 100, n = idx - hh*100;
            const float* kp = sh_hp + n*HPS2 + hh*16;
            const float* qp = sh_q + hh*16;
            float a0 = 0.f, a1 = 0.f;
#pragma unroll
            for (int d2 = 0; d2 < 16; d2 += 2) {
                a0 = fmaf(qp[d2],   kp[d2],   a0);
                a1 = fmaf(qp[d2+1], kp[d2+1], a1);
            }
            sh_c[idx] = sh_mask[n] ? NEGV : (a0 + a1) * NF;
        }
        __syncthreads();
        // 3. softmax, warps 0-7 (double exp)
        if (w < 8) {
            int head = w;
            float mx = -1e30f;
            for (int n = lane; n < 100; n += 32) mx = fmaxf(mx, sh_c[head*100 + n]);
#pragma unroll
            for (int off = 16; off; off >>= 1) mx = fmaxf(mx, __shfl_xor_sync(0xffffffffu, mx, off));
            double sum = 0.0, ev[4];
#pragma unroll
            for (int j = 0; j < 4; j++) {
                int n = lane + 32*j;
                if (n < 100) { ev[j] = exp((double)(sh_c[head*100 + n] - mx)); sum += ev[j]; }
                else ev[j] = 0.0;
            }
#pragma unroll
            for (int off = 16; off; off >>= 1) sum += __shfl_xor_sync(0xffffffffu, sum, off);
            double inv = 1.0 / sum;
#pragma unroll
            for (int j = 0; j < 4; j++) {
                int n = lane + 32*j;
                if (n < 100) sh_c[head*100 + n] = (float)(ev[j] * inv);
            }
        }
        __syncthreads();
        // 4. glimpse partials
        {
            int hh = dd >> 4;
            const float* pp = sh_c + hh*100 + part*25;
            const float* vp = sh_hp + (size_t)(part*25) * HPS2 + D + dd;
            float a0 = 0.f, a1 = 0.f;
#pragma unroll 4
            for (int n = 0; n < 24; n += 2) {
                a0 = fmaf(pp[n],   vp[(n)*HPS2],   a0);
                a1 = fmaf(pp[n+1], vp[(n+1)*HPS2], a1);
            }
            a0 = fmaf(pp[24], vp[24*HPS2], a0);
            sh_part[tid] = a0 + a1;
        }
        __syncthreads();
        if (tid < 128) sh_g[tid] = sh_part[tid] + sh_part[tid+128] + sh_part[tid+256] + sh_part[tid+384];
        __syncthreads();
        // 5. logits partials: lKW from L2 (float4 per thread)
        if (dd < 100) {
            int k0 = part * 32;
            const float* lp = lkwB + (size_t)dd * D + k0;
            float a0 = 0.f, a1 = 0.f;
#pragma unroll
            for (int q4 = 0; q4 < 8; q4++) {
                float4 v = __ldg(reinterpret_cast<const float4*>(lp + q4*4));
                float4 g = *reinterpret_cast<const float4*>(&sh_g[k0 + q4*4]);
                a0 = fmaf(g.x, v.x, a0); a1 = fmaf(g.y, v.y, a1);
                a0 = fmaf(g.z, v.z, a0); a1 = fmaf(g.w, v.w, a1);
            }
            sh_part[tid] = a0 + a1;
        }
        __syncthreads();
        if (tid < 100) {
            double a = (double)(sh_part[tid] + sh_part[tid+128] + sh_part[tid+256] + sh_part[tid+384]);
            sh_lg[tid] = sh_mask[tid] ? NEGV : (float)(tanh(a * (double)NF) * CLIPV);
        }
        __syncthreads();
        // 6. argmax + logsumexp, warp 0
        if (w == 0) {
            float mx = -1e30f; int mi = N + 1;
            for (int n = lane; n < N; n += 32) {
                float v = sh_lg[n];
                if (v > mx) { mx = v; mi = n; }
            }
#pragma unroll
            for (int off = 16; off; off >>= 1) {
                float om = __shfl_xor_sync(0xffffffffu, mx, off);
                int   oi = __shfl_xor_sync(0xffffffffu, mi, off);
                if (om > mx || (om == mx && oi < mi)) { mx = om; mi = oi; }
            }
            double sum = 0.0;
            for (int n = lane; n < N; n += 32) sum += exp((double)sh_lg[n] - (double)mx);
#pragma unroll
            for (int off = 16; off; off >>= 1) sum += __shfl_xor_sync(0xffffffffu, sum, off);
            if (lane == 0) {
                double lse = (double)mx + log(sum);
                sh_ll[0] += (double)sh_lg[mi] - lse;
                sh_mask[mi] = 1;
                sh_ctrl[1] = mi;
                if (s == 0) sh_ctrl[0] = mi;
                sh_pi[s] = mi;
                out[2*B + b*N + s] = (float)mi;
            }
        }
        __syncthreads();
    }
    // tour cost (closed cycle)
    if (tid < N) {
        int a = sh_pi[tid], c = sh_pi[(tid + 1) % N];
        double dx = (double)x[(b*N + a)*2]     - (double)x[(b*N + c)*2];
        double dy = (double)x[(b*N + a)*2 + 1] - (double)x[(b*N + c)*2 + 1];
        sh_lg[tid] = (float)sqrt(dx*dx + dy*dy);
    }
    __syncthreads();
    if (tid == 0) {
        double cst = 0.0;
        for (int t = 0; t < N; t++) cst += (double)sh_lg[t];
        out[b] = (float)cst;
        out[B + b] = (float)sh_ll[0];
    }
}

// ---------------------------------------------------------------------------
extern "C" void kernel_launch(void* const* d_in, const int* in_sizes, int n_in,
                              void* d_out, int out_size) {
    const float* x        = (const float*)d_in[0];
    const float* init_W   = (const float*)d_in[1];
    const float* init_b   = (const float*)d_in[2];
    const float* qkv_W    = (const float*)d_in[3];
    const float* out_W    = (const float*)d_in[4];
    const float* bn1      = (const float*)d_in[5];
    const float* bn2      = (const float*)d_in[6];
    const float* ff1_W    = (const float*)d_in[7];
    const float* ff1_b    = (const float*)d_in[8];
    const float* ff2_W    = (const float*)d_in[9];
    const float* ff2_b    = (const float*)d_in[10];
    const float* Wph      = (const float*)d_in[11];
    const float* nodes_W  = (const float*)d_in[12];
    const float* fixed_W  = (const float*)d_in[13];
    const float* step_W   = (const float*)d_in[14];
    const float* pout_W   = (const float*)d_in[15];
    float* out = (float*)d_out;

    cudaFuncSetAttribute(decode_kernel, cudaFuncAttributeMaxDynamicSharedMemorySize,
                         DEC_SMEM_BYTES + 128);
    cudaFuncSetAttribute(attn_kernel, cudaFuncAttributeMaxDynamicSharedMemorySize,
                         ATTN_SMEM_BYTES + 128);

    float *p_h, *p_3d, *p_ff, *p_o, *p_s, *p_efed, *p_lkw, *p_wt, *p_w2p;
    cudaGetSymbolAddress((void**)&p_h,    g_h);
    cudaGetSymbolAddress((void**)&p_3d,   g_3d);
    cudaGetSymbolAddress((void**)&p_ff,   g_ff);
    cudaGetSymbolAddress((void**)&p_o,    g_o);
    cudaGetSymbolAddress((void**)&p_s,    g_s);
    cudaGetSymbolAddress((void**)&p_efed, g_efed);
    cudaGetSymbolAddress((void**)&p_lkw,  g_lkw);
    cudaGetSymbolAddress((void**)&p_wt,   g_wt);
    cudaGetSymbolAddress((void**)&p_w2p,  g_w2p);

    int vgrid = (M_ROWS * 32 + 255) / 256;   // float4 elementwise grids

    init_embed_kernel<<<vgrid, 256>>>(x, init_W, init_b);
    wphw_kernel<<<1, 128>>>(Wph, step_W);
    transpose_kernel<<<64, 256>>>(pout_W);
    pack_w2_kernel<<<128, 256>>>(step_W);

    for (int l = 0; l < 2; l++) {
        gemm32_kernel<<<dim3(TD/128, M_ROWS/128), 256>>>(
            p_h, qkv_W + (size_t)l*D*TD, nullptr, nullptr, p_3d, M_ROWS, D, TD, D, 0, 0);
        attn_kernel<<<B*H, 256, ATTN_SMEM_BYTES + 128>>>(p_3d, p_o);
        // s = o @ Wout + h, with fused BN stats
        gemm32_kernel<<<dim3(D/128, M_ROWS/128), 256>>>(
            p_o, out_W + (size_t)l*D*D, nullptr, p_h, p_s, M_ROWS, D, D, D, 0, 1);
        bn_stats2_kernel<<<1, 128>>>();
        bn_apply_kernel<<<vgrid, 256>>>(p_s, bn1 + (size_t)l*2*D, p_h);
        gemm32_kernel<<<dim3(FF/128, M_ROWS/128), 256>>>(
            p_h, ff1_W + (size_t)l*D*FF, ff1_b + (size_t)l*FF, nullptr, p_ff, M_ROWS, D, FF, D, 1, 0);
        // s = ff1 @ W2 + b2 + h, with fused BN stats
        gemm32_kernel<<<dim3(D/128, M_ROWS/128), 256>>>(
            p_ff, ff2_W + (size_t)l*FF*D, ff2_b + (size_t)l*D, p_h, p_s, M_ROWS, FF, D, FF, 0, 1);
        bn_stats2_kernel<<<1, 128>>>();
        bn_apply_kernel<<<vgrid, 256>>>(p_s, bn2 + (size_t)l*2*D, p_h);
    }

    // decoder precompute
    gemm32_kernel<<<dim3(TD/128, M_ROWS/128), 256>>>(
        p_h, nodes_W, nullptr, nullptr, p_3d, M_ROWS, D, TD, D, 0, 0);
    // combined ef|ed table: h @ [Wstep1|Wstep2]  (Nc=256)
    gemm32_kernel<<<dim3(2, M_ROWS/128), 256>>>(
        p_h, p_w2p, nullptr, nullptr, p_efed, M_ROWS, D, 256, D, 0, 0);
    // lKW = lK @ Wout^T  (lK = strided rows inside g_3d)
    gemm32_kernel<<<dim3(D/128, M_ROWS/128), 256>>>(
        p_3d + 2*D, p_wt, nullptr, nullptr, p_lkw, M_ROWS, D, D, TD, 0, 0);
    meanfix_kernel<<<B, D>>>(fixed_W);

    decode_kernel<<<B, 512, DEC_SMEM_BYTES + 128>>>(x, out);
}

// round 15
// speedup vs baseline: 1.2227x; 1.0026x over previous
#include <cuda_runtime.h>
#include <math.h>
#include <stdint.h>

// Problem constants
#define B 512
#define N 100
#define D 128
#define H 8
#define DK 16
#define FF 512
#define TD 384          // 3*D
#define M_ROWS (B*N)    // 51200
#define NEGV -1e9f
#define CLIPV 10.0

static __device__ float g_h [ (size_t)M_ROWS * D ];     // pre-BN2 / embed buffer
static __device__ float g_3d[ (size_t)M_ROWS * TD ];    // qkv / hp scratch
static __device__ float g_ff[ (size_t)M_ROWS * FF ];    // ff1 output
static __device__ float g_o [ (size_t)M_ROWS * D ];     // attention output
static __device__ float g_s [ (size_t)M_ROWS * D ];     // pre-BN1 buffer
static __device__ float g_efed[ (size_t)M_ROWS * 256 ]; // h @ [Wstep1|Wstep2]
static __device__ float g_lkw[ (size_t)M_ROWS * D ];    // lK @ Wout^T
static __device__ float g_wt[D*D];                      // Wout^T
static __device__ float g_w2p[D*256];                   // packed [Wstep1|Wstep2]
static __device__ float g_part32[2][400][128];          // per-block BN partials
static __device__ float g_bnsc[D], g_bnsh[D];           // current BN scale/shift
static __device__ double g_wphw[D];                     // Wph @ Wstep
static __device__ float g_fc[B*D], g_q0[B*D];           // fixed_ctx, step-0 query

// ---------------------------------------------------------------------------
// h = x @ init_W + init_b  (float4 over D)
// ---------------------------------------------------------------------------
__global__ void init_embed_kernel(const float* __restrict__ x,
                                  const float* __restrict__ W,
                                  const float* __restrict__ bias) {
    int idx = blockIdx.x * blockDim.x + threadIdx.x;   // over M_ROWS*32
    if (idx >= M_ROWS * 32) return;
    int i = idx >> 5, d0 = (idx & 31) * 4;
    double x0 = (double)x[i*2], x1 = (double)x[i*2+1];
    float4 o;
    o.x = (float)(x0 * (double)W[d0+0] + x1 * (double)W[D+d0+0] + (double)bias[d0+0]);
    o.y = (float)(x0 * (double)W[d0+1] + x1 * (double)W[D+d0+1] + (double)bias[d0+1]);
    o.z = (float)(x0 * (double)W[d0+2] + x1 * (double)W[D+d0+2] + (double)bias[d0+2]);
    o.w = (float)(x0 * (double)W[d0+3] + x1 * (double)W[D+d0+3] + (double)bias[d0+3]);
    *reinterpret_cast<float4*>(&g_h[(size_t)idx*4]) = o;
}

// ---------------------------------------------------------------------------
// Wout^T and packed step weights
// ---------------------------------------------------------------------------
__global__ void transpose_kernel(const float* __restrict__ Wout) {
    int idx = blockIdx.x * blockDim.x + threadIdx.x;   // over D*D
    int d = idx >> 7, k = idx & 127;
    g_wt[d*D + k] = Wout[k*D + d];
}
__global__ void pack_w2_kernel(const float* __restrict__ Wstep) {
    int idx = blockIdx.x * blockDim.x + threadIdx.x;   // over D*256
    int k = idx >> 8, j = idx & 255;
    g_w2p[k*256 + j] = (j < 128) ? Wstep[k*D + j] : Wstep[(128 + k)*D + (j - 128)];
}

// ---------------------------------------------------------------------------
// fp32 tiled GEMM v4: k-major A smem, cp.async B, double-buffered, race-free.
// Optional per-column affine on A (aSc/aSh, index = k) and on res (rSc/rSh,
// index = output column) -- implements fused BatchNorm apply.
// BM=BN=128, BK=16, 256 threads, 8x8/thread.
// bnstats!=0: per-column (sum,sumsq) partials -> g_part32[*][blockIdx.y][*]
// (requires gridDim.x==1, Nc==128).
// ---------------------------------------------------------------------------
__global__ __launch_bounds__(256, 2)
void gemm32_kernel(const float* __restrict__ A, const float* __restrict__ W,
                   const float* __restrict__ bias, const float* __restrict__ res,
                   float* __restrict__ C, int M, int K, int Nc, int lda,
                   int relu, int bnstats,
                   const float* __restrict__ aSc, const float* __restrict__ aSh,
                   const float* __restrict__ rSc, const float* __restrict__ rSh) {
    __shared__ float As[2][16][132];     // k-major, 16.9 KB
    __shared__ float Bs[2][16][132];     // k-major, 16.9 KB
    const int tid = threadIdx.x;
    const int tx = tid & 15, ty = tid >> 4;
    const int row0 = blockIdx.y * 128, col0 = blockIdx.x * 128;
    const int ar = tid >> 1, akc = (tid & 1) * 8;   // A: row ar, k cols akc..akc+7
    float acc[8][8];
#pragma unroll
    for (int i = 0; i < 8; i++)
#pragma unroll
        for (int j = 0; j < 8; j++) acc[i][j] = 0.f;

    float4 pa0, pa1;
    auto ldgA = [&](int kt) {
        const float* base = &A[(size_t)(row0 + ar) * lda + kt + akc];
        pa0 = *reinterpret_cast<const float4*>(base);
        pa1 = *reinterpret_cast<const float4*>(base + 4);
        if (aSc) {
            const float* sc = aSc + kt + akc;
            const float* sh = aSh + kt + akc;
            pa0.x = fmaf(pa0.x, sc[0], sh[0]); pa0.y = fmaf(pa0.y, sc[1], sh[1]);
            pa0.z = fmaf(pa0.z, sc[2], sh[2]); pa0.w = fmaf(pa0.w, sc[3], sh[3]);
            pa1.x = fmaf(pa1.x, sc[4], sh[4]); pa1.y = fmaf(pa1.y, sc[5], sh[5]);
            pa1.z = fmaf(pa1.z, sc[6], sh[6]); pa1.w = fmaf(pa1.w, sc[7], sh[7]);
        }
    };
    auto stsA = [&](int buf) {
        As[buf][akc+0][ar] = pa0.x; As[buf][akc+1][ar] = pa0.y;
        As[buf][akc+2][ar] = pa0.z; As[buf][akc+3][ar] = pa0.w;
        As[buf][akc+4][ar] = pa1.x; As[buf][akc+5][ar] = pa1.y;
        As[buf][akc+6][ar] = pa1.z; As[buf][akc+7][ar] = pa1.w;
    };
    auto loadB = [&](int kt, int buf) {
#pragma unroll
        for (int p = 0; p < 2; p++) {
            int c = tid + p*256;
            int br = c >> 5, bsub = (c & 31) * 4;
            unsigned db = (unsigned)__cvta_generic_to_shared(&Bs[buf][br][bsub]);
            const float* sb = &W[(size_t)(kt+br)*Nc + col0 + bsub];
            asm volatile("cp.async.cg.shared.global [%0], [%1], 16;" :: "r"(db), "l"(sb));
        }
        asm volatile("cp.async.commit_group;");
    };

    const int T = K >> 4;
    ldgA(0);
    loadB(0, 0);
    stsA(0);
    if (T > 1) { ldgA(16); loadB(16, 1); }
    if (T > 1) asm volatile("cp.async.wait_group 1;");
    else       asm volatile("cp.async.wait_group 0;");
    __syncthreads();

    for (int t = 0; t < T; t++) {
        const int buf = t & 1;
#pragma unroll
        for (int k = 0; k < 16; k++) {
            float a[8], bb[8];
            float4 a0 = *reinterpret_cast<const float4*>(&As[buf][k][ty*4]);
            float4 a1 = *reinterpret_cast<const float4*>(&As[buf][k][64 + ty*4]);
            float4 b0 = *reinterpret_cast<const float4*>(&Bs[buf][k][tx*4]);
            float4 b1 = *reinterpret_cast<const float4*>(&Bs[buf][k][64 + tx*4]);
            a[0]=a0.x;a[1]=a0.y;a[2]=a0.z;a[3]=a0.w;a[4]=a1.x;a[5]=a1.y;a[6]=a1.z;a[7]=a1.w;
            bb[0]=b0.x;bb[1]=b0.y;bb[2]=b0.z;bb[3]=b0.w;bb[4]=b1.x;bb[5]=b1.y;bb[6]=b1.z;bb[7]=b1.w;
#pragma unroll
            for (int i = 0; i < 8; i++)
#pragma unroll
                for (int j = 0; j < 8; j++) acc[i][j] = fmaf(a[i], bb[j], acc[i][j]);
        }
        __syncthreads();                 // all reads of buf done before reuse
        if (t + 1 < T) {
            stsA(1 - buf);
            if (t + 2 < T) { ldgA((t+2)*16); loadB((t+2)*16, buf); }
            if (t + 2 < T) asm volatile("cp.async.wait_group 1;");
            else           asm volatile("cp.async.wait_group 0;");
            __syncthreads();
        }
    }

    float cs[8], cq[8];
#pragma unroll
    for (int j = 0; j < 8; j++) { cs[j] = 0.f; cq[j] = 0.f; }
#pragma unroll
    for (int i = 0; i < 8; i++) {
        int r = row0 + ty*4 + (i < 4 ? i : 60 + i);
#pragma unroll
        for (int j = 0; j < 8; j++) {
            int c = col0 + tx*4 + (j < 4 ? j : 60 + j);
            float v = acc[i][j];
            if (bias) v += bias[c];
            if (res) {
                float rv = res[(size_t)r*Nc + c];
                if (rSc) v += fmaf(rv, rSc[c], rSh[c]);
                else     v += rv;
            }
            if (relu) v = fmaxf(v, 0.f);
            C[(size_t)r*Nc + c] = v;
            cs[j] += v;
            cq[j] = fmaf(v, v, cq[j]);
        }
    }
    if (bnstats) {
        float* red1 = &As[0][0][0];      // reuse smem: 16x128
        float* red2 = &Bs[0][0][0];
        __syncthreads();
#pragma unroll
        for (int j = 0; j < 8; j++) {
            int c = tx*4 + (j < 4 ? j : 60 + j);
            red1[ty*128 + c] = cs[j];
            red2[ty*128 + c] = cq[j];
        }
        __syncthreads();
        if (tid < 128) {
            float ssum = 0.f, ssq = 0.f;
#pragma unroll
            for (int t = 0; t < 16; t++) { ssum += red1[t*128 + tid]; ssq += red2[t*128 + tid]; }
            g_part32[0][blockIdx.y][tid] = ssum;
            g_part32[1][blockIdx.y][tid] = ssq;
        }
    }
}

// ---------------------------------------------------------------------------
// Fused MHA (proven version): one block per (b,h), 256 threads.
// ---------------------------------------------------------------------------
#define ATTN_SMEM_BYTES ((3*1700 + 10000) * 4)
__global__ __launch_bounds__(256)
void attn_kernel(const float* __restrict__ qkv, float* __restrict__ o) {
    extern __shared__ float asm_[];
    float* qsh = asm_;            // 100*17
    float* ksh = qsh + 1700;      // 100*17
    float* vsh = ksh + 1700;      // 100*17
    float* psh = vsh + 1700;      // 100*100
    int bh = blockIdx.x;
    int b = bh >> 3, hh = bh & 7;
    int tid = threadIdx.x;
    for (int i = tid; i < 1600; i += 256) {
        int m = i >> 4, d = i & 15;
        const float* base = qkv + (size_t)(b*N + m) * TD + hh*16 + d;
        qsh[m*17 + d] = base[0];
        ksh[m*17 + d] = base[D];
        vsh[m*17 + d] = base[2*D];
    }
    __syncthreads();
    int w = tid >> 5, lane = tid & 31;
    for (int n = w; n < 100; n += 8) {
        float qreg[16];
        const float* qp = qsh + n*17;
#pragma unroll
        for (int d = 0; d < 16; d++) qreg[d] = qp[d];
        float sc[4];
        float mx = -1e30f;
#pragma unroll
        for (int j = 0; j < 4; j++) {
            int m = lane + 32*j;
            if (m < 100) {
                const float* kp = ksh + m*17;
                float a0 = 0.f, a1 = 0.f;
#pragma unroll
                for (int d = 0; d < 16; d += 2) {
                    a0 = fmaf(qreg[d],   kp[d],   a0);
                    a1 = fmaf(qreg[d+1], kp[d+1], a1);
                }
                sc[j] = (a0 + a1) * 0.25f;
                mx = fmaxf(mx, sc[j]);
            } else sc[j] = -1e30f;
        }
#pragma unroll
        for (int off = 16; off; off >>= 1) mx = fmaxf(mx, __shfl_xor_sync(0xffffffffu, mx, off));
        double sum = 0.0, ev[4];
#pragma unroll
        for (int j = 0; j < 4; j++) {
            int m = lane + 32*j;
            if (m < 100) { ev[j] = exp((double)(sc[j] - mx)); sum += ev[j]; }
            else ev[j] = 0.0;
        }
#pragma unroll
        for (int off = 16; off; off >>= 1) sum += __shfl_xor_sync(0xffffffffu, sum, off);
        double inv = 1.0 / sum;
#pragma unroll
        for (int j = 0; j < 4; j++) {
            int m = lane + 32*j;
            if (m < 100) psh[n*100 + m] = (float)(ev[j] * inv);
        }
    }
    __syncthreads();
    for (int idx = tid; idx < 1600; idx += 256) {
        int n = idx >> 4, dk = idx & 15;
        const float* pp = psh + n*100;
        const float* vp = vsh + dk;
        float a0 = 0.f, a1 = 0.f;
#pragma unroll 4
        for (int m = 0; m < 100; m += 2) {
            a0 = fmaf(pp[m],   vp[(m)*17],   a0);
            a1 = fmaf(pp[m+1], vp[(m+1)*17], a1);
        }
        o[(size_t)(b*N + n) * D + hh*16 + dk] = a0 + a1;
    }
}

// ---------------------------------------------------------------------------
// BN finalize: reduce 400 partials (double), emit fp32 scale/shift.
// scale = gamma*rstd ; shift = beta - gamma*mean*rstd
// ---------------------------------------------------------------------------
__global__ void bn_stats2_kernel(const float* __restrict__ gb) {
    int c = threadIdx.x;
    double a = 0.0, q = 0.0;
    for (int p = 0; p < 400; p++) { a += (double)g_part32[0][p][c]; q += (double)g_part32[1][p][c]; }
    double mean = a * (1.0 / (double)M_ROWS);
    double var  = q * (1.0 / (double)M_ROWS) - mean*mean;
    double rstd = 1.0 / sqrt(var + 1e-5);
    double gamma = (double)gb[c], beta = (double)gb[D + c];
    g_bnsc[c] = (float)(gamma * rstd);
    g_bnsh[c] = (float)(beta - gamma * mean * rstd);
}

// ---------------------------------------------------------------------------
// wphw[d] = Wph @ Wstep (column d)
// ---------------------------------------------------------------------------
__global__ void wphw_kernel(const float* __restrict__ Wph, const float* __restrict__ Wstep) {
    int d = threadIdx.x;
    double a0 = 0.0, a1 = 0.0;
    for (int k = 0; k < 2*D; k += 2) {
        a0 = fma((double)Wph[k],   (double)Wstep[(k)*D + d],   a0);
        a1 = fma((double)Wph[k+1], (double)Wstep[(k+1)*D + d], a1);
    }
    g_wphw[d] = a0 + a1;
}

// ---------------------------------------------------------------------------
// Per-batch: hm = affine(mean_n(s_b)); fc = hm @ Wf; q0 = fc + wphw
// (g_h holds pre-BN2 values; affine = g_bnsc/g_bnsh)
// ---------------------------------------------------------------------------
__global__ void meanfix_kernel(const float* __restrict__ Wf) {
    __shared__ float sh[D];
    int b = blockIdx.x, d = threadIdx.x;
    double a = 0.0;
    for (int n = 0; n < N; n++) a += (double)g_h[(size_t)(b*N + n) * D + d];
    a *= (1.0 / (double)N);
    sh[d] = (float)((double)g_bnsc[d] * a + (double)g_bnsh[d]);
    __syncthreads();
    double fc = 0.0;
    for (int k = 0; k < D; k++) fc = fma((double)sh[k], (double)Wf[k*D + d], fc);
    g_fc[b*D + d] = (float)fc;
    g_q0[b*D + d] = (float)(fc + g_wphw[d]);
}

// ---------------------------------------------------------------------------
// Persistent greedy decode v4 (unchanged). 512 threads, 2 blocks/SM.
// ---------------------------------------------------------------------------
#define HPS2 257
#define DEC_SMEM_BYTES (16 + (N*HPS2 + 128 + 128 + 800 + 128 + 512 + 100)*4 + 202*4)

__global__ __launch_bounds__(512, 2)
void decode_kernel(const float* __restrict__ x,
                   float* __restrict__ out) {
    extern __shared__ double dsm[];
    double* sh_ll  = dsm;
    float* sh_hp   = (float*)(dsm + 2);     // 100*257 (gK | gV)
    float* sh_q    = sh_hp + N*HPS2;        // 128
    float* sh_qb   = sh_q + D;              // 128
    float* sh_c    = sh_qb + D;             // 800
    float* sh_g    = sh_c + 800;            // 128
    float* sh_part = sh_g + D;              // 512
    float* sh_lg   = sh_part + 512;         // 100
    int*   sh_mask = (int*)(sh_lg + 100);
    int*   sh_pi   = sh_mask + 100;
    int*   sh_ctrl = sh_pi + 100;

    const float NF = 0.08838834764831843f;
    int b = blockIdx.x, tid = threadIdx.x;
    int w = tid >> 5, lane = tid & 31;
    int dd = tid & 127, part = tid >> 7;
    const float* lkwB = g_lkw + (size_t)b * N * D;

    for (int i = tid; i < N*256; i += 512) {
        int n = i >> 8, j = i & 255;
        sh_hp[n*HPS2 + j] = g_3d[(size_t)b * (N*TD) + n*TD + j];
    }
    if (tid < N) sh_mask[tid] = 0;
    if (tid == 0) { sh_ll[0] = 0.0; sh_ctrl[0] = 0; sh_ctrl[1] = 0; }
    __syncthreads();

    for (int s = 0; s < N; s++) {
        // 1. q from precomputed tables
        if (tid < 128) {
            if (s == 0) {
                sh_q[tid] = g_q0[b*D + tid];
            } else {
                float qb;
                if (s == 1) {
                    qb = g_fc[b*D + tid] + g_efed[(size_t)(b*N + sh_ctrl[0]) * 256 + tid];
                    sh_qb[tid] = qb;
                } else qb = sh_qb[tid];
                sh_q[tid] = qb + g_efed[(size_t)(b*N + sh_ctrl[1]) * 256 + 128 + tid];
            }
        }
        __syncthreads();
        // 2. compat [H,N]
        for (int idx = tid; idx < 800; idx += 512) {
            int hh = idx / 100, n = idx - hh*100;
            const float* kp = sh_hp + n*HPS2 + hh*16;
            const float* qp = sh_q + hh*16;
            float a0 = 0.f, a1 = 0.f;
#pragma unroll
            for (int d2 = 0; d2 < 16; d2 += 2) {
                a0 = fmaf(qp[d2],   kp[d2],   a0);
                a1 = fmaf(qp[d2+1], kp[d2+1], a1);
            }
            sh_c[idx] = sh_mask[n] ? NEGV : (a0 + a1) * NF;
        }
        __syncthreads();
        // 3. softmax, warps 0-7 (double exp)
        if (w < 8) {
            int head = w;
            float mx = -1e30f;
            for (int n = lane; n < 100; n += 32) mx = fmaxf(mx, sh_c[head*100 + n]);
#pragma unroll
            for (int off = 16; off; off >>= 1) mx = fmaxf(mx, __shfl_xor_sync(0xffffffffu, mx, off));
            double sum = 0.0, ev[4];
#pragma unroll
            for (int j = 0; j < 4; j++) {
                int n = lane + 32*j;
                if (n < 100) { ev[j] = exp((double)(sh_c[head*100 + n] - mx)); sum += ev[j]; }
                else ev[j] = 0.0;
            }
#pragma unroll
            for (int off = 16; off; off >>= 1) sum += __shfl_xor_sync(0xffffffffu, sum, off);
            double inv = 1.0 / sum;
#pragma unroll
            for (int j = 0; j < 4; j++) {
                int n = lane + 32*j;
                if (n < 100) sh_c[head*100 + n] = (float)(ev[j] * inv);
            }
        }
        __syncthreads();
        // 4. glimpse partials
        {
            int hh = dd >> 4;
            const float* pp = sh_c + hh*100 + part*25;
            const float* vp = sh_hp + (size_t)(part*25) * HPS2 + D + dd;
            float a0 = 0.f, a1 = 0.f;
#pragma unroll 4
            for (int n = 0; n < 24; n += 2) {
                a0 = fmaf(pp[n],   vp[(n)*HPS2],   a0);
                a1 = fmaf(pp[n+1], vp[(n+1)*HPS2], a1);
            }
            a0 = fmaf(pp[24], vp[24*HPS2], a0);
            sh_part[tid] = a0 + a1;
        }
        __syncthreads();
        if (tid < 128) sh_g[tid] = sh_part[tid] + sh_part[tid+128] + sh_part[tid+256] + sh_part[tid+384];
        __syncthreads();
        // 5. logits partials: lKW from L2
        if (dd < 100) {
            int k0 = part * 32;
            const float* lp = lkwB + (size_t)dd * D + k0;
            float a0 = 0.f, a1 = 0.f;
#pragma unroll
            for (int q4 = 0; q4 < 8; q4++) {
                float4 v = __ldg(reinterpret_cast<const float4*>(lp + q4*4));
                float4 g = *reinterpret_cast<const float4*>(&sh_g[k0 + q4*4]);
                a0 = fmaf(g.x, v.x, a0); a1 = fmaf(g.y, v.y, a1);
                a0 = fmaf(g.z, v.z, a0); a1 = fmaf(g.w, v.w, a1);
            }
            sh_part[tid] = a0 + a1;
        }
        __syncthreads();
        if (tid < 100) {
            double a = (double)(sh_part[tid] + sh_part[tid+128] + sh_part[tid+256] + sh_part[tid+384]);
            sh_lg[tid] = sh_mask[tid] ? NEGV : (float)(tanh(a * (double)NF) * CLIPV);
        }
        __syncthreads();
        // 6. argmax + logsumexp, warp 0
        if (w == 0) {
            float mx = -1e30f; int mi = N + 1;
            for (int n = lane; n < N; n += 32) {
                float v = sh_lg[n];
                if (v > mx) { mx = v; mi = n; }
            }
#pragma unroll
            for (int off = 16; off; off >>= 1) {
                float om = __shfl_xor_sync(0xffffffffu, mx, off);
                int   oi = __shfl_xor_sync(0xffffffffu, mi, off);
                if (om > mx || (om == mx && oi < mi)) { mx = om; mi = oi; }
            }
            double sum = 0.0;
            for (int n = lane; n < N; n += 32) sum += exp((double)sh_lg[n] - (double)mx);
#pragma unroll
            for (int off = 16; off; off >>= 1) sum += __shfl_xor_sync(0xffffffffu, sum, off);
            if (lane == 0) {
                double lse = (double)mx + log(sum);
                sh_ll[0] += (double)sh_lg[mi] - lse;
                sh_mask[mi] = 1;
                sh_ctrl[1] = mi;
                if (s == 0) sh_ctrl[0] = mi;
                sh_pi[s] = mi;
                out[2*B + b*N + s] = (float)mi;
            }
        }
        __syncthreads();
    }
    // tour cost (closed cycle)
    if (tid < N) {
        int a = sh_pi[tid], c = sh_pi[(tid + 1) % N];
        double dx = (double)x[(b*N + a)*2]     - (double)x[(b*N + c)*2];
        double dy = (double)x[(b*N + a)*2 + 1] - (double)x[(b*N + c)*2 + 1];
        sh_lg[tid] = (float)sqrt(dx*dx + dy*dy);
    }
    __syncthreads();
    if (tid == 0) {
        double cst = 0.0;
        for (int t = 0; t < N; t++) cst += (double)sh_lg[t];
        out[b] = (float)cst;
        out[B + b] = (float)sh_ll[0];
    }
}

// ---------------------------------------------------------------------------
extern "C" void kernel_launch(void* const* d_in, const int* in_sizes, int n_in,
                              void* d_out, int out_size) {
    const float* x        = (const float*)d_in[0];
    const float* init_W   = (const float*)d_in[1];
    const float* init_b   = (const float*)d_in[2];
    const float* qkv_W    = (const float*)d_in[3];
    const float* out_W    = (const float*)d_in[4];
    const float* bn1      = (const float*)d_in[5];
    const float* bn2      = (const float*)d_in[6];
    const float* ff1_W    = (const float*)d_in[7];
    const float* ff1_b    = (const float*)d_in[8];
    const float* ff2_W    = (const float*)d_in[9];
    const float* ff2_b    = (const float*)d_in[10];
    const float* Wph      = (const float*)d_in[11];
    const float* nodes_W  = (const float*)d_in[12];
    const float* fixed_W  = (const float*)d_in[13];
    const float* step_W   = (const float*)d_in[14];
    const float* pout_W   = (const float*)d_in[15];
    float* out = (float*)d_out;

    cudaFuncSetAttribute(decode_kernel, cudaFuncAttributeMaxDynamicSharedMemorySize,
                         DEC_SMEM_BYTES + 128);
    cudaFuncSetAttribute(attn_kernel, cudaFuncAttributeMaxDynamicSharedMemorySize,
                         ATTN_SMEM_BYTES + 128);

    float *p_h, *p_3d, *p_ff, *p_o, *p_s, *p_efed, *p_lkw, *p_wt, *p_w2p, *p_sc, *p_sh;
    cudaGetSymbolAddress((void**)&p_h,    g_h);
    cudaGetSymbolAddress((void**)&p_3d,   g_3d);
    cudaGetSymbolAddress((void**)&p_ff,   g_ff);
    cudaGetSymbolAddress((void**)&p_o,    g_o);
    cudaGetSymbolAddress((void**)&p_s,    g_s);
    cudaGetSymbolAddress((void**)&p_efed, g_efed);
    cudaGetSymbolAddress((void**)&p_lkw,  g_lkw);
    cudaGetSymbolAddress((void**)&p_wt,   g_wt);
    cudaGetSymbolAddress((void**)&p_w2p,  g_w2p);
    cudaGetSymbolAddress((void**)&p_sc,   g_bnsc);
    cudaGetSymbolAddress((void**)&p_sh,   g_bnsh);

    int vgrid = (M_ROWS * 32 + 255) / 256;

    init_embed_kernel<<<vgrid, 256>>>(x, init_W, init_b);
    wphw_kernel<<<1, 128>>>(Wph, step_W);
    transpose_kernel<<<64, 256>>>(pout_W);
    pack_w2_kernel<<<128, 256>>>(step_W);

    for (int l = 0; l < 2; l++) {
        // qkv: A = (l==0 ? plain h : affine(pre-bn2)), both stored in g_h
        gemm32_kernel<<<dim3(TD/128, M_ROWS/128), 256>>>(
            p_h, qkv_W + (size_t)l*D*TD, nullptr, nullptr, p_3d, M_ROWS, D, TD, D, 0, 0,
            l == 0 ? nullptr : p_sc, l == 0 ? nullptr : p_sh, nullptr, nullptr);
        attn_kernel<<<B*H, 256, ATTN_SMEM_BYTES + 128>>>(p_3d, p_o);
        // s_a = o @ Wout + affine?(h), fused BN1 stats
        gemm32_kernel<<<dim3(D/128, M_ROWS/128), 256>>>(
            p_o, out_W + (size_t)l*D*D, nullptr, p_h, p_s, M_ROWS, D, D, D, 0, 1,
            nullptr, nullptr, l == 0 ? nullptr : p_sc, l == 0 ? nullptr : p_sh);
        bn_stats2_kernel<<<1, 128>>>(bn1 + (size_t)l*2*D);
        // ff1 = relu(affine1(s_a) @ W1 + b1)
        gemm32_kernel<<<dim3(FF/128, M_ROWS/128), 256>>>(
            p_s, ff1_W + (size_t)l*D*FF, ff1_b + (size_t)l*FF, nullptr, p_ff, M_ROWS, D, FF, D, 1, 0,
            p_sc, p_sh, nullptr, nullptr);
        // s_b = ff1 @ W2 + b2 + affine1(s_a), fused BN2 stats -> g_h
        gemm32_kernel<<<dim3(D/128, M_ROWS/128), 256>>>(
            p_ff, ff2_W + (size_t)l*FF*D, ff2_b + (size_t)l*D, p_s, p_h, M_ROWS, FF, D, FF, 0, 1,
            nullptr, nullptr, p_sc, p_sh);
        bn_stats2_kernel<<<1, 128>>>(bn2 + (size_t)l*2*D);
    }

    // decoder precompute (A = affine2(pre-bn2) everywhere h is consumed)
    gemm32_kernel<<<dim3(TD/128, M_ROWS/128), 256>>>(
        p_h, nodes_W, nullptr, nullptr, p_3d, M_ROWS, D, TD, D, 0, 0,
        p_sc, p_sh, nullptr, nullptr);
    gemm32_kernel<<<dim3(2, M_ROWS/128), 256>>>(
        p_h, p_w2p, nullptr, nullptr, p_efed, M_ROWS, D, 256, D, 0, 0,
        p_sc, p_sh, nullptr, nullptr);
    gemm32_kernel<<<dim3(D/128, M_ROWS/128), 256>>>(
        p_3d + 2*D, p_wt, nullptr, nullptr, p_lkw, M_ROWS, D, D, TD, 0, 0,
        nullptr, nullptr, nullptr, nullptr);
    meanfix_kernel<<<B, D>>>(fixed_W);

    decode_kernel<<<B, 512, DEC_SMEM_BYTES + 128>>>(x, out);
}

// round 16
// speedup vs baseline: 1.3157x; 1.0760x over previous
#include <cuda_runtime.h>
#include <math.h>
#include <stdint.h>

// Problem constants
#define B 512
#define N 100
#define D 128
#define H 8
#define DK 16
#define FF 512
#define TD 384          // 3*D
#define M_ROWS (B*N)    // 51200
#define NEGV -1e9f
#define CLIPV 10.0

static __device__ float g_h [ (size_t)M_ROWS * D ];     // pre-BN2 / embed buffer
static __device__ float g_3d[ (size_t)M_ROWS * TD ];    // qkv / hp scratch
static __device__ float g_ff[ (size_t)M_ROWS * FF ];    // ff1 output
static __device__ float g_o [ (size_t)M_ROWS * D ];     // attention output
static __device__ float g_s [ (size_t)M_ROWS * D ];     // pre-BN1 buffer
static __device__ float g_efed[ (size_t)M_ROWS * 256 ]; // h @ [Wstep1|Wstep2]
static __device__ float g_lkw[ (size_t)M_ROWS * D ];    // lK @ Wout^T
static __device__ float g_wt[D*D];                      // Wout^T
static __device__ float g_w2p[D*256];                   // packed [Wstep1|Wstep2]
static __device__ float g_part32[2][400][128];          // per-block BN partials
static __device__ float g_bnsc[D], g_bnsh[D];           // current BN scale/shift
static __device__ double g_wphw[D];                     // Wph @ Wstep
static __device__ float g_fc[B*D], g_q0[B*D];           // fixed_ctx, step-0 query

// ---------------------------------------------------------------------------
// h = x @ init_W + init_b  (float4 over D)
// ---------------------------------------------------------------------------
__global__ void init_embed_kernel(const float* __restrict__ x,
                                  const float* __restrict__ W,
                                  const float* __restrict__ bias) {
    int idx = blockIdx.x * blockDim.x + threadIdx.x;   // over M_ROWS*32
    if (idx >= M_ROWS * 32) return;
    int i = idx >> 5, d0 = (idx & 31) * 4;
    double x0 = (double)x[i*2], x1 = (double)x[i*2+1];
    float4 o;
    o.x = (float)(x0 * (double)W[d0+0] + x1 * (double)W[D+d0+0] + (double)bias[d0+0]);
    o.y = (float)(x0 * (double)W[d0+1] + x1 * (double)W[D+d0+1] + (double)bias[d0+1]);
    o.z = (float)(x0 * (double)W[d0+2] + x1 * (double)W[D+d0+2] + (double)bias[d0+2]);
    o.w = (float)(x0 * (double)W[d0+3] + x1 * (double)W[D+d0+3] + (double)bias[d0+3]);
    *reinterpret_cast<float4*>(&g_h[(size_t)idx*4]) = o;
}

// ---------------------------------------------------------------------------
// Wout^T and packed step weights
// ---------------------------------------------------------------------------
__global__ void transpose_kernel(const float* __restrict__ Wout) {
    int idx = blockIdx.x * blockDim.x + threadIdx.x;   // over D*D
    int d = idx >> 7, k = idx & 127;
    g_wt[d*D + k] = Wout[k*D + d];
}
__global__ void pack_w2_kernel(const float* __restrict__ Wstep) {
    int idx = blockIdx.x * blockDim.x + threadIdx.x;   // over D*256
    int k = idx >> 8, j = idx & 255;
    g_w2p[k*256 + j] = (j < 128) ? Wstep[k*D + j] : Wstep[(128 + k)*D + (j - 128)];
}

// ---------------------------------------------------------------------------
// fp32 tiled GEMM v4: k-major A smem, cp.async B, double-buffered, race-free.
// Optional per-column affine on A (aSc/aSh, index = k) and on res (rSc/rSh,
// index = output column) -- implements fused BatchNorm apply.
// BM=BN=128, BK=16, 256 threads, 8x8/thread.
// bnstats!=0: per-column (sum,sumsq) partials -> g_part32[*][blockIdx.y][*]
// (requires gridDim.x==1, Nc==128).
// ---------------------------------------------------------------------------
__global__ __launch_bounds__(256, 2)
void gemm32_kernel(const float* __restrict__ A, const float* __restrict__ W,
                   const float* __restrict__ bias, const float* __restrict__ res,
                   float* __restrict__ C, int M, int K, int Nc, int lda,
                   int relu, int bnstats,
                   const float* __restrict__ aSc, const float* __restrict__ aSh,
                   const float* __restrict__ rSc, const float* __restrict__ rSh) {
    __shared__ float As[2][16][132];     // k-major, 16.9 KB
    __shared__ float Bs[2][16][132];     // k-major, 16.9 KB
    const int tid = threadIdx.x;
    const int tx = tid & 15, ty = tid >> 4;
    const int row0 = blockIdx.y * 128, col0 = blockIdx.x * 128;
    const int ar = tid >> 1, akc = (tid & 1) * 8;   // A: row ar, k cols akc..akc+7
    float acc[8][8];
#pragma unroll
    for (int i = 0; i < 8; i++)
#pragma unroll
        for (int j = 0; j < 8; j++) acc[i][j] = 0.f;

    float4 pa0, pa1;
    auto ldgA = [&](int kt) {
        const float* base = &A[(size_t)(row0 + ar) * lda + kt + akc];
        pa0 = *reinterpret_cast<const float4*>(base);
        pa1 = *reinterpret_cast<const float4*>(base + 4);
        if (aSc) {
            const float* sc = aSc + kt + akc;
            const float* sh = aSh + kt + akc;
            pa0.x = fmaf(pa0.x, sc[0], sh[0]); pa0.y = fmaf(pa0.y, sc[1], sh[1]);
            pa0.z = fmaf(pa0.z, sc[2], sh[2]); pa0.w = fmaf(pa0.w, sc[3], sh[3]);
            pa1.x = fmaf(pa1.x, sc[4], sh[4]); pa1.y = fmaf(pa1.y, sc[5], sh[5]);
            pa1.z = fmaf(pa1.z, sc[6], sh[6]); pa1.w = fmaf(pa1.w, sc[7], sh[7]);
        }
    };
    auto stsA = [&](int buf) {
        As[buf][akc+0][ar] = pa0.x; As[buf][akc+1][ar] = pa0.y;
        As[buf][akc+2][ar] = pa0.z; As[buf][akc+3][ar] = pa0.w;
        As[buf][akc+4][ar] = pa1.x; As[buf][akc+5][ar] = pa1.y;
        As[buf][akc+6][ar] = pa1.z; As[buf][akc+7][ar] = pa1.w;
    };
    auto loadB = [&](int kt, int buf) {
#pragma unroll
        for (int p = 0; p < 2; p++) {
            int c = tid + p*256;
            int br = c >> 5, bsub = (c & 31) * 4;
            unsigned db = (unsigned)__cvta_generic_to_shared(&Bs[buf][br][bsub]);
            const float* sb = &W[(size_t)(kt+br)*Nc + col0 + bsub];
            asm volatile("cp.async.cg.shared.global [%0], [%1], 16;" :: "r"(db), "l"(sb));
        }
        asm volatile("cp.async.commit_group;");
    };

    const int T = K >> 4;
    ldgA(0);
    loadB(0, 0);
    stsA(0);
    if (T > 1) { ldgA(16); loadB(16, 1); }
    if (T > 1) asm volatile("cp.async.wait_group 1;");
    else       asm volatile("cp.async.wait_group 0;");
    __syncthreads();

    for (int t = 0; t < T; t++) {
        const int buf = t & 1;
#pragma unroll
        for (int k = 0; k < 16; k++) {
            float a[8], bb[8];
            float4 a0 = *reinterpret_cast<const float4*>(&As[buf][k][ty*4]);
            float4 a1 = *reinterpret_cast<const float4*>(&As[buf][k][64 + ty*4]);
            float4 b0 = *reinterpret_cast<const float4*>(&Bs[buf][k][tx*4]);
            float4 b1 = *reinterpret_cast<const float4*>(&Bs[buf][k][64 + tx*4]);
            a[0]=a0.x;a[1]=a0.y;a[2]=a0.z;a[3]=a0.w;a[4]=a1.x;a[5]=a1.y;a[6]=a1.z;a[7]=a1.w;
            bb[0]=b0.x;bb[1]=b0.y;bb[2]=b0.z;bb[3]=b0.w;bb[4]=b1.x;bb[5]=b1.y;bb[6]=b1.z;bb[7]=b1.w;
#pragma unroll
            for (int i = 0; i < 8; i++)
#pragma unroll
                for (int j = 0; j < 8; j++) acc[i][j] = fmaf(a[i], bb[j], acc[i][j]);
        }
        __syncthreads();                 // all reads of buf done before reuse
        if (t + 1 < T) {
            stsA(1 - buf);
            if (t + 2 < T) { ldgA((t+2)*16); loadB((t+2)*16, buf); }
            if (t + 2 < T) asm volatile("cp.async.wait_group 1;");
            else           asm volatile("cp.async.wait_group 0;");
            __syncthreads();
        }
    }

    float cs[8], cq[8];
#pragma unroll
    for (int j = 0; j < 8; j++) { cs[j] = 0.f; cq[j] = 0.f; }
#pragma unroll
    for (int i = 0; i < 8; i++) {
        int r = row0 + ty*4 + (i < 4 ? i : 60 + i);
#pragma unroll
        for (int j = 0; j < 8; j++) {
            int c = col0 + tx*4 + (j < 4 ? j : 60 + j);
            float v = acc[i][j];
            if (bias) v += bias[c];
            if (res) {
                float rv = res[(size_t)r*Nc + c];
                if (rSc) v += fmaf(rv, rSc[c], rSh[c]);
                else     v += rv;
            }
            if (relu) v = fmaxf(v, 0.f);
            C[(size_t)r*Nc + c] = v;
            cs[j] += v;
            cq[j] = fmaf(v, v, cq[j]);
        }
    }
    if (bnstats) {
        float* red1 = &As[0][0][0];      // reuse smem: 16x128
        float* red2 = &Bs[0][0][0];
        __syncthreads();
#pragma unroll
        for (int j = 0; j < 8; j++) {
            int c = tx*4 + (j < 4 ? j : 60 + j);
            red1[ty*128 + c] = cs[j];
            red2[ty*128 + c] = cq[j];
        }
        __syncthreads();
        if (tid < 128) {
            float ssum = 0.f, ssq = 0.f;
#pragma unroll
            for (int t = 0; t < 16; t++) { ssum += red1[t*128 + tid]; ssq += red2[t*128 + tid]; }
            g_part32[0][blockIdx.y][tid] = ssum;
            g_part32[1][blockIdx.y][tid] = ssq;
        }
    }
}

// ---------------------------------------------------------------------------
// Fused MHA (proven version): one block per (b,h), 256 threads.
// ---------------------------------------------------------------------------
#define ATTN_SMEM_BYTES ((3*1700 + 10000) * 4)
__global__ __launch_bounds__(256)
void attn_kernel(const float* __restrict__ qkv, float* __restrict__ o) {
    extern __shared__ float asm_[];
    float* qsh = asm_;            // 100*17
    float* ksh = qsh + 1700;      // 100*17
    float* vsh = ksh + 1700;      // 100*17
    float* psh = vsh + 1700;      // 100*100
    int bh = blockIdx.x;
    int b = bh >> 3, hh = bh & 7;
    int tid = threadIdx.x;
    for (int i = tid; i < 1600; i += 256) {
        int m = i >> 4, d = i & 15;
        const float* base = qkv + (size_t)(b*N + m) * TD + hh*16 + d;
        qsh[m*17 + d] = base[0];
        ksh[m*17 + d] = base[D];
        vsh[m*17 + d] = base[2*D];
    }
    __syncthreads();
    int w = tid >> 5, lane = tid & 31;
    for (int n = w; n < 100; n += 8) {
        float qreg[16];
        const float* qp = qsh + n*17;
#pragma unroll
        for (int d = 0; d < 16; d++) qreg[d] = qp[d];
        float sc[4];
        float mx = -1e30f;
#pragma unroll
        for (int j = 0; j < 4; j++) {
            int m = lane + 32*j;
            if (m < 100) {
                const float* kp = ksh + m*17;
                float a0 = 0.f, a1 = 0.f;
#pragma unroll
                for (int d = 0; d < 16; d += 2) {
                    a0 = fmaf(qreg[d],   kp[d],   a0);
                    a1 = fmaf(qreg[d+1], kp[d+1], a1);
                }
                sc[j] = (a0 + a1) * 0.25f;
                mx = fmaxf(mx, sc[j]);
            } else sc[j] = -1e30f;
        }
#pragma unroll
        for (int off = 16; off; off >>= 1) mx = fmaxf(mx, __shfl_xor_sync(0xffffffffu, mx, off));
        double sum = 0.0, ev[4];
#pragma unroll
        for (int j = 0; j < 4; j++) {
            int m = lane + 32*j;
            if (m < 100) { ev[j] = exp((double)(sc[j] - mx)); sum += ev[j]; }
            else ev[j] = 0.0;
        }
#pragma unroll
        for (int off = 16; off; off >>= 1) sum += __shfl_xor_sync(0xffffffffu, sum, off);
        double inv = 1.0 / sum;
#pragma unroll
        for (int j = 0; j < 4; j++) {
            int m = lane + 32*j;
            if (m < 100) psh[n*100 + m] = (float)(ev[j] * inv);
        }
    }
    __syncthreads();
    for (int idx = tid; idx < 1600; idx += 256) {
        int n = idx >> 4, dk = idx & 15;
        const float* pp = psh + n*100;
        const float* vp = vsh + dk;
        float a0 = 0.f, a1 = 0.f;
#pragma unroll 4
        for (int m = 0; m < 100; m += 2) {
            a0 = fmaf(pp[m],   vp[(m)*17],   a0);
            a1 = fmaf(pp[m+1], vp[(m+1)*17], a1);
        }
        o[(size_t)(b*N + n) * D + hh*16 + dk] = a0 + a1;
    }
}

// ---------------------------------------------------------------------------
// BN finalize: reduce 400 partials (double), emit fp32 scale/shift.
// ---------------------------------------------------------------------------
__global__ void bn_stats2_kernel(const float* __restrict__ gb) {
    int c = threadIdx.x;
    double a = 0.0, q = 0.0;
    for (int p = 0; p < 400; p++) { a += (double)g_part32[0][p][c]; q += (double)g_part32[1][p][c]; }
    double mean = a * (1.0 / (double)M_ROWS);
    double var  = q * (1.0 / (double)M_ROWS) - mean*mean;
    double rstd = 1.0 / sqrt(var + 1e-5);
    double gamma = (double)gb[c], beta = (double)gb[D + c];
    g_bnsc[c] = (float)(gamma * rstd);
    g_bnsh[c] = (float)(beta - gamma * mean * rstd);
}

// ---------------------------------------------------------------------------
// wphw[d] = Wph @ Wstep (column d)
// ---------------------------------------------------------------------------
__global__ void wphw_kernel(const float* __restrict__ Wph, const float* __restrict__ Wstep) {
    int d = threadIdx.x;
    double a0 = 0.0, a1 = 0.0;
    for (int k = 0; k < 2*D; k += 2) {
        a0 = fma((double)Wph[k],   (double)Wstep[(k)*D + d],   a0);
        a1 = fma((double)Wph[k+1], (double)Wstep[(k+1)*D + d], a1);
    }
    g_wphw[d] = a0 + a1;
}

// ---------------------------------------------------------------------------
// Per-batch: hm = affine(mean_n(pre-bn2)); fc = hm @ Wf; q0 = fc + wphw
// ---------------------------------------------------------------------------
__global__ void meanfix_kernel(const float* __restrict__ Wf) {
    __shared__ float sh[D];
    int b = blockIdx.x, d = threadIdx.x;
    double a = 0.0;
    for (int n = 0; n < N; n++) a += (double)g_h[(size_t)(b*N + n) * D + d];
    a *= (1.0 / (double)N);
    sh[d] = (float)((double)g_bnsc[d] * a + (double)g_bnsh[d]);
    __syncthreads();
    double fc = 0.0;
    for (int k = 0; k < D; k++) fc = fma((double)sh[k], (double)Wf[k*D + d], fc);
    g_fc[b*D + d] = (float)fc;
    g_q0[b*D + d] = (float)(fc + g_wphw[d]);
}

// ---------------------------------------------------------------------------
// Persistent greedy decode v5. 512 threads, 3 blocks/SM (gV read from L2).
// smem: gK only (stride 129) + step scratch ~= 60 KB.
// ---------------------------------------------------------------------------
#define GKS 129
#define DEC_SMEM_BYTES (16 + (N*GKS + 128 + 128 + 800 + 128 + 512 + 100)*4 + 202*4)

__global__ __launch_bounds__(512, 3)
void decode_kernel(const float* __restrict__ x,
                   float* __restrict__ out) {
    extern __shared__ double dsm[];
    double* sh_ll  = dsm;
    float* sh_gk   = (float*)(dsm + 2);     // 100*129
    float* sh_q    = sh_gk + N*GKS;         // 128
    float* sh_qb   = sh_q + D;              // 128
    float* sh_c    = sh_qb + D;             // 800
    float* sh_g    = sh_c + 800;            // 128
    float* sh_part = sh_g + D;              // 512
    float* sh_lg   = sh_part + 512;         // 100
    int*   sh_mask = (int*)(sh_lg + 100);
    int*   sh_pi   = sh_mask + 100;
    int*   sh_ctrl = sh_pi + 100;

    const float NF = 0.08838834764831843f;
    int b = blockIdx.x, tid = threadIdx.x;
    int w = tid >> 5, lane = tid & 31;
    int dd = tid & 127, part = tid >> 7;
    const float* lkwB = g_lkw + (size_t)b * N * D;
    const float* gvB  = g_3d + (size_t)b * (N*TD) + D;   // gV rows, stride TD

    for (int i = tid; i < N*D; i += 512) {
        int n = i >> 7, j = i & 127;
        sh_gk[n*GKS + j] = g_3d[(size_t)b * (N*TD) + n*TD + j];
    }
    if (tid < N) sh_mask[tid] = 0;
    if (tid == 0) { sh_ll[0] = 0.0; sh_ctrl[0] = 0; sh_ctrl[1] = 0; }
    __syncthreads();

    for (int s = 0; s < N; s++) {
        // 1. q from precomputed tables
        if (tid < 128) {
            if (s == 0) {
                sh_q[tid] = g_q0[b*D + tid];
            } else {
                float qb;
                if (s == 1) {
                    qb = g_fc[b*D + tid] + g_efed[(size_t)(b*N + sh_ctrl[0]) * 256 + tid];
                    sh_qb[tid] = qb;
                } else qb = sh_qb[tid];
                sh_q[tid] = qb + g_efed[(size_t)(b*N + sh_ctrl[1]) * 256 + 128 + tid];
            }
        }
        __syncthreads();
        // 2. compat [H,N]
        for (int idx = tid; idx < 800; idx += 512) {
            int hh = idx / 100, n = idx - hh*100;
            const float* kp = sh_gk + n*GKS + hh*16;
            const float* qp = sh_q + hh*16;
            float a0 = 0.f, a1 = 0.f;
#pragma unroll
            for (int d2 = 0; d2 < 16; d2 += 2) {
                a0 = fmaf(qp[d2],   kp[d2],   a0);
                a1 = fmaf(qp[d2+1], kp[d2+1], a1);
            }
            sh_c[idx] = sh_mask[n] ? NEGV : (a0 + a1) * NF;
        }
        __syncthreads();
        // 3. softmax, warps 0-7 (double exp)
        if (w < 8) {
            int head = w;
            float mx = -1e30f;
            for (int n = lane; n < 100; n += 32) mx = fmaxf(mx, sh_c[head*100 + n]);
#pragma unroll
            for (int off = 16; off; off >>= 1) mx = fmaxf(mx, __shfl_xor_sync(0xffffffffu, mx, off));
            double sum = 0.0, ev[4];
#pragma unroll
            for (int j = 0; j < 4; j++) {
                int n = lane + 32*j;
                if (n < 100) { ev[j] = exp((double)(sh_c[head*100 + n] - mx)); sum += ev[j]; }
                else ev[j] = 0.0;
            }
#pragma unroll
            for (int off = 16; off; off >>= 1) sum += __shfl_xor_sync(0xffffffffu, sum, off);
            double inv = 1.0 / sum;
#pragma unroll
            for (int j = 0; j < 4; j++) {
                int n = lane + 32*j;
                if (n < 100) sh_c[head*100 + n] = (float)(ev[j] * inv);
            }
        }
        __syncthreads();
        // 4. glimpse partials: gV from L2 (coalesced across dd)
        {
            int hh = dd >> 4;
            const float* pp = sh_c + hh*100 + part*25;
            const float* vp = gvB + (size_t)(part*25) * TD + dd;
            float a0 = 0.f, a1 = 0.f;
#pragma unroll 4
            for (int n = 0; n < 24; n += 2) {
                a0 = fmaf(pp[n],   __ldg(&vp[(n)*TD]),   a0);
                a1 = fmaf(pp[n+1], __ldg(&vp[(n+1)*TD]), a1);
            }
            a0 = fmaf(pp[24], __ldg(&vp[24*TD]), a0);
            sh_part[tid] = a0 + a1;
        }
        __syncthreads();
        if (tid < 128) sh_g[tid] = sh_part[tid] + sh_part[tid+128] + sh_part[tid+256] + sh_part[tid+384];
        __syncthreads();
        // 5. logits partials: lKW from L2
        if (dd < 100) {
            int k0 = part * 32;
            const float* lp = lkwB + (size_t)dd * D + k0;
            float a0 = 0.f, a1 = 0.f;
#pragma unroll
            for (int q4 = 0; q4 < 8; q4++) {
                float4 v = __ldg(reinterpret_cast<const float4*>(lp + q4*4));
                float4 g = *reinterpret_cast<const float4*>(&sh_g[k0 + q4*4]);
                a0 = fmaf(g.x, v.x, a0); a1 = fmaf(g.y, v.y, a1);
                a0 = fmaf(g.z, v.z, a0); a1 = fmaf(g.w, v.w, a1);
            }
            sh_part[tid] = a0 + a1;
        }
        __syncthreads();
        if (tid < 100) {
            double a = (double)(sh_part[tid] + sh_part[tid+128] + sh_part[tid+256] + sh_part[tid+384]);
            sh_lg[tid] = sh_mask[tid] ? NEGV : (float)(tanh(a * (double)NF) * CLIPV);
        }
        __syncthreads();
        // 6. argmax + logsumexp, warp 0
        if (w == 0) {
            float mx = -1e30f; int mi = N + 1;
            for (int n = lane; n < N; n += 32) {
                float v = sh_lg[n];
                if (v > mx) { mx = v; mi = n; }
            }
#pragma unroll
            for (int off = 16; off; off >>= 1) {
                float om = __shfl_xor_sync(0xffffffffu, mx, off);
                int   oi = __shfl_xor_sync(0xffffffffu, mi, off);
                if (om > mx || (om == mx && oi < mi)) { mx = om; mi = oi; }
            }
            double sum = 0.0;
            for (int n = lane; n < N; n += 32) sum += exp((double)sh_lg[n] - (double)mx);
#pragma unroll
            for (int off = 16; off; off >>= 1) sum += __shfl_xor_sync(0xffffffffu, sum, off);
            if (lane == 0) {
                double lse = (double)mx + log(sum);
                sh_ll[0] += (double)sh_lg[mi] - lse;
                sh_mask[mi] = 1;
                sh_ctrl[1] = mi;
                if (s == 0) sh_ctrl[0] = mi;
                sh_pi[s] = mi;
                out[2*B + b*N + s] = (float)mi;
            }
        }
        __syncthreads();
    }
    // tour cost (closed cycle)
    if (tid < N) {
        int a = sh_pi[tid], c = sh_pi[(tid + 1) % N];
        double dx = (double)x[(b*N + a)*2]     - (double)x[(b*N + c)*2];
        double dy = (double)x[(b*N + a)*2 + 1] - (double)x[(b*N + c)*2 + 1];
        sh_lg[tid] = (float)sqrt(dx*dx + dy*dy);
    }
    __syncthreads();
    if (tid == 0) {
        double cst = 0.0;
        for (int t = 0; t < N; t++) cst += (double)sh_lg[t];
        out[b] = (float)cst;
        out[B + b] = (float)sh_ll[0];
    }
}

// ---------------------------------------------------------------------------
extern "C" void kernel_launch(void* const* d_in, const int* in_sizes, int n_in,
                              void* d_out, int out_size) {
    const float* x        = (const float*)d_in[0];
    const float* init_W   = (const float*)d_in[1];
    const float* init_b   = (const float*)d_in[2];
    const float* qkv_W    = (const float*)d_in[3];
    const float* out_W    = (const float*)d_in[4];
    const float* bn1      = (const float*)d_in[5];
    const float* bn2      = (const float*)d_in[6];
    const float* ff1_W    = (const float*)d_in[7];
    const float* ff1_b    = (const float*)d_in[8];
    const float* ff2_W    = (const float*)d_in[9];
    const float* ff2_b    = (const float*)d_in[10];
    const float* Wph      = (const float*)d_in[11];
    const float* nodes_W  = (const float*)d_in[12];
    const float* fixed_W  = (const float*)d_in[13];
    const float* step_W   = (const float*)d_in[14];
    const float* pout_W   = (const float*)d_in[15];
    float* out = (float*)d_out;

    cudaFuncSetAttribute(decode_kernel, cudaFuncAttributeMaxDynamicSharedMemorySize,
                         DEC_SMEM_BYTES + 128);
    cudaFuncSetAttribute(attn_kernel, cudaFuncAttributeMaxDynamicSharedMemorySize,
                         ATTN_SMEM_BYTES + 128);

    float *p_h, *p_3d, *p_ff, *p_o, *p_s, *p_efed, *p_lkw, *p_wt, *p_w2p, *p_sc, *p_sh;
    cudaGetSymbolAddress((void**)&p_h,    g_h);
    cudaGetSymbolAddress((void**)&p_3d,   g_3d);
    cudaGetSymbolAddress((void**)&p_ff,   g_ff);
    cudaGetSymbolAddress((void**)&p_o,    g_o);
    cudaGetSymbolAddress((void**)&p_s,    g_s);
    cudaGetSymbolAddress((void**)&p_efed, g_efed);
    cudaGetSymbolAddress((void**)&p_lkw,  g_lkw);
    cudaGetSymbolAddress((void**)&p_wt,   g_wt);
    cudaGetSymbolAddress((void**)&p_w2p,  g_w2p);
    cudaGetSymbolAddress((void**)&p_sc,   g_bnsc);
    cudaGetSymbolAddress((void**)&p_sh,   g_bnsh);

    int vgrid = (M_ROWS * 32 + 255) / 256;

    init_embed_kernel<<<vgrid, 256>>>(x, init_W, init_b);
    wphw_kernel<<<1, 128>>>(Wph, step_W);
    transpose_kernel<<<64, 256>>>(pout_W);
    pack_w2_kernel<<<128, 256>>>(step_W);

    for (int l = 0; l < 2; l++) {
        gemm32_kernel<<<dim3(TD/128, M_ROWS/128), 256>>>(
            p_h, qkv_W + (size_t)l*D*TD, nullptr, nullptr, p_3d, M_ROWS, D, TD, D, 0, 0,
            l == 0 ? nullptr : p_sc, l == 0 ? nullptr : p_sh, nullptr, nullptr);
        attn_kernel<<<B*H, 256, ATTN_SMEM_BYTES + 128>>>(p_3d, p_o);
        gemm32_kernel<<<dim3(D/128, M_ROWS/128), 256>>>(
            p_o, out_W + (size_t)l*D*D, nullptr, p_h, p_s, M_ROWS, D, D, D, 0, 1,
            nullptr, nullptr, l == 0 ? nullptr : p_sc, l == 0 ? nullptr : p_sh);
        bn_stats2_kernel<<<1, 128>>>(bn1 + (size_t)l*2*D);
        gemm32_kernel<<<dim3(FF/128, M_ROWS/128), 256>>>(
            p_s, ff1_W + (size_t)l*D*FF, ff1_b + (size_t)l*FF, nullptr, p_ff, M_ROWS, D, FF, D, 1, 0,
            p_sc, p_sh, nullptr, nullptr);
        gemm32_kernel<<<dim3(D/128, M_ROWS/128), 256>>>(
            p_ff, ff2_W + (size_t)l*FF*D, ff2_b + (size_t)l*D, p_s, p_h, M_ROWS, FF, D, FF, 0, 1,
            nullptr, nullptr, p_sc, p_sh);
        bn_stats2_kernel<<<1, 128>>>(bn2 + (size_t)l*2*D);
    }

    // decoder precompute
    gemm32_kernel<<<dim3(TD/128, M_ROWS/128), 256>>>(
        p_h, nodes_W, nullptr, nullptr, p_3d, M_ROWS, D, TD, D, 0, 0,
        p_sc, p_sh, nullptr, nullptr);
    gemm32_kernel<<<dim3(2, M_ROWS/128), 256>>>(
        p_h, p_w2p, nullptr, nullptr, p_efed, M_ROWS, D, 256, D, 0, 0,
        p_sc, p_sh, nullptr, nullptr);
    gemm32_kernel<<<dim3(D/128, M_ROWS/128), 256>>>(
        p_3d + 2*D, p_wt, nullptr, nullptr, p_lkw, M_ROWS, D, D, TD, 0, 0,
        nullptr, nullptr, nullptr, nullptr);
    meanfix_kernel<<<B, D>>>(fixed_W);

    decode_kernel<<<B, 512, DEC_SMEM_BYTES + 128>>>(x, out);
}

// round 17
// speedup vs baseline: 1.3161x; 1.0003x over previous
#include <cuda_runtime.h>
#include <math.h>
#include <stdint.h>

// Problem constants
#define B 512
#define N 100
#define D 128
#define H 8
#define DK 16
#define FF 512
#define TD 384          // 3*D
#define M_ROWS (B*N)    // 51200
#define NEGV -1e9f
#define CLIPV 10.0

static __device__ float g_h [ (size_t)M_ROWS * D ];     // pre-BN2 / embed buffer
static __device__ float g_3d[ (size_t)M_ROWS * TD ];    // qkv / hp scratch
static __device__ float g_ff[ (size_t)M_ROWS * FF ];    // ff1 output
static __device__ float g_o [ (size_t)M_ROWS * D ];     // attention output
static __device__ float g_s [ (size_t)M_ROWS * D ];     // pre-BN1 buffer
static __device__ float g_efed[ (size_t)M_ROWS * 256 ]; // h @ [Wstep1|Wstep2]
static __device__ float g_lkw[ (size_t)M_ROWS * D ];    // lK @ Wout^T
static __device__ float g_wt[D*D];                      // Wout^T
static __device__ float g_w2p[D*256];                   // packed [Wstep1|Wstep2]
static __device__ float g_part32[2][400][128];          // per-block BN partials
static __device__ float g_bnsc[D], g_bnsh[D];           // current BN scale/shift
static __device__ double g_wphw[D];                     // Wph @ Wstep
static __device__ float g_fc[B*D], g_q0[B*D];           // fixed_ctx, step-0 query

// ---------------------------------------------------------------------------
// h = x @ init_W + init_b  (float4 over D)
// ---------------------------------------------------------------------------
__global__ void init_embed_kernel(const float* __restrict__ x,
                                  const float* __restrict__ W,
                                  const float* __restrict__ bias) {
    int idx = blockIdx.x * blockDim.x + threadIdx.x;   // over M_ROWS*32
    if (idx >= M_ROWS * 32) return;
    int i = idx >> 5, d0 = (idx & 31) * 4;
    double x0 = (double)x[i*2], x1 = (double)x[i*2+1];
    float4 o;
    o.x = (float)(x0 * (double)W[d0+0] + x1 * (double)W[D+d0+0] + (double)bias[d0+0]);
    o.y = (float)(x0 * (double)W[d0+1] + x1 * (double)W[D+d0+1] + (double)bias[d0+1]);
    o.z = (float)(x0 * (double)W[d0+2] + x1 * (double)W[D+d0+2] + (double)bias[d0+2]);
    o.w = (float)(x0 * (double)W[d0+3] + x1 * (double)W[D+d0+3] + (double)bias[d0+3]);
    *reinterpret_cast<float4*>(&g_h[(size_t)idx*4]) = o;
}

// ---------------------------------------------------------------------------
// Wout^T and packed step weights
// ---------------------------------------------------------------------------
__global__ void transpose_kernel(const float* __restrict__ Wout) {
    int idx = blockIdx.x * blockDim.x + threadIdx.x;   // over D*D
    int d = idx >> 7, k = idx & 127;
    g_wt[d*D + k] = Wout[k*D + d];
}
__global__ void pack_w2_kernel(const float* __restrict__ Wstep) {
    int idx = blockIdx.x * blockDim.x + threadIdx.x;   // over D*256
    int k = idx >> 8, j = idx & 255;
    g_w2p[k*256 + j] = (j < 128) ? Wstep[k*D + j] : Wstep[(128 + k)*D + (j - 128)];
}

// ---------------------------------------------------------------------------
// fp32 tiled GEMM v4: k-major A smem, cp.async B, double-buffered, race-free.
// Optional per-column affine on A (aSc/aSh, index = k) and on res (rSc/rSh,
// index = output column) -- fused BatchNorm apply.
// BM=BN=128, BK=16, 256 threads, 8x8/thread.
// bnstats!=0: per-column (sum,sumsq) partials -> g_part32[*][blockIdx.y][*]
// (requires gridDim.x==1, Nc==128).
// ---------------------------------------------------------------------------
__global__ __launch_bounds__(256, 2)
void gemm32_kernel(const float* __restrict__ A, const float* __restrict__ W,
                   const float* __restrict__ bias, const float* __restrict__ res,
                   float* __restrict__ C, int M, int K, int Nc, int lda,
                   int relu, int bnstats,
                   const float* __restrict__ aSc, const float* __restrict__ aSh,
                   const float* __restrict__ rSc, const float* __restrict__ rSh) {
    __shared__ float As[2][16][132];     // k-major, 16.9 KB
    __shared__ float Bs[2][16][132];     // k-major, 16.9 KB
    const int tid = threadIdx.x;
    const int tx = tid & 15, ty = tid >> 4;
    const int row0 = blockIdx.y * 128, col0 = blockIdx.x * 128;
    const int ar = tid >> 1, akc = (tid & 1) * 8;   // A: row ar, k cols akc..akc+7
    float acc[8][8];
#pragma unroll
    for (int i = 0; i < 8; i++)
#pragma unroll
        for (int j = 0; j < 8; j++) acc[i][j] = 0.f;

    float4 pa0, pa1;
    auto ldgA = [&](int kt) {
        const float* base = &A[(size_t)(row0 + ar) * lda + kt + akc];
        pa0 = *reinterpret_cast<const float4*>(base);
        pa1 = *reinterpret_cast<const float4*>(base + 4);
        if (aSc) {
            const float* sc = aSc + kt + akc;
            const float* sh = aSh + kt + akc;
            pa0.x = fmaf(pa0.x, sc[0], sh[0]); pa0.y = fmaf(pa0.y, sc[1], sh[1]);
            pa0.z = fmaf(pa0.z, sc[2], sh[2]); pa0.w = fmaf(pa0.w, sc[3], sh[3]);
            pa1.x = fmaf(pa1.x, sc[4], sh[4]); pa1.y = fmaf(pa1.y, sc[5], sh[5]);
            pa1.z = fmaf(pa1.z, sc[6], sh[6]); pa1.w = fmaf(pa1.w, sc[7], sh[7]);
        }
    };
    auto stsA = [&](int buf) {
        As[buf][akc+0][ar] = pa0.x; As[buf][akc+1][ar] = pa0.y;
        As[buf][akc+2][ar] = pa0.z; As[buf][akc+3][ar] = pa0.w;
        As[buf][akc+4][ar] = pa1.x; As[buf][akc+5][ar] = pa1.y;
        As[buf][akc+6][ar] = pa1.z; As[buf][akc+7][ar] = pa1.w;
    };
    auto loadB = [&](int kt, int buf) {
#pragma unroll
        for (int p = 0; p < 2; p++) {
            int c = tid + p*256;
            int br = c >> 5, bsub = (c & 31) * 4;
            unsigned db = (unsigned)__cvta_generic_to_shared(&Bs[buf][br][bsub]);
            const float* sb = &W[(size_t)(kt+br)*Nc + col0 + bsub];
            asm volatile("cp.async.cg.shared.global [%0], [%1], 16;" :: "r"(db), "l"(sb));
        }
        asm volatile("cp.async.commit_group;");
    };

    const int T = K >> 4;
    ldgA(0);
    loadB(0, 0);
    stsA(0);
    if (T > 1) { ldgA(16); loadB(16, 1); }
    if (T > 1) asm volatile("cp.async.wait_group 1;");
    else       asm volatile("cp.async.wait_group 0;");
    __syncthreads();

    for (int t = 0; t < T; t++) {
        const int buf = t & 1;
#pragma unroll
        for (int k = 0; k < 16; k++) {
            float a[8], bb[8];
            float4 a0 = *reinterpret_cast<const float4*>(&As[buf][k][ty*4]);
            float4 a1 = *reinterpret_cast<const float4*>(&As[buf][k][64 + ty*4]);
            float4 b0 = *reinterpret_cast<const float4*>(&Bs[buf][k][tx*4]);
            float4 b1 = *reinterpret_cast<const float4*>(&Bs[buf][k][64 + tx*4]);
            a[0]=a0.x;a[1]=a0.y;a[2]=a0.z;a[3]=a0.w;a[4]=a1.x;a[5]=a1.y;a[6]=a1.z;a[7]=a1.w;
            bb[0]=b0.x;bb[1]=b0.y;bb[2]=b0.z;bb[3]=b0.w;bb[4]=b1.x;bb[5]=b1.y;bb[6]=b1.z;bb[7]=b1.w;
#pragma unroll
            for (int i = 0; i < 8; i++)
#pragma unroll
                for (int j = 0; j < 8; j++) acc[i][j] = fmaf(a[i], bb[j], acc[i][j]);
        }
        __syncthreads();
        if (t + 1 < T) {
            stsA(1 - buf);
            if (t + 2 < T) { ldgA((t+2)*16); loadB((t+2)*16, buf); }
            if (t + 2 < T) asm volatile("cp.async.wait_group 1;");
            else           asm volatile("cp.async.wait_group 0;");
            __syncthreads();
        }
    }

    float cs[8], cq[8];
#pragma unroll
    for (int j = 0; j < 8; j++) { cs[j] = 0.f; cq[j] = 0.f; }
#pragma unroll
    for (int i = 0; i < 8; i++) {
        int r = row0 + ty*4 + (i < 4 ? i : 60 + i);
#pragma unroll
        for (int j = 0; j < 8; j++) {
            int c = col0 + tx*4 + (j < 4 ? j : 60 + j);
            float v = acc[i][j];
            if (bias) v += bias[c];
            if (res) {
                float rv = res[(size_t)r*Nc + c];
                if (rSc) v += fmaf(rv, rSc[c], rSh[c]);
                else     v += rv;
            }
            if (relu) v = fmaxf(v, 0.f);
            C[(size_t)r*Nc + c] = v;
            cs[j] += v;
            cq[j] = fmaf(v, v, cq[j]);
        }
    }
    if (bnstats) {
        float* red1 = &As[0][0][0];      // reuse smem: 16x128
        float* red2 = &Bs[0][0][0];
        __syncthreads();
#pragma unroll
        for (int j = 0; j < 8; j++) {
            int c = tx*4 + (j < 4 ? j : 60 + j);
            red1[ty*128 + c] = cs[j];
            red2[ty*128 + c] = cq[j];
        }
        __syncthreads();
        if (tid < 128) {
            float ssum = 0.f, ssq = 0.f;
#pragma unroll
            for (int t = 0; t < 16; t++) { ssum += red1[t*128 + tid]; ssq += red2[t*128 + tid]; }
            g_part32[0][blockIdx.y][tid] = ssum;
            g_part32[1][blockIdx.y][tid] = ssq;
        }
    }
}

// ---------------------------------------------------------------------------
// Fused MHA v6: stride-20 rows (16B-aligned) -> LDS.128 K/Q loads in phase 1.
// One block per (b,h), 256 threads. Same arithmetic order as v5.
// ---------------------------------------------------------------------------
#define AQS 20
#define ATTN_SMEM_BYTES ((3*100*AQS + 10000) * 4)
__global__ __launch_bounds__(256)
void attn_kernel(const float* __restrict__ qkv, float* __restrict__ o) {
    extern __shared__ float asm_[];
    float* qsh = asm_;                 // 100*20
    float* ksh = qsh + 100*AQS;        // 100*20
    float* vsh = ksh + 100*AQS;        // 100*20
    float* psh = vsh + 100*AQS;        // 100*100
    int bh = blockIdx.x;
    int b = bh >> 3, hh = bh & 7;
    int tid = threadIdx.x;
    for (int i = tid; i < 1600; i += 256) {
        int m = i >> 4, d = i & 15;
        const float* base = qkv + (size_t)(b*N + m) * TD + hh*16 + d;
        qsh[m*AQS + d] = base[0];
        ksh[m*AQS + d] = base[D];
        vsh[m*AQS + d] = base[2*D];
    }
    __syncthreads();
    int w = tid >> 5, lane = tid & 31;
    for (int n = w; n < 100; n += 8) {
        // q row as 4 x float4
        const float4* qv = reinterpret_cast<const float4*>(qsh + n*AQS);
        float4 q0 = qv[0], q1 = qv[1], q2 = qv[2], q3 = qv[3];
        float sc[4];
        float mx = -1e30f;
#pragma unroll
        for (int j = 0; j < 4; j++) {
            int m = lane + 32*j;
            if (m < 100) {
                const float4* kv = reinterpret_cast<const float4*>(ksh + m*AQS);
                float4 k0 = kv[0], k1 = kv[1], k2 = kv[2], k3 = kv[3];
                float a0 = 0.f, a1 = 0.f;
                a0 = fmaf(q0.x, k0.x, a0); a1 = fmaf(q0.y, k0.y, a1);
                a0 = fmaf(q0.z, k0.z, a0); a1 = fmaf(q0.w, k0.w, a1);
                a0 = fmaf(q1.x, k1.x, a0); a1 = fmaf(q1.y, k1.y, a1);
                a0 = fmaf(q1.z, k1.z, a0); a1 = fmaf(q1.w, k1.w, a1);
                a0 = fmaf(q2.x, k2.x, a0); a1 = fmaf(q2.y, k2.y, a1);
                a0 = fmaf(q2.z, k2.z, a0); a1 = fmaf(q2.w, k2.w, a1);
                a0 = fmaf(q3.x, k3.x, a0); a1 = fmaf(q3.y, k3.y, a1);
                a0 = fmaf(q3.z, k3.z, a0); a1 = fmaf(q3.w, k3.w, a1);
                sc[j] = (a0 + a1) * 0.25f;
                mx = fmaxf(mx, sc[j]);
            } else sc[j] = -1e30f;
        }
#pragma unroll
        for (int off = 16; off; off >>= 1) mx = fmaxf(mx, __shfl_xor_sync(0xffffffffu, mx, off));
        double sum = 0.0, ev[4];
#pragma unroll
        for (int j = 0; j < 4; j++) {
            int m = lane + 32*j;
            if (m < 100) { ev[j] = exp((double)(sc[j] - mx)); sum += ev[j]; }
            else ev[j] = 0.0;
        }
#pragma unroll
        for (int off = 16; off; off >>= 1) sum += __shfl_xor_sync(0xffffffffu, sum, off);
        double inv = 1.0 / sum;
#pragma unroll
        for (int j = 0; j < 4; j++) {
            int m = lane + 32*j;
            if (m < 100) psh[n*100 + m] = (float)(ev[j] * inv);
        }
    }
    __syncthreads();
    for (int idx = tid; idx < 1600; idx += 256) {
        int n = idx >> 4, dk = idx & 15;
        const float* pp = psh + n*100;
        const float* vp = vsh + dk;
        float a0 = 0.f, a1 = 0.f;
#pragma unroll 4
        for (int m = 0; m < 100; m += 2) {
            a0 = fmaf(pp[m],   vp[(m)*AQS],   a0);
            a1 = fmaf(pp[m+1], vp[(m+1)*AQS], a1);
        }
        o[(size_t)(b*N + n) * D + hh*16 + dk] = a0 + a1;
    }
}

// ---------------------------------------------------------------------------
// BN finalize: reduce 400 partials (double), emit fp32 scale/shift.
// ---------------------------------------------------------------------------
__global__ void bn_stats2_kernel(const float* __restrict__ gb) {
    int c = threadIdx.x;
    double a = 0.0, q = 0.0;
    for (int p = 0; p < 400; p++) { a += (double)g_part32[0][p][c]; q += (double)g_part32[1][p][c]; }
    double mean = a * (1.0 / (double)M_ROWS);
    double var  = q * (1.0 / (double)M_ROWS) - mean*mean;
    double rstd = 1.0 / sqrt(var + 1e-5);
    double gamma = (double)gb[c], beta = (double)gb[D + c];
    g_bnsc[c] = (float)(gamma * rstd);
    g_bnsh[c] = (float)(beta - gamma * mean * rstd);
}

// ---------------------------------------------------------------------------
// wphw[d] = Wph @ Wstep (column d)
// ---------------------------------------------------------------------------
__global__ void wphw_kernel(const float* __restrict__ Wph, const float* __restrict__ Wstep) {
    int d = threadIdx.x;
    double a0 = 0.0, a1 = 0.0;
    for (int k = 0; k < 2*D; k += 2) {
        a0 = fma((double)Wph[k],   (double)Wstep[(k)*D + d],   a0);
        a1 = fma((double)Wph[k+1], (double)Wstep[(k+1)*D + d], a1);
    }
    g_wphw[d] = a0 + a1;
}

// ---------------------------------------------------------------------------
// Per-batch: hm = affine(mean_n(pre-bn2)); fc = hm @ Wf; q0 = fc + wphw
// ---------------------------------------------------------------------------
__global__ void meanfix_kernel(const float* __restrict__ Wf) {
    __shared__ float sh[D];
    int b = blockIdx.x, d = threadIdx.x;
    double a = 0.0;
    for (int n = 0; n < N; n++) a += (double)g_h[(size_t)(b*N + n) * D + d];
    a *= (1.0 / (double)N);
    sh[d] = (float)((double)g_bnsc[d] * a + (double)g_bnsh[d]);
    __syncthreads();
    double fc = 0.0;
    for (int k = 0; k < D; k++) fc = fma((double)sh[k], (double)Wf[k*D + d], fc);
    g_fc[b*D + d] = (float)fc;
    g_q0[b*D + d] = (float)(fc + g_wphw[d]);
}

// ---------------------------------------------------------------------------
// Persistent greedy decode v5 (proven). 512 threads, 3 blocks/SM.
// ---------------------------------------------------------------------------
#define GKS 129
#define DEC_SMEM_BYTES (16 + (N*GKS + 128 + 128 + 800 + 128 + 512 + 100)*4 + 202*4)

__global__ __launch_bounds__(512, 3)
void decode_kernel(const float* __restrict__ x,
                   float* __restrict__ out) {
    extern __shared__ double dsm[];
    double* sh_ll  = dsm;
    float* sh_gk   = (float*)(dsm + 2);     // 100*129
    float* sh_q    = sh_gk + N*GKS;         // 128
    float* sh_qb   = sh_q + D;              // 128
    float* sh_c    = sh_qb + D;             // 800
    float* sh_g    = sh_c + 800;            // 128
    float* sh_part = sh_g + D;              // 512
    float* sh_lg   = sh_part + 512;         // 100
    int*   sh_mask = (int*)(sh_lg + 100);
    int*   sh_pi   = sh_mask + 100;
    int*   sh_ctrl = sh_pi + 100;

    const float NF = 0.08838834764831843f;
    int b = blockIdx.x, tid = threadIdx.x;
    int w = tid >> 5, lane = tid & 31;
    int dd = tid & 127, part = tid >> 7;
    const float* lkwB = g_lkw + (size_t)b * N * D;
    const float* gvB  = g_3d + (size_t)b * (N*TD) + D;   // gV rows, stride TD

    for (int i = tid; i < N*D; i += 512) {
        int n = i >> 7, j = i & 127;
        sh_gk[n*GKS + j] = g_3d[(size_t)b * (N*TD) + n*TD + j];
    }
    if (tid < N) sh_mask[tid] = 0;
    if (tid == 0) { sh_ll[0] = 0.0; sh_ctrl[0] = 0; sh_ctrl[1] = 0; }
    __syncthreads();

    for (int s = 0; s < N; s++) {
        if (tid < 128) {
            if (s == 0) {
                sh_q[tid] = g_q0[b*D + tid];
            } else {
                float qb;
                if (s == 1) {
                    qb = g_fc[b*D + tid] + g_efed[(size_t)(b*N + sh_ctrl[0]) * 256 + tid];
                    sh_qb[tid] = qb;
                } else qb = sh_qb[tid];
                sh_q[tid] = qb + g_efed[(size_t)(b*N + sh_ctrl[1]) * 256 + 128 + tid];
            }
        }
        __syncthreads();
        for (int idx = tid; idx < 800; idx += 512) {
            int hh = idx / 100, n = idx - hh*100;
            const float* kp = sh_gk + n*GKS + hh*16;
            const float* qp = sh_q + hh*16;
            float a0 = 0.f, a1 = 0.f;
#pragma unroll
            for (int d2 = 0; d2 < 16; d2 += 2) {
                a0 = fmaf(qp[d2],   kp[d2],   a0);
                a1 = fmaf(qp[d2+1], kp[d2+1], a1);
            }
            sh_c[idx] = sh_mask[n] ? NEGV : (a0 + a1) * NF;
        }
        __syncthreads();
        if (w < 8) {
            int head = w;
            float mx = -1e30f;
            for (int n = lane; n < 100; n += 32) mx = fmaxf(mx, sh_c[head*100 + n]);
#pragma unroll
            for (int off = 16; off; off >>= 1) mx = fmaxf(mx, __shfl_xor_sync(0xffffffffu, mx, off));
            double sum = 0.0, ev[4];
#pragma unroll
            for (int j = 0; j < 4; j++) {
                int n = lane + 32*j;
                if (n < 100) { ev[j] = exp((double)(sh_c[head*100 + n] - mx)); sum += ev[j]; }
                else ev[j] = 0.0;
            }
#pragma unroll
            for (int off = 16; off; off >>= 1) sum += __shfl_xor_sync(0xffffffffu, sum, off);
            double inv = 1.0 / sum;
#pragma unroll
            for (int j = 0; j < 4; j++) {
                int n = lane + 32*j;
                if (n < 100) sh_c[head*100 + n] = (float)(ev[j] * inv);
            }
        }
        __syncthreads();
        {
            int hh = dd >> 4;
            const float* pp = sh_c + hh*100 + part*25;
            const float* vp = gvB + (size_t)(part*25) * TD + dd;
            float a0 = 0.f, a1 = 0.f;
#pragma unroll 4
            for (int n = 0; n < 24; n += 2) {
                a0 = fmaf(pp[n],   __ldg(&vp[(n)*TD]),   a0);
                a1 = fmaf(pp[n+1], __ldg(&vp[(n+1)*TD]), a1);
            }
            a0 = fmaf(pp[24], __ldg(&vp[24*TD]), a0);
            sh_part[tid] = a0 + a1;
        }
        __syncthreads();
        if (tid < 128) sh_g[tid] = sh_part[tid] + sh_part[tid+128] + sh_part[tid+256] + sh_part[tid+384];
        __syncthreads();
        if (dd < 100) {
            int k0 = part * 32;
            const float* lp = lkwB + (size_t)dd * D + k0;
            float a0 = 0.f, a1 = 0.f;
#pragma unroll
            for (int q4 = 0; q4 < 8; q4++) {
                float4 v = __ldg(reinterpret_cast<const float4*>(lp + q4*4));
                float4 g = *reinterpret_cast<const float4*>(&sh_g[k0 + q4*4]);
                a0 = fmaf(g.x, v.x, a0); a1 = fmaf(g.y, v.y, a1);
                a0 = fmaf(g.z, v.z, a0); a1 = fmaf(g.w, v.w, a1);
            }
            sh_part[tid] = a0 + a1;
        }
        __syncthreads();
        if (tid < 100) {
            double a = (double)(sh_part[tid] + sh_part[tid+128] + sh_part[tid+256] + sh_part[tid+384]);
            sh_lg[tid] = sh_mask[tid] ? NEGV : (float)(tanh(a * (double)NF) * CLIPV);
        }
        __syncthreads();
        if (w == 0) {
            float mx = -1e30f; int mi = N + 1;
            for (int n = lane; n < N; n += 32) {
                float v = sh_lg[n];
                if (v > mx) { mx = v; mi = n; }
            }
#pragma unroll
            for (int off = 16; off; off >>= 1) {
                float om = __shfl_xor_sync(0xffffffffu, mx, off);
                int   oi = __shfl_xor_sync(0xffffffffu, mi, off);
                if (om > mx || (om == mx && oi < mi)) { mx = om; mi = oi; }
            }
            double sum = 0.0;
            for (int n = lane; n < N; n += 32) sum += exp((double)sh_lg[n] - (double)mx);
#pragma unroll
            for (int off = 16; off; off >>= 1) sum += __shfl_xor_sync(0xffffffffu, sum, off);
            if (lane == 0) {
                double lse = (double)mx + log(sum);
                sh_ll[0] += (double)sh_lg[mi] - lse;
                sh_mask[mi] = 1;
                sh_ctrl[1] = mi;
                if (s == 0) sh_ctrl[0] = mi;
                sh_pi[s] = mi;
                out[2*B + b*N + s] = (float)mi;
            }
        }
        __syncthreads();
    }
    if (tid < N) {
        int a = sh_pi[tid], c = sh_pi[(tid + 1) % N];
        double dx = (double)x[(b*N + a)*2]     - (double)x[(b*N + c)*2];
        double dy = (double)x[(b*N + a)*2 + 1] - (double)x[(b*N + c)*2 + 1];
        sh_lg[tid] = (float)sqrt(dx*dx + dy*dy);
    }
    __syncthreads();
    if (tid == 0) {
        double cst = 0.0;
        for (int t = 0; t < N; t++) cst += (double)sh_lg[t];
        out[b] = (float)cst;
        out[B + b] = (float)sh_ll[0];
    }
}

// ---------------------------------------------------------------------------
extern "C" void kernel_launch(void* const* d_in, const int* in_sizes, int n_in,
                              void* d_out, int out_size) {
    const float* x        = (const float*)d_in[0];
    const float* init_W   = (const float*)d_in[1];
    const float* init_b   = (const float*)d_in[2];
    const float* qkv_W    = (const float*)d_in[3];
    const float* out_W    = (const float*)d_in[4];
    const float* bn1      = (const float*)d_in[5];
    const float* bn2      = (const float*)d_in[6];
    const float* ff1_W    = (const float*)d_in[7];
    const float* ff1_b    = (const float*)d_in[8];
    const float* ff2_W    = (const float*)d_in[9];
    const float* ff2_b    = (const float*)d_in[10];
    const float* Wph      = (const float*)d_in[11];
    const float* nodes_W  = (const float*)d_in[12];
    const float* fixed_W  = (const float*)d_in[13];
    const float* step_W   = (const float*)d_in[14];
    const float* pout_W   = (const float*)d_in[15];
    float* out = (float*)d_out;

    cudaFuncSetAttribute(decode_kernel, cudaFuncAttributeMaxDynamicSharedMemorySize,
                         DEC_SMEM_BYTES + 128);
    cudaFuncSetAttribute(attn_kernel, cudaFuncAttributeMaxDynamicSharedMemorySize,
                         ATTN_SMEM_BYTES + 128);

    float *p_h, *p_3d, *p_ff, *p_o, *p_s, *p_efed, *p_lkw, *p_wt, *p_w2p, *p_sc, *p_sh;
    cudaGetSymbolAddress((void**)&p_h,    g_h);
    cudaGetSymbolAddress((void**)&p_3d,   g_3d);
    cudaGetSymbolAddress((void**)&p_ff,   g_ff);
    cudaGetSymbolAddress((void**)&p_o,    g_o);
    cudaGetSymbolAddress((void**)&p_s,    g_s);
    cudaGetSymbolAddress((void**)&p_efed, g_efed);
    cudaGetSymbolAddress((void**)&p_lkw,  g_lkw);
    cudaGetSymbolAddress((void**)&p_wt,   g_wt);
    cudaGetSymbolAddress((void**)&p_w2p,  g_w2p);
    cudaGetSymbolAddress((void**)&p_sc,   g_bnsc);
    cudaGetSymbolAddress((void**)&p_sh,   g_bnsh);

    int vgrid = (M_ROWS * 32 + 255) / 256;

    init_embed_kernel<<<vgrid, 256>>>(x, init_W, init_b);
    wphw_kernel<<<1, 128>>>(Wph, step_W);
    transpose_kernel<<<64, 256>>>(pout_W);
    pack_w2_kernel<<<128, 256>>>(step_W);

    for (int l = 0; l < 2; l++) {
        gemm32_kernel<<<dim3(TD/128, M_ROWS/128), 256>>>(
            p_h, qkv_W + (size_t)l*D*TD, nullptr, nullptr, p_3d, M_ROWS, D, TD, D, 0, 0,
            l == 0 ? nullptr : p_sc, l == 0 ? nullptr : p_sh, nullptr, nullptr);
        attn_kernel<<<B*H, 256, ATTN_SMEM_BYTES + 128>>>(p_3d, p_o);
        gemm32_kernel<<<dim3(D/128, M_ROWS/128), 256>>>(
            p_o, out_W + (size_t)l*D*D, nullptr, p_h, p_s, M_ROWS, D, D, D, 0, 1,
            nullptr, nullptr, l == 0 ? nullptr : p_sc, l == 0 ? nullptr : p_sh);
        bn_stats2_kernel<<<1, 128>>>(bn1 + (size_t)l*2*D);
        gemm32_kernel<<<dim3(FF/128, M_ROWS/128), 256>>>(
            p_s, ff1_W + (size_t)l*D*FF, ff1_b + (size_t)l*FF, nullptr, p_ff, M_ROWS, D, FF, D, 1, 0,
            p_sc, p_sh, nullptr, nullptr);
        gemm32_kernel<<<dim3(D/128, M_ROWS/128), 256>>>(
            p_ff, ff2_W + (size_t)l*FF*D, ff2_b + (size_t)l*D, p_s, p_h, M_ROWS, FF, D, FF, 0, 1,
            nullptr, nullptr, p_sc, p_sh);
        bn_stats2_kernel<<<1, 128>>>(bn2 + (size_t)l*2*D);
    }

    // decoder precompute
    gemm32_kernel<<<dim3(TD/128, M_ROWS/128), 256>>>(
        p_h, nodes_W, nullptr, nullptr, p_3d, M_ROWS, D, TD, D, 0, 0,
        p_sc, p_sh, nullptr, nullptr);
    gemm32_kernel<<<dim3(2, M_ROWS/128), 256>>>(
        p_h, p_w2p, nullptr, nullptr, p_efed, M_ROWS, D, 256, D, 0, 0,
        p_sc, p_sh, nullptr, nullptr);
    gemm32_kernel<<<dim3(D/128, M_ROWS/128), 256>>>(
        p_3d + 2*D, p_wt, nullptr, nullptr, p_lkw, M_ROWS, D, D, TD, 0, 0,
        nullptr, nullptr, nullptr, nullptr);
    meanfix_kernel<<<B, D>>>(fixed_W);

    decode_kernel<<<B, 512, DEC_SMEM_BYTES + 128>>>(x, out);
}